// round 1
// baseline (speedup 1.0000x reference)
#include <cuda_runtime.h>
#include <math.h>

#define Bv  4
#define Tv  1024
#define Cv  1024
#define NH  16
#define NKV 4
#define HD  64
#define FFH 4096
#define MT  (Bv*Tv)   // 4096 rows

// ---------------- scratch (device globals; no allocation allowed) ----------------
__device__ float g_xn  [MT*Cv];
__device__ float g_q   [MT*Cv];
__device__ float g_k   [MT*256];
__device__ float g_v   [MT*256];
__device__ float g_y   [MT*Cv];
__device__ float g_attn[MT*Cv];
__device__ float g_ca  [MT*Cv];
__device__ float g_cah [MT*32];
__device__ float g_cah2[MT*32];
__device__ float g_x1  [MT*Cv];
__device__ float g_xm  [MT*Cv];
__device__ float g_h   [(size_t)Bv*FFH*Tv];   // (B, F, T) layout
__device__ float g_mlp [MT*Cv];
__device__ float g_gate[MT*Cv];
__device__ float g_vit32[MT*32];
__device__ float g_vitv[MT];
__device__ float g_vitf[MT];

// ---------------- rmsnorm ----------------
__global__ void rmsnorm_kernel(const float* __restrict__ x, float* __restrict__ o){
    int row = blockIdx.x;
    const float* xr = x + (size_t)row*Cv;
    float ss = 0.f;
    for (int i = threadIdx.x; i < Cv; i += 256){ float v = xr[i]; ss += v*v; }
    __shared__ float red[8];
    for (int off=16; off>0; off>>=1) ss += __shfl_xor_sync(0xffffffffu, ss, off);
    if ((threadIdx.x & 31) == 0) red[threadIdx.x>>5] = ss;
    __syncthreads();
    if (threadIdx.x < 8){
        float v = red[threadIdx.x];
        for (int off=4; off>0; off>>=1) v += __shfl_xor_sync(0x000000ffu, v, off);
        if (threadIdx.x == 0) red[0] = v;
    }
    __syncthreads();
    float r = rsqrtf(red[0]*(1.0f/Cv) + 1e-6f);
    float* orow = o + (size_t)row*Cv;
    for (int i = threadIdx.x; i < Cv; i += 256) orow[i] = xr[i]*r;
}

// ---------------- generic SGEMM: C[m,n] = sum_k A[m,k]*W[n,k] ----------------
// AMODE 0: A row-major (M,K).  AMODE 1: A laid out (B, K, T): addr = b*K*T + k*T + t
// EPI 0: plain. EPI 1: relu^2 + store to (B,N,T). EPI 2: exact GELU.
template<int AMODE, int EPI>
__global__ void __launch_bounds__(256,2)
gemm_kernel(const float* __restrict__ A, const float* __restrict__ W,
            float* __restrict__ Cg, int M, int N, int K){
    __shared__ float As[16*132];
    __shared__ float Ws[16*132];
    const int tx = threadIdx.x & 15, ty = threadIdx.x >> 4;
    const int m0 = blockIdx.y << 7, n0 = blockIdx.x << 7;
    float acc[8][8];
    #pragma unroll
    for (int i=0;i<8;i++)
        #pragma unroll
        for (int j=0;j<8;j++) acc[i][j]=0.f;
    const int r  = threadIdx.x >> 2;
    const int c4 = (threadIdx.x & 3) << 2;

    for (int k0 = 0; k0 < K; k0 += 16){
        if (AMODE == 0){
            float4 a0 = *(const float4*)(A + (size_t)(m0+r   )*K + k0 + c4);
            float4 a1 = *(const float4*)(A + (size_t)(m0+r+64)*K + k0 + c4);
            As[(c4+0)*132 + r] = a0.x; As[(c4+1)*132 + r] = a0.y;
            As[(c4+2)*132 + r] = a0.z; As[(c4+3)*132 + r] = a0.w;
            As[(c4+0)*132 + r+64] = a1.x; As[(c4+1)*132 + r+64] = a1.y;
            As[(c4+2)*132 + r+64] = a1.z; As[(c4+3)*132 + r+64] = a1.w;
        } else {
            #pragma unroll
            for (int rep=0; rep<2; rep++){
                int lin = (threadIdx.x << 2) + (rep << 10);
                int kk = lin >> 7, mm = lin & 127;
                int mg = m0 + mm;
                const float* ap = A + (size_t)(mg>>10)*K*Tv + (size_t)(k0+kk)*Tv + (mg & 1023);
                *(float4*)(As + kk*132 + mm) = *(const float4*)ap;
            }
        }
        #pragma unroll
        for (int rep=0; rep<2; rep++){
            int n = n0 + r + (rep << 6);
            float4 w = make_float4(0.f,0.f,0.f,0.f);
            if (n < N) w = *(const float4*)(W + (size_t)n*K + k0 + c4);
            Ws[(c4+0)*132 + r + (rep<<6)] = w.x; Ws[(c4+1)*132 + r + (rep<<6)] = w.y;
            Ws[(c4+2)*132 + r + (rep<<6)] = w.z; Ws[(c4+3)*132 + r + (rep<<6)] = w.w;
        }
        __syncthreads();
        #pragma unroll
        for (int kk=0; kk<16; kk++){
            float av[8], bv[8];
            *(float4*)&av[0] = *(const float4*)(As + kk*132 + (ty<<3));
            *(float4*)&av[4] = *(const float4*)(As + kk*132 + (ty<<3) + 4);
            *(float4*)&bv[0] = *(const float4*)(Ws + kk*132 + (tx<<3));
            *(float4*)&bv[4] = *(const float4*)(Ws + kk*132 + (tx<<3) + 4);
            #pragma unroll
            for (int i=0;i<8;i++)
                #pragma unroll
                for (int j=0;j<8;j++) acc[i][j] += av[i]*bv[j];
        }
        __syncthreads();
    }
    #pragma unroll
    for (int i=0;i<8;i++){
        int mg = m0 + (ty<<3) + i;
        #pragma unroll
        for (int j=0;j<8;j++){
            int n = n0 + (tx<<3) + j;
            if (n < N){
                float vv = acc[i][j];
                if (EPI == 1){
                    vv = fmaxf(vv, 0.f); vv *= vv;
                    Cg[(size_t)(mg>>10)*N*Tv + (size_t)n*Tv + (mg & 1023)] = vv;
                } else if (EPI == 2){
                    vv = 0.5f*vv*(1.f + erff(vv*0.70710678118f));
                    Cg[(size_t)mg*N + n] = vv;
                } else {
                    Cg[(size_t)mg*N + n] = vv;
                }
            }
        }
    }
}

// ---------------- VE gate + V update ----------------
__global__ void vgate_kernel(const float* __restrict__ xn, const float* __restrict__ ve,
                             const float* __restrict__ wg, float* __restrict__ v){
    int row = blockIdx.x;
    __shared__ float gs[4];
    if (threadIdx.x < 4){
        float s = 0.f;
        #pragma unroll
        for (int c=0;c<12;c++) s += xn[(size_t)row*Cv + c]*wg[threadIdx.x*12 + c];
        gs[threadIdx.x] = 3.f/(1.f + expf(-s));
    }
    __syncthreads();
    int i = threadIdx.x;
    v[(size_t)row*256 + i] += gs[i>>6]*ve[(size_t)row*256 + i];
}

// ---------------- rope + per-head rmsnorm * 1.2 (in place) ----------------
__global__ void ropeRms_kernel(float* __restrict__ qk, const float* __restrict__ cosb,
                               const float* __restrict__ sinb, int nheads){
    int row  = blockIdx.x;
    int t    = row & (Tv-1);
    int head = blockIdx.y*4 + (threadIdx.x >> 5);
    if (head >= nheads) return;
    int lane = threadIdx.x & 31;
    float* p = qk + ((size_t)row*nheads + head)*HD;
    float x1 = p[lane], x2 = p[lane+32];
    float cc = cosb[t*32 + lane], sn = sinb[t*32 + lane];
    float o1 =  x1*cc + x2*sn;
    float o2 = -x1*sn + x2*cc;
    float ss = o1*o1 + o2*o2;
    for (int off=16; off>0; off>>=1) ss += __shfl_xor_sync(0xffffffffu, ss, off);
    float r = rsqrtf(ss*(1.0f/HD) + 1e-6f)*1.2f;
    p[lane]    = o1*r;
    p[lane+32] = o2*r;
}

// ---------------- fused flash attention with prev_attn 3x3 refine conv ----------------
#define ATTN_SMEM ((3*64*68 + 66*67)*4)
__global__ void attn_kernel(const float* __restrict__ q, const float* __restrict__ k,
                            const float* __restrict__ v, const float* __restrict__ prev,
                            const float* __restrict__ rw, const float* __restrict__ alphap,
                            float* __restrict__ y){
    extern __shared__ float sm[];
    float* qT = sm;                 // [64][68] : qT[d*68 + row]
    float* kT = sm + 64*68;         // [64][68] : kT[d*68 + col]
    float* Vs = sm + 2*64*68;       // [64][68] : Vs[col*68 + d]
    float* PP = sm + 3*64*68;       // prev tile 66x66 (stride 67) / P (stride 65)

    const int tid = threadIdx.x;
    const int row = tid >> 2, quad = tid & 3;
    const int c0  = quad << 4;
    const int qt = blockIdx.x, h = blockIdx.y, b = blockIdx.z;
    const int q0 = qt << 6;
    const int kvh = h >> 2;

    const float alpha = alphap[0];
    float w9[9];
    #pragma unroll
    for (int i=0;i<9;i++) w9[i] = alpha*rw[h*9 + i];

    for (int idx = tid; idx < 64*64; idx += 256){
        int rr = idx >> 6, d = idx & 63;
        qT[d*68 + rr] = q[(((size_t)(b*Tv + q0 + rr))*NH + h)*HD + d];
    }

    float o[16];
    #pragma unroll
    for (int j=0;j<16;j++) o[j]=0.f;
    float m = -1e30f, l = 0.f;

    for (int kt = 0; kt <= qt; kt++){
        int k0 = kt << 6;
        __syncthreads();
        for (int idx = tid; idx < 64*64; idx += 256){
            int c = idx >> 6, d = idx & 63;
            size_t base = ((size_t)(b*Tv + k0 + c))*NKV + kvh;
            kT[d*68 + c] = k[base*HD + d];
            Vs[c*68 + d] = v[base*HD + d];
        }
        for (int idx = tid; idx < 66*66; idx += 256){
            int i = idx/66, j = idx - i*66;
            int rr = q0 - 1 + i, cg = k0 - 1 + j;
            float pv = 0.f;
            if (rr >= 0 && rr < Tv && cg >= 0 && cg < Tv)
                pv = prev[(((size_t)(b*NH + h))*Tv + rr)*Tv + cg];
            PP[i*67 + j] = pv;
        }
        __syncthreads();

        float s[16];
        #pragma unroll
        for (int j=0;j<16;j++) s[j]=0.f;
        for (int d=0; d<64; d++){
            float qv = qT[d*68 + row];
            #pragma unroll
            for (int jj=0; jj<4; jj++){
                float4 k4 = *(const float4*)(kT + d*68 + c0 + (jj<<2));
                s[jj*4+0] += qv*k4.x; s[jj*4+1] += qv*k4.y;
                s[jj*4+2] += qv*k4.z; s[jj*4+3] += qv*k4.w;
            }
        }
        #pragma unroll
        for (int j=0;j<16;j++){
            int col = c0 + j;
            const float* p0 = PP + (row+0)*67 + col;
            const float* p1 = PP + (row+1)*67 + col;
            const float* p2 = PP + (row+2)*67 + col;
            float cv = w9[0]*p0[0] + w9[1]*p0[1] + w9[2]*p0[2]
                     + w9[3]*p1[0] + w9[4]*p1[1] + w9[5]*p1[2]
                     + w9[6]*p2[0] + w9[7]*p2[1] + w9[8]*p2[2];
            s[j] = s[j]*0.125f + cv;
            if (kt == qt && col > row) s[j] = -1e30f;
        }
        float mt = s[0];
        #pragma unroll
        for (int j=1;j<16;j++) mt = fmaxf(mt, s[j]);
        for (int off=1; off<4; off<<=1) mt = fmaxf(mt, __shfl_xor_sync(0xffffffffu, mt, off));
        float mnew = fmaxf(m, mt);
        float corr = __expf(m - mnew);
        float ls = 0.f;
        #pragma unroll
        for (int j=0;j<16;j++){ s[j] = __expf(s[j] - mnew); ls += s[j]; }
        for (int off=1; off<4; off<<=1) ls += __shfl_xor_sync(0xffffffffu, ls, off);
        l = l*corr + ls;
        m = mnew;
        #pragma unroll
        for (int j=0;j<16;j++) o[j] *= corr;

        __syncthreads();   // done reading PP(prev) before overwriting with P
        #pragma unroll
        for (int j=0;j<16;j++) PP[row*65 + c0 + j] = s[j];
        __syncthreads();

        for (int col=0; col<64; col++){
            float p = PP[row*65 + col];
            #pragma unroll
            for (int jj=0; jj<4; jj++){
                float4 v4 = *(const float4*)(Vs + col*68 + c0 + (jj<<2));
                o[jj*4+0] += p*v4.x; o[jj*4+1] += p*v4.y;
                o[jj*4+2] += p*v4.z; o[jj*4+3] += p*v4.w;
            }
        }
    }
    float inv = 1.f/l;
    #pragma unroll
    for (int j=0;j<16;j++)
        y[(((size_t)(b*Tv + q0 + row))*NH + h)*HD + c0 + j] = o[j]*inv;
}

// ---------------- CA channel: conv over T (+gelu), layout (B,T,32) ----------------
__global__ void caconv_kernel(const float* __restrict__ hin, const float* __restrict__ cw,
                              float* __restrict__ hout){
    int ch = blockIdx.x, b = blockIdx.y;
    __shared__ float s[Tv+2];
    for (int t = threadIdx.x; t < Tv; t += 256) s[1+t] = hin[((size_t)b*Tv + t)*32 + ch];
    if (threadIdx.x == 0){ s[0] = 0.f; s[Tv+1] = 0.f; }
    __syncthreads();
    float w0 = cw[ch*3], w1 = cw[ch*3+1], w2 = cw[ch*3+2];
    for (int t = threadIdx.x; t < Tv; t += 256){
        float vv = s[1+t] + 0.1f*(w0*s[t] + w1*s[1+t] + w2*s[2+t]);
        hout[((size_t)b*Tv + t)*32 + ch] = 0.5f*vv*(1.f + erff(vv*0.70710678118f));
    }
}

// ---------------- FFN: 4 depthwise conv steps over T, layout (B,F,T) ----------------
__global__ void ffnconv_kernel(float* __restrict__ h, const float* __restrict__ cw){
    int bf = blockIdx.x; int f = bf & 4095;
    __shared__ float s0[Tv+2], s1[Tv+2];
    float* base = h + (size_t)bf*Tv;
    for (int t = threadIdx.x; t < Tv; t += 256) s0[1+t] = base[t];
    if (threadIdx.x == 0){ s0[0]=0.f; s0[Tv+1]=0.f; s1[0]=0.f; s1[Tv+1]=0.f; }
    float w0 = cw[f*3], w1 = cw[f*3+1], w2 = cw[f*3+2];
    float* cur = s0; float* nxt = s1;
    for (int it=0; it<4; it++){
        __syncthreads();
        for (int t = threadIdx.x; t < Tv; t += 256)
            nxt[1+t] = cur[1+t] + 0.1f*(w0*cur[t] + w1*cur[1+t] + w2*cur[2+t]);
        float* tmp = cur; cur = nxt; nxt = tmp;
    }
    __syncthreads();
    for (int t = threadIdx.x; t < Tv; t += 256) base[t] = cur[1+t];
}

// ---------------- elementwise combines ----------------
__global__ void x1_kernel(const float* __restrict__ x, const float* __restrict__ attn,
                          const float* __restrict__ ca, float* __restrict__ x1, int n){
    for (int i = blockIdx.x*blockDim.x + threadIdx.x; i < n; i += gridDim.x*blockDim.x)
        x1[i] = x[i] + attn[i]*(1.f + 0.1f*tanhf(ca[i]));
}

__global__ void vit2_kernel(const float* __restrict__ h32, const float* __restrict__ w2,
                            float* __restrict__ out){
    int row  = blockIdx.x*8 + (threadIdx.x >> 5);
    int lane = threadIdx.x & 31;
    float vv = h32[(size_t)row*32 + lane]*w2[lane];
    for (int off=16; off>0; off>>=1) vv += __shfl_xor_sync(0xffffffffu, vv, off);
    if (lane == 0) out[row] = 1.f/(1.f + expf(-vv));
}

__global__ void vitsmooth_kernel(const float* __restrict__ vin, float* __restrict__ vout){
    int b = blockIdx.x;
    __shared__ float s[Tv+4];
    for (int t = threadIdx.x; t < Tv; t += 256) s[2+t] = vin[b*Tv + t];
    if (threadIdx.x < 2){ s[threadIdx.x] = 0.f; s[Tv+2+threadIdx.x] = 0.f; }
    __syncthreads();
    for (int t = threadIdx.x; t < Tv; t += 256){
        float vs = (s[t] + s[t+1] + s[t+2] + s[t+3] + s[t+4])*0.2f;
        float vv = 0.7f*s[2+t] + 0.3f*vs;
        vout[b*Tv + t] = (vv > 0.3f) ? vv : 0.1f*vv;
    }
}

__global__ void final_kernel(const float* __restrict__ x1, const float* __restrict__ mlp,
                             const float* __restrict__ gate, const float* __restrict__ ca,
                             const float* __restrict__ vitf, float* __restrict__ out, int n){
    for (int i = blockIdx.x*blockDim.x + threadIdx.x; i < n; i += gridDim.x*blockDim.x){
        int row = i >> 10;
        float gg = 1.f/(1.f + expf(-gate[i]));
        out[i] = x1[i] + mlp[i]*gg*(1.f + 0.1f*tanhf(ca[i]))*vitf[row];
    }
}

// ---------------- launch ----------------
extern "C" void kernel_launch(void* const* d_in, const int* in_sizes, int n_in,
                              void* d_out, int out_size){
    const float* x     = (const float*)d_in[0];
    const float* ve    = (const float*)d_in[1];
    const float* cosp  = (const float*)d_in[2];
    const float* sinp  = (const float*)d_in[3];
    const float* prev  = (const float*)d_in[4];
    const float* w_q   = (const float*)d_in[5];
    const float* w_k   = (const float*)d_in[6];
    const float* w_v   = (const float*)d_in[7];
    const float* w_o   = (const float*)d_in[8];
    const float* w_veg = (const float*)d_in[9];
    const float* rfw   = (const float*)d_in[10];
    const float* ralpha= (const float*)d_in[11];
    const float* ca_pi = (const float*)d_in[12];
    const float* ca_cw = (const float*)d_in[13];
    const float* ca_po = (const float*)d_in[14];
    const float* ffn_in= (const float*)d_in[15];
    const float* ffn_cw= (const float*)d_in[16];
    const float* ffn_out=(const float*)d_in[17];
    const float* ffn_gt= (const float*)d_in[18];
    const float* vit_w1= (const float*)d_in[19];
    const float* vit_w2= (const float*)d_in[20];
    float* out = (float*)d_out;

    float *xn,*q,*k,*v,*y,*attn,*ca,*cah,*cah2,*x1,*xm,*h,*mlp,*gate,*vit32,*vitv,*vitf;
    cudaGetSymbolAddress((void**)&xn,   g_xn);
    cudaGetSymbolAddress((void**)&q,    g_q);
    cudaGetSymbolAddress((void**)&k,    g_k);
    cudaGetSymbolAddress((void**)&v,    g_v);
    cudaGetSymbolAddress((void**)&y,    g_y);
    cudaGetSymbolAddress((void**)&attn, g_attn);
    cudaGetSymbolAddress((void**)&ca,   g_ca);
    cudaGetSymbolAddress((void**)&cah,  g_cah);
    cudaGetSymbolAddress((void**)&cah2, g_cah2);
    cudaGetSymbolAddress((void**)&x1,   g_x1);
    cudaGetSymbolAddress((void**)&xm,   g_xm);
    cudaGetSymbolAddress((void**)&h,    g_h);
    cudaGetSymbolAddress((void**)&mlp,  g_mlp);
    cudaGetSymbolAddress((void**)&gate, g_gate);
    cudaGetSymbolAddress((void**)&vit32,g_vit32);
    cudaGetSymbolAddress((void**)&vitv, g_vitv);
    cudaGetSymbolAddress((void**)&vitf, g_vitf);

    cudaFuncSetAttribute(attn_kernel, cudaFuncAttributeMaxDynamicSharedMemorySize, ATTN_SMEM);

    dim3 gN8(8,32), gN2(2,32), gN1(1,32), gN32(32,32);

    // xn = rmsnorm(x); QKV
    rmsnorm_kernel<<<MT,256>>>(x, xn);
    gemm_kernel<0,0><<<gN8,256>>>(xn, w_q, q, MT, 1024, 1024);
    gemm_kernel<0,0><<<gN2,256>>>(xn, w_k, k, MT, 256, 1024);
    gemm_kernel<0,0><<<gN2,256>>>(xn, w_v, v, MT, 256, 1024);
    vgate_kernel<<<MT,256>>>(xn, ve, w_veg, v);
    ropeRms_kernel<<<dim3(MT,4),128>>>(q, cosp, sinp, NH);
    ropeRms_kernel<<<dim3(MT,1),128>>>(k, cosp, sinp, NKV);

    // attention
    attn_kernel<<<dim3(16,NH,Bv),256,ATTN_SMEM>>>(q, k, v, prev, rfw, ralpha, y);
    gemm_kernel<0,0><<<gN8,256>>>(y, w_o, attn, MT, 1024, 1024);

    // ca1 on x; x1
    gemm_kernel<0,0><<<gN1,256>>>(x, ca_pi, cah, MT, 32, 1024);
    caconv_kernel<<<dim3(32,Bv),256>>>(cah, ca_cw, cah2);
    gemm_kernel<0,0><<<gN8,256>>>(cah2, ca_po, ca, MT, 1024, 32);
    x1_kernel<<<4096,256>>>(x, attn, ca, x1, MT*Cv);

    // FFN
    rmsnorm_kernel<<<MT,256>>>(x1, xm);
    gemm_kernel<0,1><<<gN32,256>>>(xm, ffn_in, h, MT, FFH, 1024);
    ffnconv_kernel<<<Bv*FFH,256>>>(h, ffn_cw);
    gemm_kernel<1,0><<<gN8,256>>>(h, ffn_out, mlp, MT, 1024, FFH);
    gemm_kernel<0,0><<<gN8,256>>>(xm, ffn_gt, gate, MT, 1024, 1024);

    // ca2 on x1
    gemm_kernel<0,0><<<gN1,256>>>(x1, ca_pi, cah, MT, 32, 1024);
    caconv_kernel<<<dim3(32,Bv),256>>>(cah, ca_cw, cah2);
    gemm_kernel<0,0><<<gN8,256>>>(cah2, ca_po, ca, MT, 1024, 32);

    // vit gate
    gemm_kernel<0,2><<<gN1,256>>>(x1, vit_w1, vit32, MT, 32, 1024);
    vit2_kernel<<<512,256>>>(vit32, vit_w2, vitv);
    vitsmooth_kernel<<<Bv,256>>>(vitv, vitf);

    final_kernel<<<4096,256>>>(x1, mlp, gate, ca, vitf, out, MT*Cv);
}

// round 3
// speedup vs baseline: 1.2686x; 1.2686x over previous
#include <cuda_runtime.h>
#include <cuda_bf16.h>
#include <math.h>
#include <stdint.h>

#define Bv  4
#define Tv  1024
#define Cv  1024
#define NH  16
#define NKV 4
#define HD  64
#define FFH 4096
#define MT  (Bv*Tv)   // 4096 rows

// ---------------- scratch ----------------
__device__ float g_xn  [MT*Cv];
__device__ float g_q   [MT*Cv];
__device__ float g_k   [MT*256];
__device__ float g_v   [MT*256];
__device__ float g_y   [MT*Cv];
__device__ float g_attn[MT*Cv];
__device__ float g_ca  [MT*Cv];
__device__ float g_cah [MT*32];
__device__ float g_cah2[MT*32];
__device__ float g_x1  [MT*Cv];
__device__ float g_xm  [MT*Cv];
__device__ float g_h   [(size_t)Bv*FFH*Tv];   // (B, F, T) layout
__device__ float g_mlp [MT*Cv];
__device__ float g_gate[MT*Cv];
__device__ float g_vit32[MT*32];
__device__ float g_vitv[MT];
__device__ float g_vitf[MT];

// =================== mma.sync helpers ===================
__device__ __forceinline__ uint32_t smem_u32(const void* p){
    uint32_t a;
    asm("{ .reg .u64 t; cvta.to.shared.u64 t, %1; cvt.u32.u64 %0, t; }" : "=r"(a) : "l"(p));
    return a;
}
__device__ __forceinline__ void mma16816(float* c, const uint32_t* a, uint32_t b0, uint32_t b1){
    asm volatile("mma.sync.aligned.m16n8k16.row.col.f32.bf16.bf16.f32 "
        "{%0,%1,%2,%3}, {%4,%5,%6,%7}, {%8,%9}, {%0,%1,%2,%3};"
        : "+f"(c[0]), "+f"(c[1]), "+f"(c[2]), "+f"(c[3])
        : "r"(a[0]), "r"(a[1]), "r"(a[2]), "r"(a[3]), "r"(b0), "r"(b1));
}
__device__ __forceinline__ void ldsm4(uint32_t* r, uint32_t addr){
    asm volatile("ldmatrix.sync.aligned.m8n8.x4.shared.b16 {%0,%1,%2,%3}, [%4];"
        : "=r"(r[0]), "=r"(r[1]), "=r"(r[2]), "=r"(r[3]) : "r"(addr));
}
// swizzled byte offset inside a 128x32-bf16 tile (64B rows): conflict-free for ldmatrix
__device__ __forceinline__ uint32_t sw_off(int row, int k){
    int chunk = (k >> 3) ^ ((row >> 1) & 3);
    return (uint32_t)(row*64 + chunk*16 + (k & 7)*2);
}
__device__ __forceinline__ void split4(float4 v, uint2& hu, uint2& lu){
    __nv_bfloat16 h0 = __float2bfloat16(v.x), h1 = __float2bfloat16(v.y);
    __nv_bfloat16 h2 = __float2bfloat16(v.z), h3 = __float2bfloat16(v.w);
    __nv_bfloat16 l0 = __float2bfloat16(v.x - __bfloat162float(h0));
    __nv_bfloat16 l1 = __float2bfloat16(v.y - __bfloat162float(h1));
    __nv_bfloat16 l2 = __float2bfloat16(v.z - __bfloat162float(h2));
    __nv_bfloat16 l3 = __float2bfloat16(v.w - __bfloat162float(h3));
    hu.x = ((uint32_t)__bfloat16_as_ushort(h1) << 16) | __bfloat16_as_ushort(h0);
    hu.y = ((uint32_t)__bfloat16_as_ushort(h3) << 16) | __bfloat16_as_ushort(h2);
    lu.x = ((uint32_t)__bfloat16_as_ushort(l1) << 16) | __bfloat16_as_ushort(l0);
    lu.y = ((uint32_t)__bfloat16_as_ushort(l3) << 16) | __bfloat16_as_ushort(l2);
}

// stage layout: Ahi 0, Alo 8192, Bhi 16384, Blo 24576 ; stage size 32768, 2 stages
#define STG_SZ 32768
#define MMA_SMEM 65536

// C[m,n] = sum_k A[m,k]*W[n,k]; CTA tile 128x128, 512 threads, warp tile 32x32.
// AMODE 0: A row-major (M,K). AMODE 1: A in (B,K,T) layout (h buffer).
// EPI 0: plain row-major store. EPI 1: relu^2, store to (B,N,T).
template<int AMODE, int EPI>
__global__ void __launch_bounds__(512,1)
gemm_mma(const float* __restrict__ A, const float* __restrict__ W, float* __restrict__ Cg,
         int N, int K){
    extern __shared__ char smem[];
    const int tid = threadIdx.x;
    const int lane = tid & 31, wid = tid >> 5;
    const int warpM = wid & 3, warpN = wid >> 2;
    const int m0 = blockIdx.y << 7, n0 = blockIdx.x << 7;
    const int b = m0 >> 10, tb = m0 & 1023;
    uint32_t sb = smem_u32(smem);

    float4 aPf[2], bPf[2];
    float acc[2][4][4];
    #pragma unroll
    for (int i=0;i<2;i++)
        #pragma unroll
        for (int j=0;j<4;j++)
            #pragma unroll
            for (int q=0;q<4;q++) acc[i][j][q]=0.f;

    // ---- load chunk (global -> regs) ----
    auto LOAD = [&](int k0){
        #pragma unroll
        for (int i=0;i<2;i++){
            int idx = tid + (i << 9);
            if (AMODE == 0){
                int row = idx >> 3, c4 = (idx & 7) << 2;
                aPf[i] = *(const float4*)(A + (size_t)(m0+row)*K + k0 + c4);
            } else {
                int kk = idx >> 5, t4 = (idx & 31) << 2;
                aPf[i] = *(const float4*)(A + ((size_t)b*K + (k0+kk))*1024 + tb + t4);
            }
            int row = idx >> 3, c4 = (idx & 7) << 2;
            bPf[i] = *(const float4*)(W + (size_t)(n0+row)*K + k0 + c4);
        }
    };
    // ---- convert regs -> smem stage ----
    auto CONV = [&](int s){
        char* Ahi = smem + s*STG_SZ;
        char* Alo = Ahi + 8192;
        char* Bhi = Ahi + 16384;
        char* Blo = Ahi + 24576;
        #pragma unroll
        for (int i=0;i<2;i++){
            int idx = tid + (i << 9);
            uint2 hu, lu;
            if (AMODE == 0){
                int row = idx >> 3, c4 = (idx & 7) << 2;
                split4(aPf[i], hu, lu);
                uint32_t off = sw_off(row, c4);
                *(uint2*)(Ahi + off) = hu;
                *(uint2*)(Alo + off) = lu;
            } else {
                int kk = idx >> 5, t4 = (idx & 31) << 2;
                float vv[4] = {aPf[i].x, aPf[i].y, aPf[i].z, aPf[i].w};
                #pragma unroll
                for (int j=0;j<4;j++){
                    int row = t4 + j;
                    __nv_bfloat16 h = __float2bfloat16(vv[j]);
                    uint32_t off = sw_off(row, kk);
                    *(__nv_bfloat16*)(Ahi + off) = h;
                    *(__nv_bfloat16*)(Alo + off) = __float2bfloat16(vv[j] - __bfloat162float(h));
                }
            }
            int row = idx >> 3, c4 = (idx & 7) << 2;
            split4(bPf[i], hu, lu);
            uint32_t off = sw_off(row, c4);
            *(uint2*)(Bhi + off) = hu;
            *(uint2*)(Blo + off) = lu;
        }
    };

    LOAD(0);
    CONV(0);
    __syncthreads();

    const int NC = K >> 5;
    const int lr = lane & 15, lc = (lane < 16) ? 0 : 8;
    for (int c = 0; c < NC; c++){
        int s = c & 1;
        if (c + 1 < NC) LOAD((c + 1) << 5);
        uint32_t sAhi = sb + s*STG_SZ, sAlo = sAhi + 8192;
        uint32_t sBhi = sAhi + 16384, sBlo = sAhi + 24576;
        #pragma unroll
        for (int kk = 0; kk < 32; kk += 16){
            uint32_t ah[2][4], al[2][4];
            #pragma unroll
            for (int mt=0; mt<2; mt++){
                int r = warpM*32 + mt*16 + lr;
                uint32_t off = sw_off(r, kk + lc);
                ldsm4(ah[mt], sAhi + off);
                ldsm4(al[mt], sAlo + off);
            }
            #pragma unroll
            for (int nb=0; nb<2; nb++){
                int r = warpN*32 + nb*16 + lr;
                uint32_t off = sw_off(r, kk + lc);
                uint32_t bh[4], bl[4];
                ldsm4(bh, sBhi + off);
                ldsm4(bl, sBlo + off);
                #pragma unroll
                for (int mt=0; mt<2; mt++){
                    // n-tile 0 of this 16: b0=r[0], b1=r[2]; n-tile 1: b0=r[1], b1=r[3]
                    mma16816(acc[mt][nb*2+0], ah[mt], bh[0], bh[2]);
                    mma16816(acc[mt][nb*2+0], ah[mt], bl[0], bl[2]);
                    mma16816(acc[mt][nb*2+0], al[mt], bh[0], bh[2]);
                    mma16816(acc[mt][nb*2+1], ah[mt], bh[1], bh[3]);
                    mma16816(acc[mt][nb*2+1], ah[mt], bl[1], bl[3]);
                    mma16816(acc[mt][nb*2+1], al[mt], bh[1], bh[3]);
                }
            }
        }
        if (c + 1 < NC) CONV(s ^ 1);
        __syncthreads();
    }

    const int g = lane >> 2, t2 = (lane & 3) << 1;
    if (EPI == 0){
        #pragma unroll
        for (int mt=0; mt<2; mt++){
            int m = m0 + warpM*32 + mt*16 + g;
            #pragma unroll
            for (int ni=0; ni<4; ni++){
                int n = n0 + warpN*32 + ni*8 + t2;
                float2 v0 = make_float2(acc[mt][ni][0], acc[mt][ni][1]);
                float2 v1 = make_float2(acc[mt][ni][2], acc[mt][ni][3]);
                *(float2*)(Cg + (size_t)m*N + n) = v0;
                *(float2*)(Cg + (size_t)(m+8)*N + n) = v1;
            }
        }
    } else {
        float* ep = (float*)smem;   // 64 x 136
        #pragma unroll
        for (int slab=0; slab<2; slab++){
            __syncthreads();
            if ((warpN >> 1) == slab){
                #pragma unroll
                for (int mt=0; mt<2; mt++){
                    int mloc = warpM*32 + mt*16 + g;
                    #pragma unroll
                    for (int ni=0; ni<4; ni++){
                        int nL = (warpN & 1)*32 + ni*8 + t2;
                        ep[nL*136 + mloc]        = acc[mt][ni][0];
                        ep[nL*136 + mloc + 136]  = acc[mt][ni][1];   // n+1
                        ep[(nL)*136 + mloc + 8]  = acc[mt][ni][2];
                        ep[(nL+1)*136 + mloc + 8]= acc[mt][ni][3];
                    }
                }
            }
            __syncthreads();
            #pragma unroll
            for (int i=0;i<4;i++){
                int idx = tid + (i << 9);       // 2048 f4
                int nr = idx >> 5, t4 = (idx & 31) << 2;
                float a0 = fmaxf(ep[nr*136 + t4 + 0], 0.f);
                float a1 = fmaxf(ep[nr*136 + t4 + 1], 0.f);
                float a2 = fmaxf(ep[nr*136 + t4 + 2], 0.f);
                float a3 = fmaxf(ep[nr*136 + t4 + 3], 0.f);
                float4 o4 = make_float4(a0*a0, a1*a1, a2*a2, a3*a3);
                int n = n0 + slab*64 + nr;
                *(float4*)(Cg + ((size_t)b*N + n)*1024 + tb + t4) = o4;
            }
        }
    }
}
// fix: EPI1 write of acc[mt][ni][1] belongs to n+1? No: c0,c1 are cols 2t,2t+1 same row pair.
// (handled above: [0]->(g,2t), [1]->(g,2t+1), [2]->(g+8,2t), [3]->(g+8,2t+1))

// ---------------- small-N (=32) GEMM: warp-per-row ----------------
template<int EPI>
__global__ void __launch_bounds__(256)
gemm32_kernel(const float* __restrict__ A, const float* __restrict__ W, float* __restrict__ Cg){
    __shared__ float xs[8*1024];
    int row0 = blockIdx.x << 3;
    #pragma unroll
    for (int i = 0; i < 8; i++){
        int f4 = threadIdx.x + (i << 8);
        ((float4*)xs)[f4] = ((const float4*)(A + ((size_t)row0 << 10)))[f4];
    }
    __syncthreads();
    int w = threadIdx.x >> 5, n = threadIdx.x & 31;
    const float4* Wr = (const float4*)(W + (size_t)n*1024);
    const float4* xr = (const float4*)(xs + (w << 10));
    float acc = 0.f;
    #pragma unroll 4
    for (int k = 0; k < 256; k++){
        float4 a = xr[k], b = Wr[k];
        acc += a.x*b.x + a.y*b.y + a.z*b.z + a.w*b.w;
    }
    if (EPI == 2) acc = 0.5f*acc*(1.f + erff(acc*0.70710678118f));
    Cg[((size_t)(row0 + w) << 5) + n] = acc;
}

// ---------------- FFMA GEMM (ca_po, K=32) ----------------
__global__ void __launch_bounds__(256,2)
gemm_k32(const float* __restrict__ A, const float* __restrict__ W,
         float* __restrict__ Cg, int N){
    __shared__ float As[32*132];
    __shared__ float Ws[32*132];
    const int tx = threadIdx.x & 15, ty = threadIdx.x >> 4;
    const int m0 = blockIdx.y << 7, n0 = blockIdx.x << 7;
    float acc[8][8];
    #pragma unroll
    for (int i=0;i<8;i++)
        #pragma unroll
        for (int j=0;j<8;j++) acc[i][j]=0.f;
    const int r = threadIdx.x >> 1;
    const int c4 = (threadIdx.x & 1) << 4;
    #pragma unroll
    for (int q=0;q<4;q++){
        float4 a0 = *(const float4*)(A + (size_t)(m0+r)*32 + c4 + q*4);
        As[(c4+q*4+0)*132 + r] = a0.x; As[(c4+q*4+1)*132 + r] = a0.y;
        As[(c4+q*4+2)*132 + r] = a0.z; As[(c4+q*4+3)*132 + r] = a0.w;
        float4 w0 = *(const float4*)(W + (size_t)(n0+r)*32 + c4 + q*4);
        Ws[(c4+q*4+0)*132 + r] = w0.x; Ws[(c4+q*4+1)*132 + r] = w0.y;
        Ws[(c4+q*4+2)*132 + r] = w0.z; Ws[(c4+q*4+3)*132 + r] = w0.w;
    }
    __syncthreads();
    #pragma unroll
    for (int kk=0; kk<32; kk++){
        float av[8], bv[8];
        *(float4*)&av[0] = *(const float4*)(As + kk*132 + (ty<<3));
        *(float4*)&av[4] = *(const float4*)(As + kk*132 + (ty<<3) + 4);
        *(float4*)&bv[0] = *(const float4*)(Ws + kk*132 + (tx<<3));
        *(float4*)&bv[4] = *(const float4*)(Ws + kk*132 + (tx<<3) + 4);
        #pragma unroll
        for (int i=0;i<8;i++)
            #pragma unroll
            for (int j=0;j<8;j++) acc[i][j] += av[i]*bv[j];
    }
    #pragma unroll
    for (int i=0;i<8;i++){
        int mg = m0 + (ty<<3) + i;
        #pragma unroll
        for (int j=0;j<8;j++)
            Cg[(size_t)mg*N + n0 + (tx<<3) + j] = acc[i][j];
    }
}

// ---------------- rmsnorm ----------------
__global__ void rmsnorm_kernel(const float* __restrict__ x, float* __restrict__ o){
    int row = blockIdx.x;
    const float* xr = x + (size_t)row*Cv;
    float ss = 0.f;
    for (int i = threadIdx.x; i < Cv; i += 256){ float v = xr[i]; ss += v*v; }
    __shared__ float red[8];
    for (int off=16; off>0; off>>=1) ss += __shfl_xor_sync(0xffffffffu, ss, off);
    if ((threadIdx.x & 31) == 0) red[threadIdx.x>>5] = ss;
    __syncthreads();
    if (threadIdx.x < 8){
        float v = red[threadIdx.x];
        for (int off=4; off>0; off>>=1) v += __shfl_xor_sync(0x000000ffu, v, off);
        if (threadIdx.x == 0) red[0] = v;
    }
    __syncthreads();
    float r = rsqrtf(red[0]*(1.0f/Cv) + 1e-6f);
    float* orow = o + (size_t)row*Cv;
    for (int i = threadIdx.x; i < Cv; i += 256) orow[i] = xr[i]*r;
}

// ---------------- VE gate + V update ----------------
__global__ void vgate_kernel(const float* __restrict__ xn, const float* __restrict__ ve,
                             const float* __restrict__ wg, float* __restrict__ v){
    int row = blockIdx.x;
    __shared__ float gs[4];
    if (threadIdx.x < 4){
        float s = 0.f;
        #pragma unroll
        for (int c=0;c<12;c++) s += xn[(size_t)row*Cv + c]*wg[threadIdx.x*12 + c];
        gs[threadIdx.x] = 3.f/(1.f + expf(-s));
    }
    __syncthreads();
    int i = threadIdx.x;
    v[(size_t)row*256 + i] += gs[i>>6]*ve[(size_t)row*256 + i];
}

// ---------------- rope + per-head rmsnorm * 1.2 ----------------
__global__ void ropeRms_kernel(float* __restrict__ qk, const float* __restrict__ cosb,
                               const float* __restrict__ sinb, int nheads){
    int row  = blockIdx.x;
    int t    = row & (Tv-1);
    int head = blockIdx.y*4 + (threadIdx.x >> 5);
    if (head >= nheads) return;
    int lane = threadIdx.x & 31;
    float* p = qk + ((size_t)row*nheads + head)*HD;
    float x1 = p[lane], x2 = p[lane+32];
    float cc = cosb[t*32 + lane], sn = sinb[t*32 + lane];
    float o1 =  x1*cc + x2*sn;
    float o2 = -x1*sn + x2*cc;
    float ss = o1*o1 + o2*o2;
    for (int off=16; off>0; off>>=1) ss += __shfl_xor_sync(0xffffffffu, ss, off);
    float r = rsqrtf(ss*(1.0f/HD) + 1e-6f)*1.2f;
    p[lane]    = o1*r;
    p[lane+32] = o2*r;
}

// ---------------- fused flash attention + prev_attn 3x3 refine ----------------
#define ATTN_SMEM ((3*64*68 + 66*67)*4)
__global__ void attn_kernel(const float* __restrict__ q, const float* __restrict__ k,
                            const float* __restrict__ v, const float* __restrict__ prev,
                            const float* __restrict__ rw, const float* __restrict__ alphap,
                            float* __restrict__ y){
    extern __shared__ float sm[];
    float* qT = sm;
    float* kT = sm + 64*68;
    float* Vs = sm + 2*64*68;
    float* PP = sm + 3*64*68;

    const int tid = threadIdx.x;
    const int row = tid >> 2, quad = tid & 3;
    const int c0  = quad << 4;
    const int qt = blockIdx.x, h = blockIdx.y, b = blockIdx.z;
    const int q0 = qt << 6;
    const int kvh = h >> 2;

    const float alpha = alphap[0];
    float w9[9];
    #pragma unroll
    for (int i=0;i<9;i++) w9[i] = alpha*rw[h*9 + i];

    for (int idx = tid; idx < 64*64; idx += 256){
        int rr = idx >> 6, d = idx & 63;
        qT[d*68 + rr] = q[(((size_t)(b*Tv + q0 + rr))*NH + h)*HD + d];
    }

    float o[16];
    #pragma unroll
    for (int j=0;j<16;j++) o[j]=0.f;
    float m = -1e30f, l = 0.f;

    for (int kt = 0; kt <= qt; kt++){
        int k0 = kt << 6;
        __syncthreads();
        for (int idx = tid; idx < 64*64; idx += 256){
            int c = idx >> 6, d = idx & 63;
            size_t base = ((size_t)(b*Tv + k0 + c))*NKV + kvh;
            kT[d*68 + c] = k[base*HD + d];
            Vs[c*68 + d] = v[base*HD + d];
        }
        for (int idx = tid; idx < 66*66; idx += 256){
            int i = idx/66, j = idx - i*66;
            int rr = q0 - 1 + i, cg = k0 - 1 + j;
            float pv = 0.f;
            if (rr >= 0 && rr < Tv && cg >= 0 && cg < Tv)
                pv = prev[(((size_t)(b*NH + h))*Tv + rr)*Tv + cg];
            PP[i*67 + j] = pv;
        }
        __syncthreads();

        float s[16];
        #pragma unroll
        for (int j=0;j<16;j++) s[j]=0.f;
        for (int d=0; d<64; d++){
            float qv = qT[d*68 + row];
            #pragma unroll
            for (int jj=0; jj<4; jj++){
                float4 k4 = *(const float4*)(kT + d*68 + c0 + (jj<<2));
                s[jj*4+0] += qv*k4.x; s[jj*4+1] += qv*k4.y;
                s[jj*4+2] += qv*k4.z; s[jj*4+3] += qv*k4.w;
            }
        }
        #pragma unroll
        for (int j=0;j<16;j++){
            int col = c0 + j;
            const float* p0 = PP + (row+0)*67 + col;
            const float* p1 = PP + (row+1)*67 + col;
            const float* p2 = PP + (row+2)*67 + col;
            float cv = w9[0]*p0[0] + w9[1]*p0[1] + w9[2]*p0[2]
                     + w9[3]*p1[0] + w9[4]*p1[1] + w9[5]*p1[2]
                     + w9[6]*p2[0] + w9[7]*p2[1] + w9[8]*p2[2];
            s[j] = s[j]*0.125f + cv;
            if (kt == qt && col > row) s[j] = -1e30f;
        }
        float mt = s[0];
        #pragma unroll
        for (int j=1;j<16;j++) mt = fmaxf(mt, s[j]);
        for (int off=1; off<4; off<<=1) mt = fmaxf(mt, __shfl_xor_sync(0xffffffffu, mt, off));
        float mnew = fmaxf(m, mt);
        float corr = __expf(m - mnew);
        float ls = 0.f;
        #pragma unroll
        for (int j=0;j<16;j++){ s[j] = __expf(s[j] - mnew); ls += s[j]; }
        for (int off=1; off<4; off<<=1) ls += __shfl_xor_sync(0xffffffffu, ls, off);
        l = l*corr + ls;
        m = mnew;
        #pragma unroll
        for (int j=0;j<16;j++) o[j] *= corr;

        __syncthreads();
        #pragma unroll
        for (int j=0;j<16;j++) PP[row*65 + c0 + j] = s[j];
        __syncthreads();

        for (int col=0; col<64; col++){
            float p = PP[row*65 + col];
            #pragma unroll
            for (int jj=0; jj<4; jj++){
                float4 v4 = *(const float4*)(Vs + col*68 + c0 + (jj<<2));
                o[jj*4+0] += p*v4.x; o[jj*4+1] += p*v4.y;
                o[jj*4+2] += p*v4.z; o[jj*4+3] += p*v4.w;
            }
        }
    }
    float inv = 1.f/l;
    #pragma unroll
    for (int j=0;j<16;j++)
        y[(((size_t)(b*Tv + q0 + row))*NH + h)*HD + c0 + j] = o[j]*inv;
}

// ---------------- CA conv + gelu ----------------
__global__ void caconv_kernel(const float* __restrict__ hin, const float* __restrict__ cw,
                              float* __restrict__ hout){
    int ch = blockIdx.x, b = blockIdx.y;
    __shared__ float s[Tv+2];
    for (int t = threadIdx.x; t < Tv; t += 256) s[1+t] = hin[((size_t)b*Tv + t)*32 + ch];
    if (threadIdx.x == 0){ s[0] = 0.f; s[Tv+1] = 0.f; }
    __syncthreads();
    float w0 = cw[ch*3], w1 = cw[ch*3+1], w2 = cw[ch*3+2];
    for (int t = threadIdx.x; t < Tv; t += 256){
        float vv = s[1+t] + 0.1f*(w0*s[t] + w1*s[1+t] + w2*s[2+t]);
        hout[((size_t)b*Tv + t)*32 + ch] = 0.5f*vv*(1.f + erff(vv*0.70710678118f));
    }
}

// ---------------- FFN conv x4 ----------------
__global__ void ffnconv_kernel(float* __restrict__ h, const float* __restrict__ cw){
    int bf = blockIdx.x; int f = bf & 4095;
    __shared__ float s0[Tv+2], s1[Tv+2];
    float* base = h + (size_t)bf*Tv;
    for (int t = threadIdx.x; t < Tv; t += 256) s0[1+t] = base[t];
    if (threadIdx.x == 0){ s0[0]=0.f; s0[Tv+1]=0.f; s1[0]=0.f; s1[Tv+1]=0.f; }
    float w0 = cw[f*3], w1 = cw[f*3+1], w2 = cw[f*3+2];
    float* cur = s0; float* nxt = s1;
    for (int it=0; it<4; it++){
        __syncthreads();
        for (int t = threadIdx.x; t < Tv; t += 256)
            nxt[1+t] = cur[1+t] + 0.1f*(w0*cur[t] + w1*cur[1+t] + w2*cur[2+t]);
        float* tmp = cur; cur = nxt; nxt = tmp;
    }
    __syncthreads();
    for (int t = threadIdx.x; t < Tv; t += 256) base[t] = cur[1+t];
}

// ---------------- elementwise ----------------
__global__ void x1_kernel(const float* __restrict__ x, const float* __restrict__ attn,
                          const float* __restrict__ ca, float* __restrict__ x1, int n){
    for (int i = blockIdx.x*blockDim.x + threadIdx.x; i < n; i += gridDim.x*blockDim.x)
        x1[i] = x[i] + attn[i]*(1.f + 0.1f*tanhf(ca[i]));
}

__global__ void vit2_kernel(const float* __restrict__ h32, const float* __restrict__ w2,
                            float* __restrict__ out){
    int row  = blockIdx.x*8 + (threadIdx.x >> 5);
    int lane = threadIdx.x & 31;
    float vv = h32[(size_t)row*32 + lane]*w2[lane];
    for (int off=16; off>0; off>>=1) vv += __shfl_xor_sync(0xffffffffu, vv, off);
    if (lane == 0) out[row] = 1.f/(1.f + expf(-vv));
}

__global__ void vitsmooth_kernel(const float* __restrict__ vin, float* __restrict__ vout){
    int b = blockIdx.x;
    __shared__ float s[Tv+4];
    for (int t = threadIdx.x; t < Tv; t += 256) s[2+t] = vin[b*Tv + t];
    if (threadIdx.x < 2){ s[threadIdx.x] = 0.f; s[Tv+2+threadIdx.x] = 0.f; }
    __syncthreads();
    for (int t = threadIdx.x; t < Tv; t += 256){
        float vs = (s[t] + s[t+1] + s[t+2] + s[t+3] + s[t+4])*0.2f;
        float vv = 0.7f*s[2+t] + 0.3f*vs;
        vout[b*Tv + t] = (vv > 0.3f) ? vv : 0.1f*vv;
    }
}

__global__ void final_kernel(const float* __restrict__ x1, const float* __restrict__ mlp,
                             const float* __restrict__ gate, const float* __restrict__ ca,
                             const float* __restrict__ vitf, float* __restrict__ out, int n){
    for (int i = blockIdx.x*blockDim.x + threadIdx.x; i < n; i += gridDim.x*blockDim.x){
        int row = i >> 10;
        float gg = 1.f/(1.f + expf(-gate[i]));
        out[i] = x1[i] + mlp[i]*gg*(1.f + 0.1f*tanhf(ca[i]))*vitf[row];
    }
}

// ---------------- launch ----------------
extern "C" void kernel_launch(void* const* d_in, const int* in_sizes, int n_in,
                              void* d_out, int out_size){
    const float* x     = (const float*)d_in[0];
    const float* ve    = (const float*)d_in[1];
    const float* cosp  = (const float*)d_in[2];
    const float* sinp  = (const float*)d_in[3];
    const float* prev  = (const float*)d_in[4];
    const float* w_q   = (const float*)d_in[5];
    const float* w_k   = (const float*)d_in[6];
    const float* w_v   = (const float*)d_in[7];
    const float* w_o   = (const float*)d_in[8];
    const float* w_veg = (const float*)d_in[9];
    const float* rfw   = (const float*)d_in[10];
    const float* ralpha= (const float*)d_in[11];
    const float* ca_pi = (const float*)d_in[12];
    const float* ca_cw = (const float*)d_in[13];
    const float* ca_po = (const float*)d_in[14];
    const float* ffn_in= (const float*)d_in[15];
    const float* ffn_cw= (const float*)d_in[16];
    const float* ffn_outw=(const float*)d_in[17];
    const float* ffn_gt= (const float*)d_in[18];
    const float* vit_w1= (const float*)d_in[19];
    const float* vit_w2= (const float*)d_in[20];
    float* out = (float*)d_out;

    float *xn,*q,*k,*v,*y,*attn,*ca,*cah,*cah2,*x1,*xm,*h,*mlp,*gate,*vit32,*vitv,*vitf;
    cudaGetSymbolAddress((void**)&xn,   g_xn);
    cudaGetSymbolAddress((void**)&q,    g_q);
    cudaGetSymbolAddress((void**)&k,    g_k);
    cudaGetSymbolAddress((void**)&v,    g_v);
    cudaGetSymbolAddress((void**)&y,    g_y);
    cudaGetSymbolAddress((void**)&attn, g_attn);
    cudaGetSymbolAddress((void**)&ca,   g_ca);
    cudaGetSymbolAddress((void**)&cah,  g_cah);
    cudaGetSymbolAddress((void**)&cah2, g_cah2);
    cudaGetSymbolAddress((void**)&x1,   g_x1);
    cudaGetSymbolAddress((void**)&xm,   g_xm);
    cudaGetSymbolAddress((void**)&h,    g_h);
    cudaGetSymbolAddress((void**)&mlp,  g_mlp);
    cudaGetSymbolAddress((void**)&gate, g_gate);
    cudaGetSymbolAddress((void**)&vit32,g_vit32);
    cudaGetSymbolAddress((void**)&vitv, g_vitv);
    cudaGetSymbolAddress((void**)&vitf, g_vitf);

    cudaFuncSetAttribute(attn_kernel, cudaFuncAttributeMaxDynamicSharedMemorySize, ATTN_SMEM);
    cudaFuncSetAttribute(gemm_mma<0,0>, cudaFuncAttributeMaxDynamicSharedMemorySize, MMA_SMEM);
    cudaFuncSetAttribute(gemm_mma<0,1>, cudaFuncAttributeMaxDynamicSharedMemorySize, MMA_SMEM);
    cudaFuncSetAttribute(gemm_mma<1,0>, cudaFuncAttributeMaxDynamicSharedMemorySize, MMA_SMEM);

    // xn = rmsnorm(x); QKV on tensor cores (mma.sync)
    rmsnorm_kernel<<<MT,256>>>(x, xn);
    gemm_mma<0,0><<<dim3(8,32),512,MMA_SMEM>>>(xn, w_q, q, 1024, 1024);
    gemm_mma<0,0><<<dim3(2,32),512,MMA_SMEM>>>(xn, w_k, k, 256, 1024);
    gemm_mma<0,0><<<dim3(2,32),512,MMA_SMEM>>>(xn, w_v, v, 256, 1024);
    vgate_kernel<<<MT,256>>>(xn, ve, w_veg, v);
    ropeRms_kernel<<<dim3(MT,4),128>>>(q, cosp, sinp, NH);
    ropeRms_kernel<<<dim3(MT,1),128>>>(k, cosp, sinp, NKV);

    // attention
    attn_kernel<<<dim3(16,NH,Bv),256,ATTN_SMEM>>>(q, k, v, prev, rfw, ralpha, y);
    gemm_mma<0,0><<<dim3(8,32),512,MMA_SMEM>>>(y, w_o, attn, 1024, 1024);

    // ca1 on x; x1
    gemm32_kernel<0><<<512,256>>>(x, ca_pi, cah);
    caconv_kernel<<<dim3(32,Bv),256>>>(cah, ca_cw, cah2);
    gemm_k32<<<dim3(8,32),256>>>(cah2, ca_po, ca, 1024);
    x1_kernel<<<4096,256>>>(x, attn, ca, x1, MT*Cv);

    // FFN
    rmsnorm_kernel<<<MT,256>>>(x1, xm);
    gemm_mma<0,1><<<dim3(32,32),512,MMA_SMEM>>>(xm, ffn_in, h, FFH, 1024);
    ffnconv_kernel<<<Bv*FFH,256>>>(h, ffn_cw);
    gemm_mma<1,0><<<dim3(8,32),512,MMA_SMEM>>>(h, ffn_outw, mlp, 1024, FFH);
    gemm_mma<0,0><<<dim3(8,32),512,MMA_SMEM>>>(xm, ffn_gt, gate, 1024, 1024);

    // ca2 on x1
    gemm32_kernel<0><<<512,256>>>(x1, ca_pi, cah);
    caconv_kernel<<<dim3(32,Bv),256>>>(cah, ca_cw, cah2);
    gemm_k32<<<dim3(8,32),256>>>(cah2, ca_po, ca, 1024);

    // vit gate
    gemm32_kernel<2><<<512,256>>>(x1, vit_w1, vit32);
    vit2_kernel<<<512,256>>>(vit32, vit_w2, vitv);
    vitsmooth_kernel<<<Bv,256>>>(vitv, vitf);

    final_kernel<<<4096,256>>>(x1, mlp, gate, ca, vitf, out, MT*Cv);
}

// round 4
// speedup vs baseline: 2.1130x; 1.6656x over previous
#include <cuda_runtime.h>
#include <cuda_bf16.h>
#include <math.h>
#include <stdint.h>

#define Bv  4
#define Tv  1024
#define Cv  1024
#define NH  16
#define NKV 4
#define HD  64
#define FFH 4096
#define MT  (Bv*Tv)

typedef __nv_bfloat16 bf16;

// ---------------- fp32 scratch ----------------
__device__ float g_xn  [MT*Cv];
__device__ float g_qkv [MT*1536];
__device__ float g_attn[MT*Cv];
__device__ float g_ca  [MT*Cv];
__device__ float g_cah [MT*32];
__device__ float g_cah2[MT*32];
__device__ float g_x1  [MT*Cv];
__device__ float g_h   [(size_t)Bv*FFH*Tv];   // (B,F,T)
__device__ float g_mlp [MT*Cv];
__device__ float g_gate[MT*Cv];
__device__ float g_vit32[MT*32];
__device__ float g_vitv[MT];
__device__ float g_vitf[MT];

// ---------------- bf16 split scratch ----------------
__device__ bf16 g_xn_h[MT*Cv],  g_xn_l[MT*Cv];
__device__ bf16 g_xm_h[MT*Cv],  g_xm_l[MT*Cv];
__device__ bf16 g_y_h [MT*Cv],  g_y_l [MT*Cv];
__device__ bf16 g_q_h [MT*1024],g_q_l [MT*1024];   // (b,t,h,d)
__device__ bf16 g_k_h [MT*256], g_k_l [MT*256];    // (b,t,kv,d)
__device__ bf16 g_v_h [MT*256], g_v_l [MT*256];    // (b,kv,d,t) transposed
__device__ bf16 g_hs_h[(size_t)MT*FFH], g_hs_l[(size_t)MT*FFH]; // (b,t,f)
__device__ bf16 g_wqkv_h[1536*1024], g_wqkv_l[1536*1024];
__device__ bf16 g_wo_h[1024*1024],  g_wo_l[1024*1024];
__device__ bf16 g_fin_h[FFH*1024],  g_fin_l[FFH*1024];
__device__ bf16 g_fout_h[1024*FFH], g_fout_l[1024*FFH];
__device__ bf16 g_fgt_h[1024*1024], g_fgt_l[1024*1024];

// =================== helpers ===================
__device__ __forceinline__ uint32_t smem_u32(const void* p){
    uint32_t a;
    asm("{ .reg .u64 t; cvta.to.shared.u64 t, %1; cvt.u32.u64 %0, t; }" : "=r"(a) : "l"(p));
    return a;
}
__device__ __forceinline__ void mma16816(float* c, const uint32_t* a, uint32_t b0, uint32_t b1){
    asm volatile("mma.sync.aligned.m16n8k16.row.col.f32.bf16.bf16.f32 "
        "{%0,%1,%2,%3}, {%4,%5,%6,%7}, {%8,%9}, {%0,%1,%2,%3};"
        : "+f"(c[0]), "+f"(c[1]), "+f"(c[2]), "+f"(c[3])
        : "r"(a[0]), "r"(a[1]), "r"(a[2]), "r"(a[3]), "r"(b0), "r"(b1));
}
__device__ __forceinline__ void ldsm4(uint32_t* r, uint32_t addr){
    asm volatile("ldmatrix.sync.aligned.m8n8.x4.shared.b16 {%0,%1,%2,%3}, [%4];"
        : "=r"(r[0]), "=r"(r[1]), "=r"(r[2]), "=r"(r[3]) : "r"(addr));
}
__device__ __forceinline__ void cpa16(uint32_t saddr, const void* g){
    asm volatile("cp.async.cg.shared.global [%0], [%1], 16;" :: "r"(saddr), "l"(g));
}
#define CPA_COMMIT() asm volatile("cp.async.commit_group;" ::: "memory")
#define CPA_WAIT(n)  asm volatile("cp.async.wait_group %0;" :: "n"(n) : "memory")

// 64B-row swizzle (tiles of 32 bf16 per row)
__device__ __forceinline__ uint32_t sw_off(int row, int k){
    int chunk = (k >> 3) ^ ((row >> 1) & 3);
    return (uint32_t)(row*64 + chunk*16 + (k & 7)*2);
}
// 128B-row swizzle (tiles of 64 bf16 per row)
__device__ __forceinline__ uint32_t sw128(int row, int k){
    return (uint32_t)(row*128 + ((((k>>3) ^ (row & 7)) << 4) | ((k & 7) << 1)));
}
__device__ __forceinline__ void split1(float v, bf16& h, bf16& l){
    h = __float2bfloat16(v);
    l = __float2bfloat16(v - __bfloat162float(h));
}

// ---------------- weight split ----------------
__global__ void split_kernel(const float* __restrict__ src, bf16* __restrict__ hi,
                             bf16* __restrict__ lo, int n4){
    int i = blockIdx.x*256 + threadIdx.x;
    if (i >= n4) return;
    float4 v = ((const float4*)src)[i];
    bf16 h0,h1,h2,h3,l0,l1,l2,l3;
    split1(v.x,h0,l0); split1(v.y,h1,l1); split1(v.z,h2,l2); split1(v.w,h3,l3);
    uint2 uh, ul;
    uh.x = ((uint32_t)__bfloat16_as_ushort(h1)<<16)|__bfloat16_as_ushort(h0);
    uh.y = ((uint32_t)__bfloat16_as_ushort(h3)<<16)|__bfloat16_as_ushort(h2);
    ul.x = ((uint32_t)__bfloat16_as_ushort(l1)<<16)|__bfloat16_as_ushort(l0);
    ul.y = ((uint32_t)__bfloat16_as_ushort(l3)<<16)|__bfloat16_as_ushort(l2);
    ((uint2*)hi)[i] = uh;
    ((uint2*)lo)[i] = ul;
}

// ---------------- rmsnorm (+ split output) ----------------
template<int WF32>
__global__ void rms_kernel(const float* __restrict__ x, float* __restrict__ o32,
                           bf16* __restrict__ ohi, bf16* __restrict__ olo){
    int row = blockIdx.x;
    const float* xr = x + (size_t)row*Cv;
    float ss = 0.f;
    for (int i = threadIdx.x; i < Cv; i += 256){ float v = xr[i]; ss += v*v; }
    __shared__ float red[8];
    for (int off=16; off>0; off>>=1) ss += __shfl_xor_sync(0xffffffffu, ss, off);
    if ((threadIdx.x & 31) == 0) red[threadIdx.x>>5] = ss;
    __syncthreads();
    if (threadIdx.x < 8){
        float v = red[threadIdx.x];
        for (int off=4; off>0; off>>=1) v += __shfl_xor_sync(0x000000ffu, v, off);
        if (threadIdx.x == 0) red[0] = v;
    }
    __syncthreads();
    float r = rsqrtf(red[0]*(1.0f/Cv) + 1e-6f);
    for (int i = threadIdx.x; i < Cv; i += 256){
        float v = xr[i]*r;
        if (WF32) o32[(size_t)row*Cv + i] = v;
        bf16 h,l; split1(v,h,l);
        ohi[(size_t)row*Cv + i] = h;
        olo[(size_t)row*Cv + i] = l;
    }
}

// =================== bf16 split GEMM (cp.async pipeline) ===================
// C[m,n] = sum_k A[m,k]*W[n,k]; tile 128x128, 512 thr, warps 4x4, warp tile 32x32.
// EPI 0: plain fp32 store. EPI 1: relu^2 to (B,N,T) fp32.
#define GSTG 32768
#define GEMM_SMEM (3*GSTG)
template<int EPI>
__global__ void __launch_bounds__(512,1)
gemm_bf16(const bf16* __restrict__ Ahi, const bf16* __restrict__ Alo,
          const bf16* __restrict__ Bhi, const bf16* __restrict__ Blo,
          float* __restrict__ Cg, int N, int K){
    extern __shared__ char smem[];
    const int tid = threadIdx.x, lane = tid & 31, wid = tid >> 5;
    const int warpM = wid & 3, warpN = wid >> 2;
    const int m0 = blockIdx.y << 7, n0 = blockIdx.x << 7;
    const int b = m0 >> 10, tb = m0 & 1023;
    uint32_t sb = smem_u32(smem);

    const int r = tid >> 2, kc = tid & 3;
    const bf16* srcs[4] = { Ahi + (size_t)(m0+r)*K + (kc<<3),
                            Alo + (size_t)(m0+r)*K + (kc<<3),
                            Bhi + (size_t)(n0+r)*K + (kc<<3),
                            Blo + (size_t)(n0+r)*K + (kc<<3) };
    uint32_t dsw = sw_off(r, kc<<3);

    auto ISSUE = [&](int c, int s){
        int k0 = c << 5;
        #pragma unroll
        for (int i=0;i<4;i++)
            cpa16(sb + s*GSTG + i*8192 + dsw, srcs[i] + k0);
        CPA_COMMIT();
    };

    float acc[2][4][4];
    #pragma unroll
    for (int i=0;i<2;i++)
        #pragma unroll
        for (int j=0;j<4;j++)
            #pragma unroll
            for (int q=0;q<4;q++) acc[i][j][q]=0.f;

    const int NC = K >> 5;
    ISSUE(0,0);
    ISSUE(1,1);
    const int lr = lane & 15, lc = (lane < 16) ? 0 : 8;
    for (int c = 0; c < NC; c++){
        CPA_WAIT(1);
        __syncthreads();
        if (c + 2 < NC) ISSUE(c+2, (c+2)%3);
        int st = c % 3;
        uint32_t sA = sb + st*GSTG;
        #pragma unroll
        for (int kk = 0; kk < 32; kk += 16){
            uint32_t ah[2][4], al[2][4];
            #pragma unroll
            for (int mt=0; mt<2; mt++){
                uint32_t off = sw_off(warpM*32 + mt*16 + lr, kk + lc);
                ldsm4(ah[mt], sA + off);
                ldsm4(al[mt], sA + 8192 + off);
            }
            #pragma unroll
            for (int nb=0; nb<2; nb++){
                uint32_t off = sw_off(warpN*32 + nb*16 + lr, kk + lc);
                uint32_t bh[4], bl[4];
                ldsm4(bh, sA + 16384 + off);
                ldsm4(bl, sA + 24576 + off);
                #pragma unroll
                for (int mt=0; mt<2; mt++){
                    mma16816(acc[mt][nb*2+0], ah[mt], bh[0], bh[2]);
                    mma16816(acc[mt][nb*2+0], ah[mt], bl[0], bl[2]);
                    mma16816(acc[mt][nb*2+0], al[mt], bh[0], bh[2]);
                    mma16816(acc[mt][nb*2+1], ah[mt], bh[1], bh[3]);
                    mma16816(acc[mt][nb*2+1], ah[mt], bl[1], bl[3]);
                    mma16816(acc[mt][nb*2+1], al[mt], bh[1], bh[3]);
                }
            }
        }
    }
    __syncthreads();

    const int g = lane >> 2, t2 = (lane & 3) << 1;
    if (EPI == 0){
        #pragma unroll
        for (int mt=0; mt<2; mt++){
            int m = m0 + warpM*32 + mt*16 + g;
            #pragma unroll
            for (int ni=0; ni<4; ni++){
                int n = n0 + warpN*32 + ni*8 + t2;
                *(float2*)(Cg + (size_t)m*N + n) = make_float2(acc[mt][ni][0], acc[mt][ni][1]);
                *(float2*)(Cg + (size_t)(m+8)*N + n) = make_float2(acc[mt][ni][2], acc[mt][ni][3]);
            }
        }
    } else {
        float* ep = (float*)smem;   // 64 x 136
        #pragma unroll
        for (int slab=0; slab<2; slab++){
            __syncthreads();
            if ((warpN >> 1) == slab){
                #pragma unroll
                for (int mt=0; mt<2; mt++){
                    int mloc = warpM*32 + mt*16 + g;
                    #pragma unroll
                    for (int ni=0; ni<4; ni++){
                        int nL = (warpN & 1)*32 + ni*8 + t2;
                        ep[nL*136 + mloc]         = acc[mt][ni][0];
                        ep[(nL+1)*136 + mloc]     = acc[mt][ni][1];
                        ep[nL*136 + mloc + 8]     = acc[mt][ni][2];
                        ep[(nL+1)*136 + mloc + 8] = acc[mt][ni][3];
                    }
                }
            }
            __syncthreads();
            #pragma unroll
            for (int i=0;i<4;i++){
                int idx = tid + (i << 9);
                int nr = idx >> 5, t4 = (idx & 31) << 2;
                float a0 = fmaxf(ep[nr*136 + t4 + 0], 0.f);
                float a1 = fmaxf(ep[nr*136 + t4 + 1], 0.f);
                float a2 = fmaxf(ep[nr*136 + t4 + 2], 0.f);
                float a3 = fmaxf(ep[nr*136 + t4 + 3], 0.f);
                int n = n0 + slab*64 + nr;
                *(float4*)(Cg + ((size_t)b*N + n)*1024 + tb + t4)
                    = make_float4(a0*a0, a1*a1, a2*a2, a3*a3);
            }
        }
    }
}

// ---------------- small-N (=32) GEMM ----------------
template<int EPI>
__global__ void __launch_bounds__(256)
gemm32_kernel(const float* __restrict__ A, const float* __restrict__ W, float* __restrict__ Cg){
    __shared__ float xs[8*1024];
    int row0 = blockIdx.x << 3;
    #pragma unroll
    for (int i = 0; i < 8; i++){
        int f4 = threadIdx.x + (i << 8);
        ((float4*)xs)[f4] = ((const float4*)(A + ((size_t)row0 << 10)))[f4];
    }
    __syncthreads();
    int w = threadIdx.x >> 5, n = threadIdx.x & 31;
    const float4* Wr = (const float4*)(W + (size_t)n*1024);
    const float4* xr = (const float4*)(xs + (w << 10));
    float acc = 0.f;
    #pragma unroll 4
    for (int k = 0; k < 256; k++){
        float4 a = xr[k], b = Wr[k];
        acc += a.x*b.x + a.y*b.y + a.z*b.z + a.w*b.w;
    }
    if (EPI == 2) acc = 0.5f*acc*(1.f + erff(acc*0.70710678118f));
    Cg[((size_t)(row0 + w) << 5) + n] = acc;
}

// ---------------- FFMA GEMM (ca_po, K=32) ----------------
__global__ void __launch_bounds__(256,2)
gemm_k32(const float* __restrict__ A, const float* __restrict__ W,
         float* __restrict__ Cg, int N){
    __shared__ float As[32*132];
    __shared__ float Ws[32*132];
    const int tx = threadIdx.x & 15, ty = threadIdx.x >> 4;
    const int m0 = blockIdx.y << 7, n0 = blockIdx.x << 7;
    float acc[8][8];
    #pragma unroll
    for (int i=0;i<8;i++)
        #pragma unroll
        for (int j=0;j<8;j++) acc[i][j]=0.f;
    const int r = threadIdx.x >> 1;
    const int c4 = (threadIdx.x & 1) << 4;
    #pragma unroll
    for (int q=0;q<4;q++){
        float4 a0 = *(const float4*)(A + (size_t)(m0+r)*32 + c4 + q*4);
        As[(c4+q*4+0)*132 + r] = a0.x; As[(c4+q*4+1)*132 + r] = a0.y;
        As[(c4+q*4+2)*132 + r] = a0.z; As[(c4+q*4+3)*132 + r] = a0.w;
        float4 w0 = *(const float4*)(W + (size_t)(n0+r)*32 + c4 + q*4);
        Ws[(c4+q*4+0)*132 + r] = w0.x; Ws[(c4+q*4+1)*132 + r] = w0.y;
        Ws[(c4+q*4+2)*132 + r] = w0.z; Ws[(c4+q*4+3)*132 + r] = w0.w;
    }
    __syncthreads();
    #pragma unroll
    for (int kk=0; kk<32; kk++){
        float av[8], bv[8];
        *(float4*)&av[0] = *(const float4*)(As + kk*132 + (ty<<3));
        *(float4*)&av[4] = *(const float4*)(As + kk*132 + (ty<<3) + 4);
        *(float4*)&bv[0] = *(const float4*)(Ws + kk*132 + (tx<<3));
        *(float4*)&bv[4] = *(const float4*)(Ws + kk*132 + (tx<<3) + 4);
        #pragma unroll
        for (int i=0;i<8;i++)
            #pragma unroll
            for (int j=0;j<8;j++) acc[i][j] += av[i]*bv[j];
    }
    #pragma unroll
    for (int i=0;i<8;i++){
        int mg = m0 + (ty<<3) + i;
        #pragma unroll
        for (int j=0;j<8;j++)
            Cg[(size_t)mg*N + n0 + (tx<<3) + j] = acc[i][j];
    }
}

// ---------------- VE gate + V update -> transposed split ----------------
__global__ void vgate_kernel(const float* __restrict__ xn, const float* __restrict__ ve,
                             const float* __restrict__ wg, const float* __restrict__ qkv,
                             bf16* __restrict__ vhi, bf16* __restrict__ vlo){
    int row = blockIdx.x;
    __shared__ float gs[4];
    if (threadIdx.x < 4){
        float s = 0.f;
        #pragma unroll
        for (int c=0;c<12;c++) s += xn[(size_t)row*Cv + c]*wg[threadIdx.x*12 + c];
        gs[threadIdx.x] = 3.f/(1.f + expf(-s));
    }
    __syncthreads();
    int i = threadIdx.x;
    int kv = i >> 6, d = i & 63;
    float vv = qkv[(size_t)row*1536 + 1280 + i] + gs[kv]*ve[(size_t)row*256 + i];
    bf16 h,l; split1(vv,h,l);
    size_t o = ((size_t)((row>>10)*4 + kv)*64 + d)*1024 + (row & 1023);
    vhi[o] = h; vlo[o] = l;
}

// ---------------- rope + per-head rmsnorm*1.2 -> split ----------------
__global__ void ropeRms_kernel(const float* __restrict__ src, int srcStride, int srcOff,
                               bf16* __restrict__ dhi, bf16* __restrict__ dlo,
                               const float* __restrict__ cosb, const float* __restrict__ sinb,
                               int nheads){
    int row  = blockIdx.x;
    int t    = row & (Tv-1);
    int head = blockIdx.y*4 + (threadIdx.x >> 5);
    if (head >= nheads) return;
    int lane = threadIdx.x & 31;
    const float* p = src + (size_t)row*srcStride + srcOff + head*HD;
    float x1 = p[lane], x2 = p[lane+32];
    float cc = cosb[t*32 + lane], sn = sinb[t*32 + lane];
    float o1 =  x1*cc + x2*sn;
    float o2 = -x1*sn + x2*cc;
    float ss = o1*o1 + o2*o2;
    for (int off=16; off>0; off>>=1) ss += __shfl_xor_sync(0xffffffffu, ss, off);
    float rr = rsqrtf(ss*(1.0f/HD) + 1e-6f)*1.2f;
    o1 *= rr; o2 *= rr;
    size_t base = ((size_t)row*nheads + head)*HD;
    bf16 h,l;
    split1(o1,h,l); dhi[base+lane] = h;    dlo[base+lane] = l;
    split1(o2,h,l); dhi[base+lane+32] = h; dlo[base+lane+32] = l;
}

// =================== flash attention with mma.sync ===================
#define SM_QHI 0
#define SM_QLO 8192
#define SM_KHI 16384
#define SM_KLO 24576
#define SM_VHI 32768
#define SM_VLO 40960
#define SM_PP  49152
#define SM_S   66848
#define SM_PHI 85792
#define SM_PLO 93984
#define SM_CORR 102176
#define SM_LINV 102432
#define ATTN_SMEM 102688

__global__ void __launch_bounds__(256)
attn_kernel(const bf16* __restrict__ qhi, const bf16* __restrict__ qlo,
            const bf16* __restrict__ khi, const bf16* __restrict__ klo,
            const bf16* __restrict__ vhi, const bf16* __restrict__ vlo,
            const float* __restrict__ prev, const float* __restrict__ rw,
            const float* __restrict__ alphap,
            bf16* __restrict__ yhi, bf16* __restrict__ ylo){
    extern __shared__ char smc[];
    uint32_t sb = smem_u32(smc);
    float* PP   = (float*)(smc + SM_PP);   // stride 67
    float* S    = (float*)(smc + SM_S);    // stride 74
    float* corr_s = (float*)(smc + SM_CORR);
    float* linv   = (float*)(smc + SM_LINV);

    const int tid = threadIdx.x, lane = tid & 31, wid = tid >> 5;
    const int warpM = wid & 3, warpN = wid >> 2;
    const int row = tid >> 2, quad = tid & 3, c0 = quad << 4;
    const int qt = blockIdx.x, h = blockIdx.y, b = blockIdx.z;
    const int q0 = qt << 6;
    const int kvh = h >> 2;
    const int lr = lane & 15, lc = (lane < 16) ? 0 : 8;
    const int g = lane >> 2, t2 = (lane & 3) << 1;

    const float alpha = alphap[0];
    float w9[9];
    #pragma unroll
    for (int i=0;i<9;i++) w9[i] = alpha*rw[h*9 + i];

    // Q tiles via cp.async (1024 chunks)
    {
        #pragma unroll
        for (int i=0;i<4;i++){
            int idx = tid + (i << 8);
            int arr = idx >> 9, rr = (idx >> 3) & 63, kc = idx & 7;
            const bf16* src = (arr ? qlo : qhi) + ((((size_t)(b*Tv + q0 + rr))*NH + h) << 6) + (kc << 3);
            cpa16(sb + arr*8192 + sw128(rr, kc << 3), src);
        }
        CPA_COMMIT();
    }

    float o[4][4];
    #pragma unroll
    for (int i=0;i<4;i++)
        #pragma unroll
        for (int j=0;j<4;j++) o[i][j]=0.f;
    float m = -1e30f, l = 0.f;

    for (int kt = 0; kt <= qt; kt++){
        int k0 = kt << 6;
        // K/V tiles (2048 chunks)
        #pragma unroll
        for (int i=0;i<8;i++){
            int idx = tid + (i << 8);
            int arr = idx >> 9, rr = (idx >> 3) & 63, kc = idx & 7;
            const bf16* src;
            if (arr < 2) src = (arr ? klo : khi) + ((((size_t)(b*Tv + k0 + rr))*NKV + kvh) << 6) + (kc << 3);
            else         src = (arr == 2 ? vhi : vlo) + (((size_t)((b*NKV + kvh)*64 + rr)) << 10) + k0 + (kc << 3);
            cpa16(sb + SM_KHI + arr*8192 + sw128(rr, kc << 3), src);
        }
        CPA_COMMIT();
        // prev halo tile (scalar)
        for (int idx = tid; idx < 66*66; idx += 256){
            int i = idx/66, j = idx - i*66;
            int rr = q0 - 1 + i, cg = k0 - 1 + j;
            float pv = 0.f;
            if (rr >= 0 && rr < Tv && cg >= 0 && cg < Tv)
                pv = prev[(((size_t)(b*NH + h))*Tv + rr)*Tv + cg];
            PP[i*67 + j] = pv;
        }
        CPA_WAIT(0);
        __syncthreads();

        // ---- QK^T mma ----
        float c[4][4];
        #pragma unroll
        for (int i=0;i<4;i++)
            #pragma unroll
            for (int j=0;j<4;j++) c[i][j]=0.f;
        #pragma unroll
        for (int k16 = 0; k16 < 4; k16++){
            uint32_t qh_[4], ql_[4];
            uint32_t offq = sw128(warpM*16 + lr, k16*16 + lc);
            ldsm4(qh_, sb + SM_QHI + offq);
            ldsm4(ql_, sb + SM_QLO + offq);
            #pragma unroll
            for (int nb=0; nb<2; nb++){
                uint32_t offk = sw128(warpN*32 + nb*16 + lr, k16*16 + lc);
                uint32_t kh_[4], kl_[4];
                ldsm4(kh_, sb + SM_KHI + offk);
                ldsm4(kl_, sb + SM_KLO + offk);
                mma16816(c[nb*2+0], qh_, kh_[0], kh_[2]);
                mma16816(c[nb*2+0], qh_, kl_[0], kl_[2]);
                mma16816(c[nb*2+0], ql_, kh_[0], kh_[2]);
                mma16816(c[nb*2+1], qh_, kh_[1], kh_[3]);
                mma16816(c[nb*2+1], qh_, kl_[1], kl_[3]);
                mma16816(c[nb*2+1], ql_, kh_[1], kh_[3]);
            }
        }
        // write scores to smem
        #pragma unroll
        for (int ni=0; ni<4; ni++){
            int col = warpN*32 + ni*8 + t2;
            int r0 = warpM*16 + g;
            *(float2*)(S + r0*74 + col)     = make_float2(c[ni][0], c[ni][1]);
            *(float2*)(S + (r0+8)*74 + col) = make_float2(c[ni][2], c[ni][3]);
        }
        __syncthreads();

        // ---- scalar: conv + mask + softmax + split-P ----
        float s[16];
        #pragma unroll
        for (int j=0;j<16;j++){
            int col = c0 + j;
            const float* p0 = PP + (row+0)*67 + col;
            const float* p1 = PP + (row+1)*67 + col;
            const float* p2 = PP + (row+2)*67 + col;
            float cv = w9[0]*p0[0] + w9[1]*p0[1] + w9[2]*p0[2]
                     + w9[3]*p1[0] + w9[4]*p1[1] + w9[5]*p1[2]
                     + w9[6]*p2[0] + w9[7]*p2[1] + w9[8]*p2[2];
            s[j] = S[row*74 + col]*0.125f + cv;
            if (kt == qt && col > row) s[j] = -1e30f;
        }
        float mt = s[0];
        #pragma unroll
        for (int j=1;j<16;j++) mt = fmaxf(mt, s[j]);
        for (int off=1; off<4; off<<=1) mt = fmaxf(mt, __shfl_xor_sync(0xffffffffu, mt, off));
        float mnew = fmaxf(m, mt);
        float corrv = __expf(m - mnew);
        float ls = 0.f;
        #pragma unroll
        for (int j=0;j<16;j++){ s[j] = __expf(s[j] - mnew); ls += s[j]; }
        for (int off=1; off<4; off<<=1) ls += __shfl_xor_sync(0xffffffffu, ls, off);
        l = l*corrv + ls;
        m = mnew;
        if (quad == 0) corr_s[row] = corrv;
        #pragma unroll
        for (int j=0;j<16;j++){
            int col = c0 + j;
            bf16 ph, pl; split1(s[j], ph, pl);
            uint32_t off = sw128(row, col);
            *(bf16*)(smc + SM_PHI + off) = ph;
            *(bf16*)(smc + SM_PLO + off) = pl;
        }
        __syncthreads();

        // ---- PV mma ----
        float cr0 = corr_s[warpM*16 + g], cr1 = corr_s[warpM*16 + g + 8];
        #pragma unroll
        for (int ni=0; ni<4; ni++){
            o[ni][0] *= cr0; o[ni][1] *= cr0;
            o[ni][2] *= cr1; o[ni][3] *= cr1;
        }
        #pragma unroll
        for (int k16 = 0; k16 < 4; k16++){
            uint32_t ph_[4], pl_[4];
            uint32_t offp = sw128(warpM*16 + lr, k16*16 + lc);
            ldsm4(ph_, sb + SM_PHI + offp);
            ldsm4(pl_, sb + SM_PLO + offp);
            #pragma unroll
            for (int nb=0; nb<2; nb++){
                uint32_t offv = sw128(warpN*32 + nb*16 + lr, k16*16 + lc);
                uint32_t vh_[4], vl_[4];
                ldsm4(vh_, sb + SM_VHI + offv);
                ldsm4(vl_, sb + SM_VLO + offv);
                mma16816(o[nb*2+0], ph_, vh_[0], vh_[2]);
                mma16816(o[nb*2+0], ph_, vl_[0], vl_[2]);
                mma16816(o[nb*2+0], pl_, vh_[0], vh_[2]);
                mma16816(o[nb*2+1], ph_, vh_[1], vh_[3]);
                mma16816(o[nb*2+1], ph_, vl_[1], vl_[3]);
                mma16816(o[nb*2+1], pl_, vh_[1], vh_[3]);
            }
        }
        __syncthreads();
    }

    if (quad == 0) linv[row] = 1.f/l;
    __syncthreads();
    float i0 = linv[warpM*16 + g], i1 = linv[warpM*16 + g + 8];
    #pragma unroll
    for (int ni=0; ni<4; ni++){
        int col = warpN*32 + ni*8 + t2;
        float v00 = o[ni][0]*i0, v01 = o[ni][1]*i0;
        float v10 = o[ni][2]*i1, v11 = o[ni][3]*i1;
        bf16 h0,l0,h1,l1;
        size_t base0 = ((((size_t)(b*Tv + q0 + warpM*16 + g))*NH + h) << 6) + col;
        size_t base1 = ((((size_t)(b*Tv + q0 + warpM*16 + g + 8))*NH + h) << 6) + col;
        split1(v00,h0,l0); split1(v01,h1,l1);
        *(uint32_t*)(yhi + base0) = ((uint32_t)__bfloat16_as_ushort(h1)<<16)|__bfloat16_as_ushort(h0);
        *(uint32_t*)(ylo + base0) = ((uint32_t)__bfloat16_as_ushort(l1)<<16)|__bfloat16_as_ushort(l0);
        split1(v10,h0,l0); split1(v11,h1,l1);
        *(uint32_t*)(yhi + base1) = ((uint32_t)__bfloat16_as_ushort(h1)<<16)|__bfloat16_as_ushort(h0);
        *(uint32_t*)(ylo + base1) = ((uint32_t)__bfloat16_as_ushort(l1)<<16)|__bfloat16_as_ushort(l0);
    }
}

// ---------------- CA conv + gelu ----------------
__global__ void caconv_kernel(const float* __restrict__ hin, const float* __restrict__ cw,
                              float* __restrict__ hout){
    int ch = blockIdx.x, b = blockIdx.y;
    __shared__ float s[Tv+2];
    for (int t = threadIdx.x; t < Tv; t += 256) s[1+t] = hin[((size_t)b*Tv + t)*32 + ch];
    if (threadIdx.x == 0){ s[0] = 0.f; s[Tv+1] = 0.f; }
    __syncthreads();
    float w0 = cw[ch*3], w1 = cw[ch*3+1], w2 = cw[ch*3+2];
    for (int t = threadIdx.x; t < Tv; t += 256){
        float vv = s[1+t] + 0.1f*(w0*s[t] + w1*s[1+t] + w2*s[2+t]);
        hout[((size_t)b*Tv + t)*32 + ch] = 0.5f*vv*(1.f + erff(vv*0.70710678118f));
    }
}

// ---------------- FFN conv x4 + transpose to split (B,T,F) ----------------
#define FFNC_SMEM (2*16*1026*4)
__global__ void __launch_bounds__(256)
ffnconvT_kernel(const float* __restrict__ h, const float* __restrict__ cw,
                bf16* __restrict__ hhi, bf16* __restrict__ hlo){
    extern __shared__ float fs[];
    float (*buf0)[1026] = (float(*)[1026])fs;
    float (*buf1)[1026] = (float(*)[1026])(fs + 16*1026);
    int f0 = blockIdx.x << 4, b = blockIdx.y;
    for (int idx = threadIdx.x; idx < 16*1024; idx += 256){
        int cch = idx >> 10, t = idx & 1023;
        buf0[cch][1+t] = h[((size_t)(b*FFH + f0 + cch)) * Tv + t];
    }
    if (threadIdx.x < 16){
        buf0[threadIdx.x][0] = 0.f; buf0[threadIdx.x][1025] = 0.f;
        buf1[threadIdx.x][0] = 0.f; buf1[threadIdx.x][1025] = 0.f;
    }
    int cch = threadIdx.x >> 4, j = threadIdx.x & 15;
    float w0 = cw[(f0+cch)*3], w1 = cw[(f0+cch)*3+1], w2 = cw[(f0+cch)*3+2];
    float (*cur)[1026] = buf0; float (*nxt)[1026] = buf1;
    #pragma unroll
    for (int it=0; it<4; it++){
        __syncthreads();
        #pragma unroll 4
        for (int t = j*64; t < j*64 + 64; t++)
            nxt[cch][1+t] = cur[cch][1+t] + 0.1f*(w0*cur[cch][t] + w1*cur[cch][1+t] + w2*cur[cch][2+t]);
        float (*tmp)[1026] = cur; cur = nxt; nxt = tmp;
    }
    __syncthreads();
    // transpose write: thread -> t values, 16 channels each
    for (int t = threadIdx.x; t < Tv; t += 256){
        uint32_t wh[8], wl[8];
        #pragma unroll
        for (int cc = 0; cc < 16; cc += 2){
            bf16 h0,l0,h1,l1;
            split1(cur[cc][1+t],   h0, l0);
            split1(cur[cc+1][1+t], h1, l1);
            wh[cc>>1] = ((uint32_t)__bfloat16_as_ushort(h1)<<16)|__bfloat16_as_ushort(h0);
            wl[cc>>1] = ((uint32_t)__bfloat16_as_ushort(l1)<<16)|__bfloat16_as_ushort(l0);
        }
        size_t o = ((size_t)(b*Tv + t))*FFH + f0;
        *(uint4*)(hhi + o)     = make_uint4(wh[0],wh[1],wh[2],wh[3]);
        *(uint4*)(hhi + o + 8) = make_uint4(wh[4],wh[5],wh[6],wh[7]);
        *(uint4*)(hlo + o)     = make_uint4(wl[0],wl[1],wl[2],wl[3]);
        *(uint4*)(hlo + o + 8) = make_uint4(wl[4],wl[5],wl[6],wl[7]);
    }
}

// ---------------- elementwise ----------------
__global__ void x1_kernel(const float* __restrict__ x, const float* __restrict__ attn,
                          const float* __restrict__ ca, float* __restrict__ x1, int n){
    for (int i = blockIdx.x*blockDim.x + threadIdx.x; i < n; i += gridDim.x*blockDim.x)
        x1[i] = x[i] + attn[i]*(1.f + 0.1f*tanhf(ca[i]));
}
__global__ void vit2_kernel(const float* __restrict__ h32, const float* __restrict__ w2,
                            float* __restrict__ out){
    int row  = blockIdx.x*8 + (threadIdx.x >> 5);
    int lane = threadIdx.x & 31;
    float vv = h32[(size_t)row*32 + lane]*w2[lane];
    for (int off=16; off>0; off>>=1) vv += __shfl_xor_sync(0xffffffffu, vv, off);
    if (lane == 0) out[row] = 1.f/(1.f + expf(-vv));
}
__global__ void vitsmooth_kernel(const float* __restrict__ vin, float* __restrict__ vout){
    int b = blockIdx.x;
    __shared__ float s[Tv+4];
    for (int t = threadIdx.x; t < Tv; t += 256) s[2+t] = vin[b*Tv + t];
    if (threadIdx.x < 2){ s[threadIdx.x] = 0.f; s[Tv+2+threadIdx.x] = 0.f; }
    __syncthreads();
    for (int t = threadIdx.x; t < Tv; t += 256){
        float vs = (s[t] + s[t+1] + s[t+2] + s[t+3] + s[t+4])*0.2f;
        float vv = 0.7f*s[2+t] + 0.3f*vs;
        vout[b*Tv + t] = (vv > 0.3f) ? vv : 0.1f*vv;
    }
}
__global__ void final_kernel(const float* __restrict__ x1, const float* __restrict__ mlp,
                             const float* __restrict__ gate, const float* __restrict__ ca,
                             const float* __restrict__ vitf, float* __restrict__ out, int n){
    for (int i = blockIdx.x*blockDim.x + threadIdx.x; i < n; i += gridDim.x*blockDim.x){
        int row = i >> 10;
        float gg = 1.f/(1.f + expf(-gate[i]));
        out[i] = x1[i] + mlp[i]*gg*(1.f + 0.1f*tanhf(ca[i]))*vitf[row];
    }
}

// ---------------- launch ----------------
extern "C" void kernel_launch(void* const* d_in, const int* in_sizes, int n_in,
                              void* d_out, int out_size){
    const float* x     = (const float*)d_in[0];
    const float* ve    = (const float*)d_in[1];
    const float* cosp  = (const float*)d_in[2];
    const float* sinp  = (const float*)d_in[3];
    const float* prev  = (const float*)d_in[4];
    const float* w_q   = (const float*)d_in[5];
    const float* w_k   = (const float*)d_in[6];
    const float* w_v   = (const float*)d_in[7];
    const float* w_o   = (const float*)d_in[8];
    const float* w_veg = (const float*)d_in[9];
    const float* rfw   = (const float*)d_in[10];
    const float* ralpha= (const float*)d_in[11];
    const float* ca_pi = (const float*)d_in[12];
    const float* ca_cw = (const float*)d_in[13];
    const float* ca_po = (const float*)d_in[14];
    const float* ffn_in= (const float*)d_in[15];
    const float* ffn_cw= (const float*)d_in[16];
    const float* ffn_outw=(const float*)d_in[17];
    const float* ffn_gt= (const float*)d_in[18];
    const float* vit_w1= (const float*)d_in[19];
    const float* vit_w2= (const float*)d_in[20];
    float* out = (float*)d_out;

    float *xn,*qkv,*attn,*ca,*cah,*cah2,*x1,*h,*mlp,*gate,*vit32,*vitv,*vitf;
    bf16 *xnh,*xnl,*xmh,*xml,*yh,*yl,*qh,*ql,*kh,*kl,*vh,*vl,*hsh,*hsl;
    bf16 *wqkvh,*wqkvl,*woh,*wol,*finh,*finl,*fouth,*foutl,*fgth,*fgtl;
    cudaGetSymbolAddress((void**)&xn, g_xn);     cudaGetSymbolAddress((void**)&qkv, g_qkv);
    cudaGetSymbolAddress((void**)&attn, g_attn); cudaGetSymbolAddress((void**)&ca, g_ca);
    cudaGetSymbolAddress((void**)&cah, g_cah);   cudaGetSymbolAddress((void**)&cah2, g_cah2);
    cudaGetSymbolAddress((void**)&x1, g_x1);     cudaGetSymbolAddress((void**)&h, g_h);
    cudaGetSymbolAddress((void**)&mlp, g_mlp);   cudaGetSymbolAddress((void**)&gate, g_gate);
    cudaGetSymbolAddress((void**)&vit32, g_vit32); cudaGetSymbolAddress((void**)&vitv, g_vitv);
    cudaGetSymbolAddress((void**)&vitf, g_vitf);
    cudaGetSymbolAddress((void**)&xnh, g_xn_h);  cudaGetSymbolAddress((void**)&xnl, g_xn_l);
    cudaGetSymbolAddress((void**)&xmh, g_xm_h);  cudaGetSymbolAddress((void**)&xml, g_xm_l);
    cudaGetSymbolAddress((void**)&yh, g_y_h);    cudaGetSymbolAddress((void**)&yl, g_y_l);
    cudaGetSymbolAddress((void**)&qh, g_q_h);    cudaGetSymbolAddress((void**)&ql, g_q_l);
    cudaGetSymbolAddress((void**)&kh, g_k_h);    cudaGetSymbolAddress((void**)&kl, g_k_l);
    cudaGetSymbolAddress((void**)&vh, g_v_h);    cudaGetSymbolAddress((void**)&vl, g_v_l);
    cudaGetSymbolAddress((void**)&hsh, g_hs_h);  cudaGetSymbolAddress((void**)&hsl, g_hs_l);
    cudaGetSymbolAddress((void**)&wqkvh, g_wqkv_h); cudaGetSymbolAddress((void**)&wqkvl, g_wqkv_l);
    cudaGetSymbolAddress((void**)&woh, g_wo_h);  cudaGetSymbolAddress((void**)&wol, g_wo_l);
    cudaGetSymbolAddress((void**)&finh, g_fin_h); cudaGetSymbolAddress((void**)&finl, g_fin_l);
    cudaGetSymbolAddress((void**)&fouth, g_fout_h); cudaGetSymbolAddress((void**)&foutl, g_fout_l);
    cudaGetSymbolAddress((void**)&fgth, g_fgt_h); cudaGetSymbolAddress((void**)&fgtl, g_fgt_l);

    cudaFuncSetAttribute(attn_kernel, cudaFuncAttributeMaxDynamicSharedMemorySize, ATTN_SMEM);
    cudaFuncSetAttribute(gemm_bf16<0>, cudaFuncAttributeMaxDynamicSharedMemorySize, GEMM_SMEM);
    cudaFuncSetAttribute(gemm_bf16<1>, cudaFuncAttributeMaxDynamicSharedMemorySize, GEMM_SMEM);
    cudaFuncSetAttribute(ffnconvT_kernel, cudaFuncAttributeMaxDynamicSharedMemorySize, FFNC_SMEM);

    // weight splits (qkv fused into one 1536xK buffer)
    split_kernel<<<1024,256>>>(w_q, wqkvh, wqkvl, 262144);
    split_kernel<<<256,256>>>(w_k, wqkvh + 1024*1024, wqkvl + 1024*1024, 65536);
    split_kernel<<<256,256>>>(w_v, wqkvh + 1280*1024, wqkvl + 1280*1024, 65536);
    split_kernel<<<1024,256>>>(w_o, woh, wol, 262144);
    split_kernel<<<4096,256>>>(ffn_in, finh, finl, 1048576);
    split_kernel<<<4096,256>>>(ffn_outw, fouth, foutl, 1048576);
    split_kernel<<<1024,256>>>(ffn_gt, fgth, fgtl, 262144);

    // xn = rmsnorm(x) (fp32 + split); fused QKV GEMM
    rms_kernel<1><<<MT,256>>>(x, xn, xnh, xnl);
    gemm_bf16<0><<<dim3(12,32),512,GEMM_SMEM>>>(xnh, xnl, wqkvh, wqkvl, qkv, 1536, 1024);
    vgate_kernel<<<MT,256>>>(xn, ve, w_veg, qkv, vh, vl);
    ropeRms_kernel<<<dim3(MT,4),128>>>(qkv, 1536, 0,    qh, ql, cosp, sinp, NH);
    ropeRms_kernel<<<dim3(MT,1),128>>>(qkv, 1536, 1024, kh, kl, cosp, sinp, NKV);

    // attention (mma) + w_o
    attn_kernel<<<dim3(16,NH,Bv),256,ATTN_SMEM>>>(qh, ql, kh, kl, vh, vl, prev, rfw, ralpha, yh, yl);
    gemm_bf16<0><<<dim3(8,32),512,GEMM_SMEM>>>(yh, yl, woh, wol, attn, 1024, 1024);

    // ca1 on x; x1
    gemm32_kernel<0><<<512,256>>>(x, ca_pi, cah);
    caconv_kernel<<<dim3(32,Bv),256>>>(cah, ca_cw, cah2);
    gemm_k32<<<dim3(8,32),256>>>(cah2, ca_po, ca, 1024);
    x1_kernel<<<4096,256>>>(x, attn, ca, x1, MT*Cv);

    // FFN
    rms_kernel<0><<<MT,256>>>(x1, (float*)0, xmh, xml);
    gemm_bf16<1><<<dim3(32,32),512,GEMM_SMEM>>>(xmh, xml, finh, finl, h, FFH, 1024);
    ffnconvT_kernel<<<dim3(256,Bv),256,FFNC_SMEM>>>(h, ffn_cw, hsh, hsl);
    gemm_bf16<0><<<dim3(8,32),512,GEMM_SMEM>>>(hsh, hsl, fouth, foutl, mlp, 1024, 4096);
    gemm_bf16<0><<<dim3(8,32),512,GEMM_SMEM>>>(xmh, xml, fgth, fgtl, gate, 1024, 1024);

    // ca2 on x1
    gemm32_kernel<0><<<512,256>>>(x1, ca_pi, cah);
    caconv_kernel<<<dim3(32,Bv),256>>>(cah, ca_cw, cah2);
    gemm_k32<<<dim3(8,32),256>>>(cah2, ca_po, ca, 1024);

    // vit gate
    gemm32_kernel<2><<<512,256>>>(x1, vit_w1, vit32);
    vit2_kernel<<<512,256>>>(vit32, vit_w2, vitv);
    vitsmooth_kernel<<<Bv,256>>>(vitv, vitf);

    final_kernel<<<4096,256>>>(x1, mlp, gate, ca, vitf, out, MT*Cv);
}

// round 5
// speedup vs baseline: 2.1447x; 1.0150x over previous
#include <cuda_runtime.h>
#include <cuda_bf16.h>
#include <math.h>
#include <stdint.h>

#define Bv  4
#define Tv  1024
#define Cv  1024
#define NH  16
#define NKV 4
#define HD  64
#define FFH 4096
#define MT  (Bv*Tv)

typedef __nv_bfloat16 bf16;

// ---------------- fp32 scratch ----------------
__device__ float g_xn  [MT*Cv];
__device__ float g_qkv [MT*1536];
__device__ float g_attn[MT*Cv];
__device__ float g_ca  [MT*Cv];
__device__ float g_cah [MT*32];
__device__ float g_cah2[MT*32];
__device__ float g_x1  [MT*Cv];
__device__ float g_mlp [MT*Cv];
__device__ float g_gate[MT*Cv];
__device__ float g_vit32[MT*32];
__device__ float g_vitv[MT];
__device__ float g_vitf[MT];

// ---------------- bf16 split scratch ----------------
__device__ bf16 g_xn_h[MT*Cv],  g_xn_l[MT*Cv];
__device__ bf16 g_xm_h[MT*Cv],  g_xm_l[MT*Cv];
__device__ bf16 g_y_h [MT*Cv],  g_y_l [MT*Cv];
__device__ bf16 g_q_h [MT*1024],g_q_l [MT*1024];   // (b,t,h,d)
__device__ bf16 g_k_h [MT*256], g_k_l [MT*256];    // (b,t,kv,d)
__device__ bf16 g_v_h [MT*256], g_v_l [MT*256];    // (b,kv,d,t)
__device__ bf16 g_hf_h[(size_t)MT*FFH], g_hf_l[(size_t)MT*FFH]; // (b,f,t) post-relu2
__device__ bf16 g_hs_h[(size_t)MT*FFH], g_hs_l[(size_t)MT*FFH]; // (b,t,f) post-conv
__device__ bf16 g_wqkv_h[1536*1024], g_wqkv_l[1536*1024];
__device__ bf16 g_wo_h[1024*1024],  g_wo_l[1024*1024];
__device__ bf16 g_fin_h[FFH*1024],  g_fin_l[FFH*1024];
__device__ bf16 g_fout_h[1024*FFH], g_fout_l[1024*FFH];
__device__ bf16 g_fgt_h[1024*1024], g_fgt_l[1024*1024];

// =================== helpers ===================
__device__ __forceinline__ uint32_t smem_u32(const void* p){
    uint32_t a;
    asm("{ .reg .u64 t; cvta.to.shared.u64 t, %1; cvt.u32.u64 %0, t; }" : "=r"(a) : "l"(p));
    return a;
}
__device__ __forceinline__ void mma16816(float* c, const uint32_t* a, uint32_t b0, uint32_t b1){
    asm volatile("mma.sync.aligned.m16n8k16.row.col.f32.bf16.bf16.f32 "
        "{%0,%1,%2,%3}, {%4,%5,%6,%7}, {%8,%9}, {%0,%1,%2,%3};"
        : "+f"(c[0]), "+f"(c[1]), "+f"(c[2]), "+f"(c[3])
        : "r"(a[0]), "r"(a[1]), "r"(a[2]), "r"(a[3]), "r"(b0), "r"(b1));
}
__device__ __forceinline__ void ldsm4(uint32_t* r, uint32_t addr){
    asm volatile("ldmatrix.sync.aligned.m8n8.x4.shared.b16 {%0,%1,%2,%3}, [%4];"
        : "=r"(r[0]), "=r"(r[1]), "=r"(r[2]), "=r"(r[3]) : "r"(addr));
}
__device__ __forceinline__ void cpa16(uint32_t saddr, const void* g){
    asm volatile("cp.async.cg.shared.global [%0], [%1], 16;" :: "r"(saddr), "l"(g));
}
__device__ __forceinline__ void cpa4z(uint32_t saddr, const void* g, int srcsz){
    asm volatile("cp.async.ca.shared.global [%0], [%1], 4, %2;" :: "r"(saddr), "l"(g), "r"(srcsz));
}
#define CPA_COMMIT() asm volatile("cp.async.commit_group;" ::: "memory")
#define CPA_WAIT(n)  asm volatile("cp.async.wait_group %0;" :: "n"(n) : "memory")

// 64B-row swizzle (32 bf16 per row)
__device__ __forceinline__ uint32_t sw_off(int row, int k){
    int chunk = (k >> 3) ^ ((row >> 1) & 3);
    return (uint32_t)(row*64 + chunk*16 + (k & 7)*2);
}
// 128B-row swizzle (64 bf16 per row)
__device__ __forceinline__ uint32_t sw128(int row, int k){
    return (uint32_t)(row*128 + ((((k>>3) ^ (row & 7)) << 4) | ((k & 7) << 1)));
}
__device__ __forceinline__ void split1(float v, bf16& h, bf16& l){
    h = __float2bfloat16(v);
    l = __float2bfloat16(v - __bfloat162float(h));
}
__device__ __forceinline__ uint32_t pack2(bf16 a, bf16 b){
    return ((uint32_t)__bfloat16_as_ushort(b) << 16) | __bfloat16_as_ushort(a);
}

// ---------------- weight split (x4 ILP) ----------------
__global__ void split_kernel(const float* __restrict__ src, bf16* __restrict__ hi,
                             bf16* __restrict__ lo, int n4){
    int i0 = blockIdx.x*1024 + threadIdx.x;
    #pragma unroll
    for (int j = 0; j < 4; j++){
        int i = i0 + (j << 8);
        if (i < n4){
            float4 v = ((const float4*)src)[i];
            bf16 h0,h1,h2,h3,l0,l1,l2,l3;
            split1(v.x,h0,l0); split1(v.y,h1,l1); split1(v.z,h2,l2); split1(v.w,h3,l3);
            ((uint2*)hi)[i] = make_uint2(pack2(h0,h1), pack2(h2,h3));
            ((uint2*)lo)[i] = make_uint2(pack2(l0,l1), pack2(l2,l3));
        }
    }
}

// ---------------- rmsnorm (+ split output) ----------------
template<int WF32>
__global__ void rms_kernel(const float* __restrict__ x, float* __restrict__ o32,
                           bf16* __restrict__ ohi, bf16* __restrict__ olo){
    int row = blockIdx.x;
    const float* xr = x + (size_t)row*Cv;
    float ss = 0.f;
    float v[4];
    #pragma unroll
    for (int j=0;j<4;j++){ v[j] = xr[threadIdx.x + (j<<8)]; ss += v[j]*v[j]; }
    __shared__ float red[8];
    for (int off=16; off>0; off>>=1) ss += __shfl_xor_sync(0xffffffffu, ss, off);
    if ((threadIdx.x & 31) == 0) red[threadIdx.x>>5] = ss;
    __syncthreads();
    if (threadIdx.x < 8){
        float t = red[threadIdx.x];
        for (int off=4; off>0; off>>=1) t += __shfl_xor_sync(0x000000ffu, t, off);
        if (threadIdx.x == 0) red[0] = t;
    }
    __syncthreads();
    float r = rsqrtf(red[0]*(1.0f/Cv) + 1e-6f);
    #pragma unroll
    for (int j=0;j<4;j++){
        int i = threadIdx.x + (j<<8);
        float vv = v[j]*r;
        if (WF32) o32[(size_t)row*Cv + i] = vv;
        bf16 h,l; split1(vv,h,l);
        ohi[(size_t)row*Cv + i] = h;
        olo[(size_t)row*Cv + i] = l;
    }
}

// ---------------- fused x1 + rmsnorm split ----------------
__global__ void x1rms_kernel(const float* __restrict__ x, const float* __restrict__ attn,
                             const float* __restrict__ ca, float* __restrict__ x1,
                             bf16* __restrict__ ohi, bf16* __restrict__ olo){
    int row = blockIdx.x;
    size_t base = (size_t)row*Cv;
    float v[4]; float ss = 0.f;
    #pragma unroll
    for (int j=0;j<4;j++){
        int i = threadIdx.x + (j<<8);
        float vv = x[base+i] + attn[base+i]*(1.f + 0.1f*tanhf(ca[base+i]));
        v[j] = vv; ss += vv*vv;
    }
    __shared__ float red[8];
    for (int off=16; off>0; off>>=1) ss += __shfl_xor_sync(0xffffffffu, ss, off);
    if ((threadIdx.x & 31) == 0) red[threadIdx.x>>5] = ss;
    __syncthreads();
    if (threadIdx.x < 8){
        float t = red[threadIdx.x];
        for (int off=4; off>0; off>>=1) t += __shfl_xor_sync(0x000000ffu, t, off);
        if (threadIdx.x == 0) red[0] = t;
    }
    __syncthreads();
    float r = rsqrtf(red[0]*(1.0f/Cv) + 1e-6f);
    #pragma unroll
    for (int j=0;j<4;j++){
        int i = threadIdx.x + (j<<8);
        x1[base+i] = v[j];
        bf16 h,l; split1(v[j]*r,h,l);
        ohi[base+i] = h;
        olo[base+i] = l;
    }
}

// =================== bf16 split GEMM: tile 128x256, 3-stage cp.async ===================
// stage: Ahi 0 (8K), Alo 8K, Bhi 16K (16K), Blo 32K  => 48KB
#define GSTG 49152
#define GEMM_SMEM (3*GSTG)
// EPI 0: fp32 row-major. EPI 1: relu^2 -> split bf16 (B,N,T).
template<int EPI>
__global__ void __launch_bounds__(512,1)
gemm_bf16(const bf16* __restrict__ Ahi, const bf16* __restrict__ Alo,
          const bf16* __restrict__ Bhi, const bf16* __restrict__ Blo,
          float* __restrict__ Cg, bf16* __restrict__ Chi, bf16* __restrict__ Clo,
          int N, int K){
    extern __shared__ char smem[];
    const int tid = threadIdx.x, lane = tid & 31, wid = tid >> 5;
    const int warpM = wid & 3, warpN = wid >> 2;
    const int m0 = blockIdx.y << 7, n0 = blockIdx.x << 8;
    const int b = m0 >> 10, tb = m0 & 1023;
    uint32_t sb = smem_u32(smem);

    const int r = tid >> 2, kc = tid & 3;
    const bf16* aH  = Ahi + (size_t)(m0+r)*K + (kc<<3);
    const bf16* aL  = Alo + (size_t)(m0+r)*K + (kc<<3);
    const bf16* bH0 = Bhi + (size_t)(n0+r)*K + (kc<<3);
    const bf16* bH1 = Bhi + (size_t)(n0+r+128)*K + (kc<<3);
    const bf16* bL0 = Blo + (size_t)(n0+r)*K + (kc<<3);
    const bf16* bL1 = Blo + (size_t)(n0+r+128)*K + (kc<<3);
    const uint32_t dA  = sw_off(r, kc<<3);
    const uint32_t dB0 = sw_off(r, kc<<3);
    const uint32_t dB1 = sw_off(r+128, kc<<3);

    auto ISSUE = [&](int c, int s){
        int k0 = c << 5;
        uint32_t st = sb + s*GSTG;
        cpa16(st + dA,          aH + k0);
        cpa16(st + 8192 + dA,   aL + k0);
        cpa16(st + 16384 + dB0, bH0 + k0);
        cpa16(st + 16384 + dB1, bH1 + k0);
        cpa16(st + 32768 + dB0, bL0 + k0);
        cpa16(st + 32768 + dB1, bL1 + k0);
        CPA_COMMIT();
    };

    float acc[2][8][4];
    #pragma unroll
    for (int i=0;i<2;i++)
        #pragma unroll
        for (int j=0;j<8;j++)
            #pragma unroll
            for (int q=0;q<4;q++) acc[i][j][q]=0.f;

    const int NC = K >> 5;
    ISSUE(0,0);
    ISSUE(1,1);
    const int lr = lane & 15, lc = (lane < 16) ? 0 : 8;
    for (int c = 0; c < NC; c++){
        if (c == NC-1) { CPA_WAIT(0); } else { CPA_WAIT(1); }
        __syncthreads();
        if (c + 2 < NC) ISSUE(c+2, (c+2)%3);
        uint32_t sA = sb + (c%3)*GSTG;
        #pragma unroll
        for (int kk = 0; kk < 32; kk += 16){
            uint32_t ah[2][4], al[2][4];
            #pragma unroll
            for (int mt=0; mt<2; mt++){
                uint32_t off = sw_off(warpM*32 + mt*16 + lr, kk + lc);
                ldsm4(ah[mt], sA + off);
                ldsm4(al[mt], sA + 8192 + off);
            }
            #pragma unroll
            for (int nb=0; nb<4; nb++){
                uint32_t off = sw_off(warpN*64 + nb*16 + lr, kk + lc);
                uint32_t bh[4], bl[4];
                ldsm4(bh, sA + 16384 + off);
                ldsm4(bl, sA + 32768 + off);
                #pragma unroll
                for (int mt=0; mt<2; mt++){
                    mma16816(acc[mt][nb*2+0], ah[mt], bh[0], bh[2]);
                    mma16816(acc[mt][nb*2+0], ah[mt], bl[0], bl[2]);
                    mma16816(acc[mt][nb*2+0], al[mt], bh[0], bh[2]);
                    mma16816(acc[mt][nb*2+1], ah[mt], bh[1], bh[3]);
                    mma16816(acc[mt][nb*2+1], ah[mt], bl[1], bl[3]);
                    mma16816(acc[mt][nb*2+1], al[mt], bh[1], bh[3]);
                }
            }
        }
    }

    const int g = lane >> 2, t2 = (lane & 3) << 1;
    if (EPI == 0){
        #pragma unroll
        for (int mt=0; mt<2; mt++){
            int m = m0 + warpM*32 + mt*16 + g;
            #pragma unroll
            for (int ni=0; ni<8; ni++){
                int n = n0 + warpN*64 + ni*8 + t2;
                *(float2*)(Cg + (size_t)m*N + n) = make_float2(acc[mt][ni][0], acc[mt][ni][1]);
                *(float2*)(Cg + (size_t)(m+8)*N + n) = make_float2(acc[mt][ni][2], acc[mt][ni][3]);
            }
        }
    } else {
        float* ep = (float*)smem;   // 64 x 136
        #pragma unroll
        for (int slab=0; slab<4; slab++){
            __syncthreads();
            if (warpN == slab){
                #pragma unroll
                for (int mt=0; mt<2; mt++){
                    int mloc = warpM*32 + mt*16 + g;
                    #pragma unroll
                    for (int ni=0; ni<8; ni++){
                        int nL = ni*8 + t2;
                        ep[nL*136 + mloc]         = acc[mt][ni][0];
                        ep[(nL+1)*136 + mloc]     = acc[mt][ni][1];
                        ep[nL*136 + mloc + 8]     = acc[mt][ni][2];
                        ep[(nL+1)*136 + mloc + 8] = acc[mt][ni][3];
                    }
                }
            }
            __syncthreads();
            #pragma unroll
            for (int i=0;i<4;i++){
                int idx = tid + (i << 9);   // 2048 groups of 4
                int nr = idx >> 5, t4 = (idx & 31) << 2;
                bf16 h0,l0,h1,l1,h2,l2,h3,l3;
                float a0 = fmaxf(ep[nr*136 + t4 + 0], 0.f);
                float a1 = fmaxf(ep[nr*136 + t4 + 1], 0.f);
                float a2 = fmaxf(ep[nr*136 + t4 + 2], 0.f);
                float a3 = fmaxf(ep[nr*136 + t4 + 3], 0.f);
                split1(a0*a0,h0,l0); split1(a1*a1,h1,l1);
                split1(a2*a2,h2,l2); split1(a3*a3,h3,l3);
                int n = n0 + slab*64 + nr;
                size_t o = ((size_t)b*N + n)*1024 + tb + t4;
                *(uint2*)(Chi + o) = make_uint2(pack2(h0,h1), pack2(h2,h3));
                *(uint2*)(Clo + o) = make_uint2(pack2(l0,l1), pack2(l2,l3));
            }
        }
    }
}

// ---------------- small-N (=32) GEMM ----------------
template<int EPI>
__global__ void __launch_bounds__(256)
gemm32_kernel(const float* __restrict__ A, const float* __restrict__ W, float* __restrict__ Cg){
    __shared__ float xs[8*1024];
    int row0 = blockIdx.x << 3;
    #pragma unroll
    for (int i = 0; i < 8; i++){
        int f4 = threadIdx.x + (i << 8);
        ((float4*)xs)[f4] = ((const float4*)(A + ((size_t)row0 << 10)))[f4];
    }
    __syncthreads();
    int w = threadIdx.x >> 5, n = threadIdx.x & 31;
    const float4* Wr = (const float4*)(W + (size_t)n*1024);
    const float4* xr = (const float4*)(xs + (w << 10));
    float acc = 0.f;
    #pragma unroll 4
    for (int k = 0; k < 256; k++){
        float4 a = xr[k], b = Wr[k];
        acc += a.x*b.x + a.y*b.y + a.z*b.z + a.w*b.w;
    }
    if (EPI == 2) acc = 0.5f*acc*(1.f + erff(acc*0.70710678118f));
    Cg[((size_t)(row0 + w) << 5) + n] = acc;
}

// ---------------- FFMA GEMM (ca_po, K=32) ----------------
__global__ void __launch_bounds__(256,2)
gemm_k32(const float* __restrict__ A, const float* __restrict__ W,
         float* __restrict__ Cg, int N){
    __shared__ float As[32*132];
    __shared__ float Ws[32*132];
    const int tx = threadIdx.x & 15, ty = threadIdx.x >> 4;
    const int m0 = blockIdx.y << 7, n0 = blockIdx.x << 7;
    float acc[8][8];
    #pragma unroll
    for (int i=0;i<8;i++)
        #pragma unroll
        for (int j=0;j<8;j++) acc[i][j]=0.f;
    const int r = threadIdx.x >> 1;
    const int c4 = (threadIdx.x & 1) << 4;
    #pragma unroll
    for (int q=0;q<4;q++){
        float4 a0 = *(const float4*)(A + (size_t)(m0+r)*32 + c4 + q*4);
        As[(c4+q*4+0)*132 + r] = a0.x; As[(c4+q*4+1)*132 + r] = a0.y;
        As[(c4+q*4+2)*132 + r] = a0.z; As[(c4+q*4+3)*132 + r] = a0.w;
        float4 w0 = *(const float4*)(W + (size_t)(n0+r)*32 + c4 + q*4);
        Ws[(c4+q*4+0)*132 + r] = w0.x; Ws[(c4+q*4+1)*132 + r] = w0.y;
        Ws[(c4+q*4+2)*132 + r] = w0.z; Ws[(c4+q*4+3)*132 + r] = w0.w;
    }
    __syncthreads();
    #pragma unroll
    for (int kk=0; kk<32; kk++){
        float av[8], bv[8];
        *(float4*)&av[0] = *(const float4*)(As + kk*132 + (ty<<3));
        *(float4*)&av[4] = *(const float4*)(As + kk*132 + (ty<<3) + 4);
        *(float4*)&bv[0] = *(const float4*)(Ws + kk*132 + (tx<<3));
        *(float4*)&bv[4] = *(const float4*)(Ws + kk*132 + (tx<<3) + 4);
        #pragma unroll
        for (int i=0;i<8;i++)
            #pragma unroll
            for (int j=0;j<8;j++) acc[i][j] += av[i]*bv[j];
    }
    #pragma unroll
    for (int i=0;i<8;i++){
        int mg = m0 + (ty<<3) + i;
        #pragma unroll
        for (int j=0;j<8;j++)
            Cg[(size_t)mg*N + n0 + (tx<<3) + j] = acc[i][j];
    }
}

// ---------------- VE gate + V update -> transposed split ----------------
__global__ void vgate_kernel(const float* __restrict__ xn, const float* __restrict__ ve,
                             const float* __restrict__ wg, const float* __restrict__ qkv,
                             bf16* __restrict__ vhi, bf16* __restrict__ vlo){
    int row = blockIdx.x;
    __shared__ float gs[4];
    if (threadIdx.x < 4){
        float s = 0.f;
        #pragma unroll
        for (int c=0;c<12;c++) s += xn[(size_t)row*Cv + c]*wg[threadIdx.x*12 + c];
        gs[threadIdx.x] = 3.f/(1.f + expf(-s));
    }
    __syncthreads();
    int i = threadIdx.x;
    int kv = i >> 6, d = i & 63;
    float vv = qkv[(size_t)row*1536 + 1280 + i] + gs[kv]*ve[(size_t)row*256 + i];
    bf16 h,l; split1(vv,h,l);
    size_t o = ((size_t)((row>>10)*4 + kv)*64 + d)*1024 + (row & 1023);
    vhi[o] = h; vlo[o] = l;
}

// ---------------- rope + per-head rmsnorm*1.2 -> split ----------------
__global__ void ropeRms_kernel(const float* __restrict__ src, int srcStride, int srcOff,
                               bf16* __restrict__ dhi, bf16* __restrict__ dlo,
                               const float* __restrict__ cosb, const float* __restrict__ sinb,
                               int nheads){
    int row  = blockIdx.x;
    int t    = row & (Tv-1);
    int head = blockIdx.y*4 + (threadIdx.x >> 5);
    if (head >= nheads) return;
    int lane = threadIdx.x & 31;
    const float* p = src + (size_t)row*srcStride + srcOff + head*HD;
    float x1 = p[lane], x2 = p[lane+32];
    float cc = cosb[t*32 + lane], sn = sinb[t*32 + lane];
    float o1 =  x1*cc + x2*sn;
    float o2 = -x1*sn + x2*cc;
    float ss = o1*o1 + o2*o2;
    for (int off=16; off>0; off>>=1) ss += __shfl_xor_sync(0xffffffffu, ss, off);
    float rr = rsqrtf(ss*(1.0f/HD) + 1e-6f)*1.2f;
    o1 *= rr; o2 *= rr;
    size_t base = ((size_t)row*nheads + head)*HD;
    bf16 h,l;
    split1(o1,h,l); dhi[base+lane] = h;    dlo[base+lane] = l;
    split1(o2,h,l); dhi[base+lane+32] = h; dlo[base+lane+32] = l;
}

// =================== flash attention, mma + double-buffered cp.async ===================
#define SM_Q    0
#define SM_KV0  16384
#define SM_KV1  49152
#define SM_PP0  81920
#define SM_PP1  99608
#define SM_S    117296
#define SM_PHI  136240
#define SM_PLO  144432
#define SM_CORR 152624
#define SM_LINV 152880
#define ATTN_SMEM 153136

__global__ void __launch_bounds__(256)
attn_kernel(const bf16* __restrict__ qhi, const bf16* __restrict__ qlo,
            const bf16* __restrict__ khi, const bf16* __restrict__ klo,
            const bf16* __restrict__ vhi, const bf16* __restrict__ vlo,
            const float* __restrict__ prev, const float* __restrict__ rw,
            const float* __restrict__ alphap,
            bf16* __restrict__ yhi, bf16* __restrict__ ylo){
    extern __shared__ char smc[];
    uint32_t sb = smem_u32(smc);
    float* S      = (float*)(smc + SM_S);    // 64 x 74
    float* corr_s = (float*)(smc + SM_CORR);
    float* linv   = (float*)(smc + SM_LINV);

    const int tid = threadIdx.x, lane = tid & 31, wid = tid >> 5;
    const int warpM = wid & 3, warpN = wid >> 2;
    const int row = tid >> 2, quad = tid & 3, c0 = quad << 4;
    const int qt = blockIdx.x, h = blockIdx.y, b = blockIdx.z;
    const int q0 = qt << 6;
    const int kvh = h >> 2;
    const int lr = lane & 15, lc = (lane < 16) ? 0 : 8;
    const int g = lane >> 2, t2 = (lane & 3) << 1;

    const float alpha = alphap[0];
    float w9[9];
    #pragma unroll
    for (int i=0;i<9;i++) w9[i] = alpha*rw[h*9 + i];

    const float* prevB = prev + ((size_t)(b*NH + h))*Tv*Tv;

    auto issueKV = [&](int kt, int s){
        int k0 = kt << 6;
        uint32_t kvb = sb + SM_KV0 + s*32768;
        #pragma unroll
        for (int i=0;i<8;i++){
            int idx = tid + (i << 8);
            int arr = idx >> 9, rr = (idx >> 3) & 63, kc = idx & 7;
            const bf16* src;
            if (arr < 2) src = (arr ? klo : khi) + ((((size_t)(b*Tv + k0 + rr))*NKV + kvh) << 6) + (kc << 3);
            else         src = (arr == 2 ? vhi : vlo) + (((size_t)((b*NKV + kvh)*64 + rr)) << 10) + k0 + (kc << 3);
            cpa16(kvb + arr*8192 + sw128(rr, kc << 3), src);
        }
    };
    auto issuePP = [&](int kt, int s){
        int k0 = kt << 6;
        uint32_t ppb = sb + SM_PP0 + s*17688;
        for (int idx = tid; idx < 66*66; idx += 256){
            int i = idx/66, j = idx - i*66;
            int rr = q0 - 1 + i, cg = k0 - 1 + j;
            int ok = (rr >= 0 && rr < Tv && cg >= 0 && cg < Tv) ? 4 : 0;
            int rrc = rr < 0 ? 0 : (rr > 1023 ? 1023 : rr);
            int cgc = cg < 0 ? 0 : (cg > 1023 ? 1023 : cg);
            cpa4z(ppb + (uint32_t)(i*67 + j)*4, prevB + (size_t)rrc*Tv + cgc, ok);
        }
    };

    // prologue: Q group, then tile-0 group
    {
        #pragma unroll
        for (int i=0;i<4;i++){
            int idx = tid + (i << 8);
            int arr = idx >> 9, rr = (idx >> 3) & 63, kc = idx & 7;
            const bf16* src = (arr ? qlo : qhi) + ((((size_t)(b*Tv + q0 + rr))*NH + h) << 6) + (kc << 3);
            cpa16(sb + SM_Q + arr*8192 + sw128(rr, kc << 3), src);
        }
        CPA_COMMIT();
        issueKV(0,0); issuePP(0,0);
        CPA_COMMIT();
    }

    float o[4][4];
    #pragma unroll
    for (int i=0;i<4;i++)
        #pragma unroll
        for (int j=0;j<4;j++) o[i][j]=0.f;
    float m = -1e30f, l = 0.f;

    for (int kt = 0; kt <= qt; kt++){
        int s = kt & 1;
        CPA_WAIT(0);
        __syncthreads();
        if (kt < qt){ issueKV(kt+1, s^1); issuePP(kt+1, s^1); CPA_COMMIT(); }
        uint32_t kvb = sb + SM_KV0 + s*32768;
        float* PP = (float*)(smc + SM_PP0 + s*17688);

        // ---- QK^T mma ----
        float c[4][4];
        #pragma unroll
        for (int i=0;i<4;i++)
            #pragma unroll
            for (int j=0;j<4;j++) c[i][j]=0.f;
        #pragma unroll
        for (int k16 = 0; k16 < 4; k16++){
            uint32_t qh_[4], ql_[4];
            uint32_t offq = sw128(warpM*16 + lr, k16*16 + lc);
            ldsm4(qh_, sb + SM_Q + offq);
            ldsm4(ql_, sb + SM_Q + 8192 + offq);
            #pragma unroll
            for (int nb=0; nb<2; nb++){
                uint32_t offk = sw128(warpN*32 + nb*16 + lr, k16*16 + lc);
                uint32_t kh_[4], kl_[4];
                ldsm4(kh_, kvb + offk);
                ldsm4(kl_, kvb + 8192 + offk);
                mma16816(c[nb*2+0], qh_, kh_[0], kh_[2]);
                mma16816(c[nb*2+0], qh_, kl_[0], kl_[2]);
                mma16816(c[nb*2+0], ql_, kh_[0], kh_[2]);
                mma16816(c[nb*2+1], qh_, kh_[1], kh_[3]);
                mma16816(c[nb*2+1], qh_, kl_[1], kl_[3]);
                mma16816(c[nb*2+1], ql_, kh_[1], kh_[3]);
            }
        }
        #pragma unroll
        for (int ni=0; ni<4; ni++){
            int col = warpN*32 + ni*8 + t2;
            int r0 = warpM*16 + g;
            *(float2*)(S + r0*74 + col)     = make_float2(c[ni][0], c[ni][1]);
            *(float2*)(S + (r0+8)*74 + col) = make_float2(c[ni][2], c[ni][3]);
        }
        __syncthreads();

        // ---- scalar conv + mask + online softmax + split-P ----
        float sr[16];
        #pragma unroll
        for (int j=0;j<16;j++){
            int col = c0 + j;
            const float* p0 = PP + (row+0)*67 + col;
            const float* p1 = PP + (row+1)*67 + col;
            const float* p2 = PP + (row+2)*67 + col;
            float cv = w9[0]*p0[0] + w9[1]*p0[1] + w9[2]*p0[2]
                     + w9[3]*p1[0] + w9[4]*p1[1] + w9[5]*p1[2]
                     + w9[6]*p2[0] + w9[7]*p2[1] + w9[8]*p2[2];
            sr[j] = S[row*74 + col]*0.125f + cv;
            if (kt == qt && col > row) sr[j] = -1e30f;
        }
        float mt = sr[0];
        #pragma unroll
        for (int j=1;j<16;j++) mt = fmaxf(mt, sr[j]);
        for (int off=1; off<4; off<<=1) mt = fmaxf(mt, __shfl_xor_sync(0xffffffffu, mt, off));
        float mnew = fmaxf(m, mt);
        float corrv = __expf(m - mnew);
        float ls = 0.f;
        #pragma unroll
        for (int j=0;j<16;j++){ sr[j] = __expf(sr[j] - mnew); ls += sr[j]; }
        for (int off=1; off<4; off<<=1) ls += __shfl_xor_sync(0xffffffffu, ls, off);
        l = l*corrv + ls;
        m = mnew;
        if (quad == 0) corr_s[row] = corrv;
        #pragma unroll
        for (int j=0;j<16;j++){
            int col = c0 + j;
            bf16 ph, pl; split1(sr[j], ph, pl);
            uint32_t off = sw128(row, col);
            *(bf16*)(smc + SM_PHI + off) = ph;
            *(bf16*)(smc + SM_PLO + off) = pl;
        }
        __syncthreads();

        // ---- PV mma ----
        float cr0 = corr_s[warpM*16 + g], cr1 = corr_s[warpM*16 + g + 8];
        #pragma unroll
        for (int ni=0; ni<4; ni++){
            o[ni][0] *= cr0; o[ni][1] *= cr0;
            o[ni][2] *= cr1; o[ni][3] *= cr1;
        }
        #pragma unroll
        for (int k16 = 0; k16 < 4; k16++){
            uint32_t ph_[4], pl_[4];
            uint32_t offp = sw128(warpM*16 + lr, k16*16 + lc);
            ldsm4(ph_, sb + SM_PHI + offp);
            ldsm4(pl_, sb + SM_PLO + offp);
            #pragma unroll
            for (int nb=0; nb<2; nb++){
                uint32_t offv = sw128(warpN*32 + nb*16 + lr, k16*16 + lc);
                uint32_t vh_[4], vl_[4];
                ldsm4(vh_, kvb + 16384 + offv);
                ldsm4(vl_, kvb + 24576 + offv);
                mma16816(o[nb*2+0], ph_, vh_[0], vh_[2]);
                mma16816(o[nb*2+0], ph_, vl_[0], vl_[2]);
                mma16816(o[nb*2+0], pl_, vh_[0], vh_[2]);
                mma16816(o[nb*2+1], ph_, vh_[1], vh_[3]);
                mma16816(o[nb*2+1], ph_, vl_[1], vl_[3]);
                mma16816(o[nb*2+1], pl_, vh_[1], vh_[3]);
            }
        }
    }

    if (quad == 0) linv[row] = 1.f/l;
    __syncthreads();
    float i0 = linv[warpM*16 + g], i1 = linv[warpM*16 + g + 8];
    #pragma unroll
    for (int ni=0; ni<4; ni++){
        int col = warpN*32 + ni*8 + t2;
        float v00 = o[ni][0]*i0, v01 = o[ni][1]*i0;
        float v10 = o[ni][2]*i1, v11 = o[ni][3]*i1;
        bf16 h0,l0,h1,l1;
        size_t base0 = ((((size_t)(b*Tv + q0 + warpM*16 + g))*NH + h) << 6) + col;
        size_t base1 = ((((size_t)(b*Tv + q0 + warpM*16 + g + 8))*NH + h) << 6) + col;
        split1(v00,h0,l0); split1(v01,h1,l1);
        *(uint32_t*)(yhi + base0) = pack2(h0,h1);
        *(uint32_t*)(ylo + base0) = pack2(l0,l1);
        split1(v10,h0,l0); split1(v11,h1,l1);
        *(uint32_t*)(yhi + base1) = pack2(h0,h1);
        *(uint32_t*)(ylo + base1) = pack2(l0,l1);
    }
}

// ---------------- CA conv + gelu ----------------
__global__ void caconv_kernel(const float* __restrict__ hin, const float* __restrict__ cw,
                              float* __restrict__ hout){
    int ch = blockIdx.x, b = blockIdx.y;
    __shared__ float s[Tv+2];
    for (int t = threadIdx.x; t < Tv; t += 256) s[1+t] = hin[((size_t)b*Tv + t)*32 + ch];
    if (threadIdx.x == 0){ s[0] = 0.f; s[Tv+1] = 0.f; }
    __syncthreads();
    float w0 = cw[ch*3], w1 = cw[ch*3+1], w2 = cw[ch*3+2];
    for (int t = threadIdx.x; t < Tv; t += 256){
        float vv = s[1+t] + 0.1f*(w0*s[t] + w1*s[1+t] + w2*s[2+t]);
        hout[((size_t)b*Tv + t)*32 + ch] = 0.5f*vv*(1.f + erff(vv*0.70710678118f));
    }
}

// ---------------- FFN conv x4: bf16 (B,F,T) in -> split (B,T,F) out ----------------
#define FFNC_SMEM (2*16*1026*4)
__global__ void __launch_bounds__(256)
ffnconvT_kernel(const bf16* __restrict__ hfh, const bf16* __restrict__ hfl,
                const float* __restrict__ cw,
                bf16* __restrict__ hhi, bf16* __restrict__ hlo){
    extern __shared__ float fs[];
    float (*buf0)[1026] = (float(*)[1026])fs;
    float (*buf1)[1026] = (float(*)[1026])(fs + 16*1026);
    int f0 = blockIdx.x << 4, b = blockIdx.y;
    for (int idx4 = threadIdx.x; idx4 < 16*256; idx4 += 256){
        int cch = idx4 >> 8, t4 = (idx4 & 255) << 2;
        size_t o = ((size_t)(b*FFH + f0 + cch))*Tv + t4;
        uint2 uh = *(const uint2*)(hfh + o);
        uint2 ul = *(const uint2*)(hfl + o);
        const bf16* ph = (const bf16*)&uh;
        const bf16* pl = (const bf16*)&ul;
        #pragma unroll
        for (int e=0;e<4;e++)
            buf0[cch][1+t4+e] = __bfloat162float(ph[e]) + __bfloat162float(pl[e]);
    }
    if (threadIdx.x < 16){
        buf0[threadIdx.x][0] = 0.f; buf0[threadIdx.x][1025] = 0.f;
        buf1[threadIdx.x][0] = 0.f; buf1[threadIdx.x][1025] = 0.f;
    }
    int cch = threadIdx.x >> 4, j = threadIdx.x & 15;
    float w0 = cw[(f0+cch)*3], w1 = cw[(f0+cch)*3+1], w2 = cw[(f0+cch)*3+2];
    float (*cur)[1026] = buf0; float (*nxt)[1026] = buf1;
    #pragma unroll
    for (int it=0; it<4; it++){
        __syncthreads();
        #pragma unroll 4
        for (int t = j*64; t < j*64 + 64; t++)
            nxt[cch][1+t] = cur[cch][1+t] + 0.1f*(w0*cur[cch][t] + w1*cur[cch][1+t] + w2*cur[cch][2+t]);
        float (*tmp)[1026] = cur; cur = nxt; nxt = tmp;
    }
    __syncthreads();
    for (int t = threadIdx.x; t < Tv; t += 256){
        uint32_t wh[8], wl[8];
        #pragma unroll
        for (int cc = 0; cc < 16; cc += 2){
            bf16 h0,l0,h1,l1;
            split1(cur[cc][1+t],   h0, l0);
            split1(cur[cc+1][1+t], h1, l1);
            wh[cc>>1] = pack2(h0,h1);
            wl[cc>>1] = pack2(l0,l1);
        }
        size_t o = ((size_t)(b*Tv + t))*FFH + f0;
        *(uint4*)(hhi + o)     = make_uint4(wh[0],wh[1],wh[2],wh[3]);
        *(uint4*)(hhi + o + 8) = make_uint4(wh[4],wh[5],wh[6],wh[7]);
        *(uint4*)(hlo + o)     = make_uint4(wl[0],wl[1],wl[2],wl[3]);
        *(uint4*)(hlo + o + 8) = make_uint4(wl[4],wl[5],wl[6],wl[7]);
    }
}

// ---------------- elementwise ----------------
__global__ void vit2_kernel(const float* __restrict__ h32, const float* __restrict__ w2,
                            float* __restrict__ out){
    int row  = blockIdx.x*8 + (threadIdx.x >> 5);
    int lane = threadIdx.x & 31;
    float vv = h32[(size_t)row*32 + lane]*w2[lane];
    for (int off=16; off>0; off>>=1) vv += __shfl_xor_sync(0xffffffffu, vv, off);
    if (lane == 0) out[row] = 1.f/(1.f + expf(-vv));
}
__global__ void vitsmooth_kernel(const float* __restrict__ vin, float* __restrict__ vout){
    int b = blockIdx.x;
    __shared__ float s[Tv+4];
    for (int t = threadIdx.x; t < Tv; t += 256) s[2+t] = vin[b*Tv + t];
    if (threadIdx.x < 2){ s[threadIdx.x] = 0.f; s[Tv+2+threadIdx.x] = 0.f; }
    __syncthreads();
    for (int t = threadIdx.x; t < Tv; t += 256){
        float vs = (s[t] + s[t+1] + s[t+2] + s[t+3] + s[t+4])*0.2f;
        float vv = 0.7f*s[2+t] + 0.3f*vs;
        vout[b*Tv + t] = (vv > 0.3f) ? vv : 0.1f*vv;
    }
}
__global__ void final_kernel(const float* __restrict__ x1, const float* __restrict__ mlp,
                             const float* __restrict__ gate, const float* __restrict__ ca,
                             const float* __restrict__ vitf, float* __restrict__ out, int n){
    for (int i = blockIdx.x*blockDim.x + threadIdx.x; i < n; i += gridDim.x*blockDim.x){
        int row = i >> 10;
        float gg = 1.f/(1.f + expf(-gate[i]));
        out[i] = x1[i] + mlp[i]*gg*(1.f + 0.1f*tanhf(ca[i]))*vitf[row];
    }
}

// ---------------- launch ----------------
extern "C" void kernel_launch(void* const* d_in, const int* in_sizes, int n_in,
                              void* d_out, int out_size){
    const float* x     = (const float*)d_in[0];
    const float* ve    = (const float*)d_in[1];
    const float* cosp  = (const float*)d_in[2];
    const float* sinp  = (const float*)d_in[3];
    const float* prev  = (const float*)d_in[4];
    const float* w_q   = (const float*)d_in[5];
    const float* w_k   = (const float*)d_in[6];
    const float* w_v   = (const float*)d_in[7];
    const float* w_o   = (const float*)d_in[8];
    const float* w_veg = (const float*)d_in[9];
    const float* rfw   = (const float*)d_in[10];
    const float* ralpha= (const float*)d_in[11];
    const float* ca_pi = (const float*)d_in[12];
    const float* ca_cw = (const float*)d_in[13];
    const float* ca_po = (const float*)d_in[14];
    const float* ffn_in= (const float*)d_in[15];
    const float* ffn_cw= (const float*)d_in[16];
    const float* ffn_outw=(const float*)d_in[17];
    const float* ffn_gt= (const float*)d_in[18];
    const float* vit_w1= (const float*)d_in[19];
    const float* vit_w2= (const float*)d_in[20];
    float* out = (float*)d_out;

    float *xn,*qkv,*attn,*ca,*cah,*cah2,*x1,*mlp,*gate,*vit32,*vitv,*vitf;
    bf16 *xnh,*xnl,*xmh,*xml,*yh,*yl,*qh,*ql,*kh,*kl,*vh,*vl,*hfh,*hfl,*hsh,*hsl;
    bf16 *wqkvh,*wqkvl,*woh,*wol,*finh,*finl,*fouth,*foutl,*fgth,*fgtl;
    cudaGetSymbolAddress((void**)&xn, g_xn);     cudaGetSymbolAddress((void**)&qkv, g_qkv);
    cudaGetSymbolAddress((void**)&attn, g_attn); cudaGetSymbolAddress((void**)&ca, g_ca);
    cudaGetSymbolAddress((void**)&cah, g_cah);   cudaGetSymbolAddress((void**)&cah2, g_cah2);
    cudaGetSymbolAddress((void**)&x1, g_x1);
    cudaGetSymbolAddress((void**)&mlp, g_mlp);   cudaGetSymbolAddress((void**)&gate, g_gate);
    cudaGetSymbolAddress((void**)&vit32, g_vit32); cudaGetSymbolAddress((void**)&vitv, g_vitv);
    cudaGetSymbolAddress((void**)&vitf, g_vitf);
    cudaGetSymbolAddress((void**)&xnh, g_xn_h);  cudaGetSymbolAddress((void**)&xnl, g_xn_l);
    cudaGetSymbolAddress((void**)&xmh, g_xm_h);  cudaGetSymbolAddress((void**)&xml, g_xm_l);
    cudaGetSymbolAddress((void**)&yh, g_y_h);    cudaGetSymbolAddress((void**)&yl, g_y_l);
    cudaGetSymbolAddress((void**)&qh, g_q_h);    cudaGetSymbolAddress((void**)&ql, g_q_l);
    cudaGetSymbolAddress((void**)&kh, g_k_h);    cudaGetSymbolAddress((void**)&kl, g_k_l);
    cudaGetSymbolAddress((void**)&vh, g_v_h);    cudaGetSymbolAddress((void**)&vl, g_v_l);
    cudaGetSymbolAddress((void**)&hfh, g_hf_h);  cudaGetSymbolAddress((void**)&hfl, g_hf_l);
    cudaGetSymbolAddress((void**)&hsh, g_hs_h);  cudaGetSymbolAddress((void**)&hsl, g_hs_l);
    cudaGetSymbolAddress((void**)&wqkvh, g_wqkv_h); cudaGetSymbolAddress((void**)&wqkvl, g_wqkv_l);
    cudaGetSymbolAddress((void**)&woh, g_wo_h);  cudaGetSymbolAddress((void**)&wol, g_wo_l);
    cudaGetSymbolAddress((void**)&finh, g_fin_h); cudaGetSymbolAddress((void**)&finl, g_fin_l);
    cudaGetSymbolAddress((void**)&fouth, g_fout_h); cudaGetSymbolAddress((void**)&foutl, g_fout_l);
    cudaGetSymbolAddress((void**)&fgth, g_fgt_h); cudaGetSymbolAddress((void**)&fgtl, g_fgt_l);

    cudaFuncSetAttribute(attn_kernel, cudaFuncAttributeMaxDynamicSharedMemorySize, ATTN_SMEM);
    cudaFuncSetAttribute(gemm_bf16<0>, cudaFuncAttributeMaxDynamicSharedMemorySize, GEMM_SMEM);
    cudaFuncSetAttribute(gemm_bf16<1>, cudaFuncAttributeMaxDynamicSharedMemorySize, GEMM_SMEM);
    cudaFuncSetAttribute(ffnconvT_kernel, cudaFuncAttributeMaxDynamicSharedMemorySize, FFNC_SMEM);

    // weight splits
    split_kernel<<<256,256>>>(w_q, wqkvh, wqkvl, 262144);
    split_kernel<<<64,256>>>(w_k, wqkvh + 1024*1024, wqkvl + 1024*1024, 65536);
    split_kernel<<<64,256>>>(w_v, wqkvh + 1280*1024, wqkvl + 1280*1024, 65536);
    split_kernel<<<256,256>>>(w_o, woh, wol, 262144);
    split_kernel<<<1024,256>>>(ffn_in, finh, finl, 1048576);
    split_kernel<<<1024,256>>>(ffn_outw, fouth, foutl, 1048576);
    split_kernel<<<256,256>>>(ffn_gt, fgth, fgtl, 262144);

    // xn = rmsnorm(x); fused QKV
    rms_kernel<1><<<MT,256>>>(x, xn, xnh, xnl);
    gemm_bf16<0><<<dim3(6,32),512,GEMM_SMEM>>>(xnh, xnl, wqkvh, wqkvl, qkv, 0, 0, 1536, 1024);
    vgate_kernel<<<MT,256>>>(xn, ve, w_veg, qkv, vh, vl);
    ropeRms_kernel<<<dim3(MT,4),128>>>(qkv, 1536, 0,    qh, ql, cosp, sinp, NH);
    ropeRms_kernel<<<dim3(MT,1),128>>>(qkv, 1536, 1024, kh, kl, cosp, sinp, NKV);

    // attention + w_o
    attn_kernel<<<dim3(16,NH,Bv),256,ATTN_SMEM>>>(qh, ql, kh, kl, vh, vl, prev, rfw, ralpha, yh, yl);
    gemm_bf16<0><<<dim3(4,32),512,GEMM_SMEM>>>(yh, yl, woh, wol, attn, 0, 0, 1024, 1024);

    // ca1 on x; fused x1 + rms split
    gemm32_kernel<0><<<512,256>>>(x, ca_pi, cah);
    caconv_kernel<<<dim3(32,Bv),256>>>(cah, ca_cw, cah2);
    gemm_k32<<<dim3(8,32),256>>>(cah2, ca_po, ca, 1024);
    x1rms_kernel<<<MT,256>>>(x, attn, ca, x1, xmh, xml);

    // FFN
    gemm_bf16<1><<<dim3(16,32),512,GEMM_SMEM>>>(xmh, xml, finh, finl, 0, hfh, hfl, FFH, 1024);
    ffnconvT_kernel<<<dim3(256,Bv),256,FFNC_SMEM>>>(hfh, hfl, ffn_cw, hsh, hsl);
    gemm_bf16<0><<<dim3(4,32),512,GEMM_SMEM>>>(hsh, hsl, fouth, foutl, mlp, 0, 0, 1024, 4096);
    gemm_bf16<0><<<dim3(4,32),512,GEMM_SMEM>>>(xmh, xml, fgth, fgtl, gate, 0, 0, 1024, 1024);

    // ca2 on x1
    gemm32_kernel<0><<<512,256>>>(x1, ca_pi, cah);
    caconv_kernel<<<dim3(32,Bv),256>>>(cah, ca_cw, cah2);
    gemm_k32<<<dim3(8,32),256>>>(cah2, ca_po, ca, 1024);

    // vit gate
    gemm32_kernel<2><<<512,256>>>(x1, vit_w1, vit32);
    vit2_kernel<<<512,256>>>(vit32, vit_w2, vitv);
    vitsmooth_kernel<<<Bv,256>>>(vitv, vitf);

    final_kernel<<<4096,256>>>(x1, mlp, gate, ca, vitf, out, MT*Cv);
}

// round 6
// speedup vs baseline: 2.5578x; 1.1926x over previous
#include <cuda_runtime.h>
#include <cuda_fp16.h>
#include <math.h>
#include <stdint.h>

#define Bv  4
#define Tv  1024
#define Cv  1024
#define NH  16
#define NKV 4
#define HD  64
#define FFH 4096
#define MT  (Bv*Tv)

typedef __half h16;

// ---------------- fp32 scratch ----------------
__device__ float g_xn  [MT*Cv];
__device__ float g_qkv [MT*1536];
__device__ float g_attn[MT*Cv];
__device__ float g_ca  [MT*Cv];
__device__ float g_cah [MT*32];
__device__ float g_cah2[MT*32];
__device__ float g_x1  [MT*Cv];
__device__ float g_mlp [MT*Cv];
__device__ float g_gate[MT*Cv];
__device__ float g_vit32[MT*32];
__device__ float g_vitv[MT];
__device__ float g_vitf[MT];

// ---------------- fp16 scratch ----------------
__device__ h16 g_xn_h[MT*Cv];                    // A single
__device__ h16 g_xm_h[MT*Cv];                    // A single
__device__ h16 g_y_h [MT*Cv];                    // A single
__device__ h16 g_q_h [MT*1024], g_q_l [MT*1024]; // (b,t,h,d) hi/lo
__device__ h16 g_k_h [MT*256],  g_k_l [MT*256];  // (b,t,kv,d) hi/lo
__device__ h16 g_v_h [MT*256],  g_v_l [MT*256];  // (b,kv,d,t) hi/lo
__device__ h16 g_hf  [(size_t)MT*FFH];           // (b,f,t) post-relu2, single
__device__ h16 g_hs  [(size_t)MT*FFH];           // (b,t,f) post-conv, single (A)
__device__ h16 g_wqkv_h[1536*1024], g_wqkv_l[1536*1024];
__device__ h16 g_wo_h[1024*1024],  g_wo_l[1024*1024];
__device__ h16 g_fin_h[FFH*1024],  g_fin_l[FFH*1024];
__device__ h16 g_fout_h[1024*FFH], g_fout_l[1024*FFH];
__device__ h16 g_fgt_h[1024*1024], g_fgt_l[1024*1024];

// =================== helpers ===================
__device__ __forceinline__ uint32_t smem_u32(const void* p){
    uint32_t a;
    asm("{ .reg .u64 t; cvta.to.shared.u64 t, %1; cvt.u32.u64 %0, t; }" : "=r"(a) : "l"(p));
    return a;
}
__device__ __forceinline__ void mma16816(float* c, const uint32_t* a, uint32_t b0, uint32_t b1){
    asm volatile("mma.sync.aligned.m16n8k16.row.col.f32.f16.f16.f32 "
        "{%0,%1,%2,%3}, {%4,%5,%6,%7}, {%8,%9}, {%0,%1,%2,%3};"
        : "+f"(c[0]), "+f"(c[1]), "+f"(c[2]), "+f"(c[3])
        : "r"(a[0]), "r"(a[1]), "r"(a[2]), "r"(a[3]), "r"(b0), "r"(b1));
}
__device__ __forceinline__ void ldsm4(uint32_t* r, uint32_t addr){
    asm volatile("ldmatrix.sync.aligned.m8n8.x4.shared.b16 {%0,%1,%2,%3}, [%4];"
        : "=r"(r[0]), "=r"(r[1]), "=r"(r[2]), "=r"(r[3]) : "r"(addr));
}
__device__ __forceinline__ void cpa16(uint32_t saddr, const void* g){
    asm volatile("cp.async.cg.shared.global [%0], [%1], 16;" :: "r"(saddr), "l"(g));
}
__device__ __forceinline__ void cpa4z(uint32_t saddr, const void* g, int srcsz){
    asm volatile("cp.async.ca.shared.global [%0], [%1], 4, %2;" :: "r"(saddr), "l"(g), "r"(srcsz));
}
#define CPA_COMMIT() asm volatile("cp.async.commit_group;" ::: "memory")
#define CPA_WAIT(n)  asm volatile("cp.async.wait_group %0;" :: "n"(n) : "memory")

__device__ __forceinline__ uint32_t sw_off(int row, int k){
    int chunk = (k >> 3) ^ ((row >> 1) & 3);
    return (uint32_t)(row*64 + chunk*16 + (k & 7)*2);
}
__device__ __forceinline__ uint32_t sw128(int row, int k){
    return (uint32_t)(row*128 + ((((k>>3) ^ (row & 7)) << 4) | ((k & 7) << 1)));
}
__device__ __forceinline__ void split1(float v, h16& h, h16& l){
    h = __float2half_rn(v);
    l = __float2half_rn(v - __half2float(h));
}
__device__ __forceinline__ uint32_t pack2(h16 a, h16 b){
    return ((uint32_t)__half_as_ushort(b) << 16) | __half_as_ushort(a);
}

// ---------------- weight split ----------------
__global__ void split_kernel(const float* __restrict__ src, h16* __restrict__ hi,
                             h16* __restrict__ lo, int n4){
    int i0 = blockIdx.x*1024 + threadIdx.x;
    #pragma unroll
    for (int j = 0; j < 4; j++){
        int i = i0 + (j << 8);
        if (i < n4){
            float4 v = ((const float4*)src)[i];
            h16 h0,h1,h2,h3,l0,l1,l2,l3;
            split1(v.x,h0,l0); split1(v.y,h1,l1); split1(v.z,h2,l2); split1(v.w,h3,l3);
            ((uint2*)hi)[i] = make_uint2(pack2(h0,h1), pack2(h2,h3));
            ((uint2*)lo)[i] = make_uint2(pack2(l0,l1), pack2(l2,l3));
        }
    }
}

// ---------------- rmsnorm (fp32 + single fp16) ----------------
template<int WF32>
__global__ void rms_kernel(const float* __restrict__ x, float* __restrict__ o32,
                           h16* __restrict__ ohi){
    int row = blockIdx.x;
    const float* xr = x + (size_t)row*Cv;
    float ss = 0.f;
    float v[4];
    #pragma unroll
    for (int j=0;j<4;j++){ v[j] = xr[threadIdx.x + (j<<8)]; ss += v[j]*v[j]; }
    __shared__ float red[8];
    for (int off=16; off>0; off>>=1) ss += __shfl_xor_sync(0xffffffffu, ss, off);
    if ((threadIdx.x & 31) == 0) red[threadIdx.x>>5] = ss;
    __syncthreads();
    if (threadIdx.x < 8){
        float t = red[threadIdx.x];
        for (int off=4; off>0; off>>=1) t += __shfl_xor_sync(0x000000ffu, t, off);
        if (threadIdx.x == 0) red[0] = t;
    }
    __syncthreads();
    float r = rsqrtf(red[0]*(1.0f/Cv) + 1e-6f);
    #pragma unroll
    for (int j=0;j<4;j++){
        int i = threadIdx.x + (j<<8);
        float vv = v[j]*r;
        if (WF32) o32[(size_t)row*Cv + i] = vv;
        ohi[(size_t)row*Cv + i] = __float2half_rn(vv);
    }
}

// ---------------- fused x1 + rmsnorm ----------------
__global__ void x1rms_kernel(const float* __restrict__ x, const float* __restrict__ attn,
                             const float* __restrict__ ca, float* __restrict__ x1,
                             h16* __restrict__ ohi){
    int row = blockIdx.x;
    size_t base = (size_t)row*Cv;
    float v[4]; float ss = 0.f;
    #pragma unroll
    for (int j=0;j<4;j++){
        int i = threadIdx.x + (j<<8);
        float vv = x[base+i] + attn[base+i]*(1.f + 0.1f*tanhf(ca[base+i]));
        v[j] = vv; ss += vv*vv;
    }
    __shared__ float red[8];
    for (int off=16; off>0; off>>=1) ss += __shfl_xor_sync(0xffffffffu, ss, off);
    if ((threadIdx.x & 31) == 0) red[threadIdx.x>>5] = ss;
    __syncthreads();
    if (threadIdx.x < 8){
        float t = red[threadIdx.x];
        for (int off=4; off>0; off>>=1) t += __shfl_xor_sync(0x000000ffu, t, off);
        if (threadIdx.x == 0) red[0] = t;
    }
    __syncthreads();
    float r = rsqrtf(red[0]*(1.0f/Cv) + 1e-6f);
    #pragma unroll
    for (int j=0;j<4;j++){
        int i = threadIdx.x + (j<<8);
        x1[base+i] = v[j];
        ohi[base+i] = __float2half_rn(v[j]*r);
    }
}

// =================== fp16 2-term GEMM: C = Ah*(Bh+Bl); tile 128x256 ===================
// stage: A 8K, Bh 16K (off 8192), Bl 16K (off 24576) => 40KB, 3 stages
#define GSTG 40960
#define GEMM_SMEM (3*GSTG)
template<int EPI>
__global__ void __launch_bounds__(512,1)
gemm_f16(const h16* __restrict__ Ah, const h16* __restrict__ Bh, const h16* __restrict__ Bl,
         float* __restrict__ Cg, h16* __restrict__ Chf, int N, int K){
    extern __shared__ char smem[];
    const int tid = threadIdx.x, lane = tid & 31, wid = tid >> 5;
    const int warpM = wid & 3, warpN = wid >> 2;
    const int m0 = blockIdx.y << 7, n0 = blockIdx.x << 8;
    const int b = m0 >> 10, tb = m0 & 1023;
    uint32_t sb = smem_u32(smem);

    const int r = tid >> 2, kc = tid & 3;
    const h16* aP  = Ah + (size_t)(m0+r)*K + (kc<<3);
    const h16* bH0 = Bh + (size_t)(n0+r)*K + (kc<<3);
    const h16* bH1 = Bh + (size_t)(n0+r+128)*K + (kc<<3);
    const h16* bL0 = Bl + (size_t)(n0+r)*K + (kc<<3);
    const h16* bL1 = Bl + (size_t)(n0+r+128)*K + (kc<<3);
    const uint32_t dA  = sw_off(r, kc<<3);
    const uint32_t dB1 = sw_off(r+128, kc<<3);

    auto ISSUE = [&](int c, int s){
        int k0 = c << 5;
        uint32_t st = sb + s*GSTG;
        cpa16(st + dA,          aP + k0);
        cpa16(st + 8192 + dA,   bH0 + k0);
        cpa16(st + 8192 + dB1,  bH1 + k0);
        cpa16(st + 24576 + dA,  bL0 + k0);
        cpa16(st + 24576 + dB1, bL1 + k0);
        CPA_COMMIT();
    };

    float acc[2][8][4];
    #pragma unroll
    for (int i=0;i<2;i++)
        #pragma unroll
        for (int j=0;j<8;j++)
            #pragma unroll
            for (int q=0;q<4;q++) acc[i][j][q]=0.f;

    const int NC = K >> 5;
    ISSUE(0,0);
    ISSUE(1,1);
    const int lr = lane & 15, lc = (lane < 16) ? 0 : 8;
    for (int c = 0; c < NC; c++){
        if (c == NC-1) { CPA_WAIT(0); } else { CPA_WAIT(1); }
        __syncthreads();
        if (c + 2 < NC) ISSUE(c+2, (c+2)%3);
        uint32_t sA = sb + (c%3)*GSTG;
        #pragma unroll
        for (int kk = 0; kk < 32; kk += 16){
            uint32_t ah[2][4];
            #pragma unroll
            for (int mt=0; mt<2; mt++)
                ldsm4(ah[mt], sA + sw_off(warpM*32 + mt*16 + lr, kk + lc));
            #pragma unroll
            for (int nb=0; nb<4; nb++){
                uint32_t off = sw_off(warpN*64 + nb*16 + lr, kk + lc);
                uint32_t bh[4], bl[4];
                ldsm4(bh, sA + 8192 + off);
                ldsm4(bl, sA + 24576 + off);
                #pragma unroll
                for (int mt=0; mt<2; mt++){
                    mma16816(acc[mt][nb*2+0], ah[mt], bh[0], bh[2]);
                    mma16816(acc[mt][nb*2+0], ah[mt], bl[0], bl[2]);
                    mma16816(acc[mt][nb*2+1], ah[mt], bh[1], bh[3]);
                    mma16816(acc[mt][nb*2+1], ah[mt], bl[1], bl[3]);
                }
            }
        }
    }

    const int g = lane >> 2, t2 = (lane & 3) << 1;
    if (EPI == 0){
        #pragma unroll
        for (int mt=0; mt<2; mt++){
            int m = m0 + warpM*32 + mt*16 + g;
            #pragma unroll
            for (int ni=0; ni<8; ni++){
                int n = n0 + warpN*64 + ni*8 + t2;
                *(float2*)(Cg + (size_t)m*N + n) = make_float2(acc[mt][ni][0], acc[mt][ni][1]);
                *(float2*)(Cg + (size_t)(m+8)*N + n) = make_float2(acc[mt][ni][2], acc[mt][ni][3]);
            }
        }
    } else {
        float* ep = (float*)smem;   // 64 x 136
        #pragma unroll
        for (int slab=0; slab<4; slab++){
            __syncthreads();
            if (warpN == slab){
                #pragma unroll
                for (int mt=0; mt<2; mt++){
                    int mloc = warpM*32 + mt*16 + g;
                    #pragma unroll
                    for (int ni=0; ni<8; ni++){
                        int nL = ni*8 + t2;
                        ep[nL*136 + mloc]         = acc[mt][ni][0];
                        ep[(nL+1)*136 + mloc]     = acc[mt][ni][1];
                        ep[nL*136 + mloc + 8]     = acc[mt][ni][2];
                        ep[(nL+1)*136 + mloc + 8] = acc[mt][ni][3];
                    }
                }
            }
            __syncthreads();
            #pragma unroll
            for (int i=0;i<4;i++){
                int idx = tid + (i << 9);
                int nr = idx >> 5, t4 = (idx & 31) << 2;
                float a0 = fmaxf(ep[nr*136 + t4 + 0], 0.f);
                float a1 = fmaxf(ep[nr*136 + t4 + 1], 0.f);
                float a2 = fmaxf(ep[nr*136 + t4 + 2], 0.f);
                float a3 = fmaxf(ep[nr*136 + t4 + 3], 0.f);
                int n = n0 + slab*64 + nr;
                size_t o = ((size_t)b*N + n)*1024 + tb + t4;
                *(uint2*)(Chf + o) = make_uint2(
                    pack2(__float2half_rn(a0*a0), __float2half_rn(a1*a1)),
                    pack2(__float2half_rn(a2*a2), __float2half_rn(a3*a3)));
            }
        }
    }
}

// ---------------- small-N (=32) GEMM ----------------
template<int EPI>
__global__ void __launch_bounds__(256)
gemm32_kernel(const float* __restrict__ A, const float* __restrict__ W, float* __restrict__ Cg){
    __shared__ float xs[8*1024];
    int row0 = blockIdx.x << 3;
    #pragma unroll
    for (int i = 0; i < 8; i++){
        int f4 = threadIdx.x + (i << 8);
        ((float4*)xs)[f4] = ((const float4*)(A + ((size_t)row0 << 10)))[f4];
    }
    __syncthreads();
    int w = threadIdx.x >> 5, n = threadIdx.x & 31;
    const float4* Wr = (const float4*)(W + (size_t)n*1024);
    const float4* xr = (const float4*)(xs + (w << 10));
    float acc = 0.f;
    #pragma unroll 4
    for (int k = 0; k < 256; k++){
        float4 a = xr[k], b = Wr[k];
        acc += a.x*b.x + a.y*b.y + a.z*b.z + a.w*b.w;
    }
    if (EPI == 2) acc = 0.5f*acc*(1.f + erff(acc*0.70710678118f));
    Cg[((size_t)(row0 + w) << 5) + n] = acc;
}

// ---------------- FFMA GEMM (ca_po, K=32) ----------------
__global__ void __launch_bounds__(256,2)
gemm_k32(const float* __restrict__ A, const float* __restrict__ W,
         float* __restrict__ Cg, int N){
    __shared__ float As[32*132];
    __shared__ float Ws[32*132];
    const int tx = threadIdx.x & 15, ty = threadIdx.x >> 4;
    const int m0 = blockIdx.y << 7, n0 = blockIdx.x << 7;
    float acc[8][8];
    #pragma unroll
    for (int i=0;i<8;i++)
        #pragma unroll
        for (int j=0;j<8;j++) acc[i][j]=0.f;
    const int r = threadIdx.x >> 1;
    const int c4 = (threadIdx.x & 1) << 4;
    #pragma unroll
    for (int q=0;q<4;q++){
        float4 a0 = *(const float4*)(A + (size_t)(m0+r)*32 + c4 + q*4);
        As[(c4+q*4+0)*132 + r] = a0.x; As[(c4+q*4+1)*132 + r] = a0.y;
        As[(c4+q*4+2)*132 + r] = a0.z; As[(c4+q*4+3)*132 + r] = a0.w;
        float4 w0 = *(const float4*)(W + (size_t)(n0+r)*32 + c4 + q*4);
        Ws[(c4+q*4+0)*132 + r] = w0.x; Ws[(c4+q*4+1)*132 + r] = w0.y;
        Ws[(c4+q*4+2)*132 + r] = w0.z; Ws[(c4+q*4+3)*132 + r] = w0.w;
    }
    __syncthreads();
    #pragma unroll
    for (int kk=0; kk<32; kk++){
        float av[8], bv[8];
        *(float4*)&av[0] = *(const float4*)(As + kk*132 + (ty<<3));
        *(float4*)&av[4] = *(const float4*)(As + kk*132 + (ty<<3) + 4);
        *(float4*)&bv[0] = *(const float4*)(Ws + kk*132 + (tx<<3));
        *(float4*)&bv[4] = *(const float4*)(Ws + kk*132 + (tx<<3) + 4);
        #pragma unroll
        for (int i=0;i<8;i++)
            #pragma unroll
            for (int j=0;j<8;j++) acc[i][j] += av[i]*bv[j];
    }
    #pragma unroll
    for (int i=0;i<8;i++){
        int mg = m0 + (ty<<3) + i;
        #pragma unroll
        for (int j=0;j<8;j++)
            Cg[(size_t)mg*N + n0 + (tx<<3) + j] = acc[i][j];
    }
}

// ---------------- VE gate + V -> transposed hi/lo ----------------
__global__ void vgate_kernel(const float* __restrict__ xn, const float* __restrict__ ve,
                             const float* __restrict__ wg, const float* __restrict__ qkv,
                             h16* __restrict__ vhi, h16* __restrict__ vlo){
    int row = blockIdx.x;
    __shared__ float gs[4];
    if (threadIdx.x < 4){
        float s = 0.f;
        #pragma unroll
        for (int c=0;c<12;c++) s += xn[(size_t)row*Cv + c]*wg[threadIdx.x*12 + c];
        gs[threadIdx.x] = 3.f/(1.f + expf(-s));
    }
    __syncthreads();
    int i = threadIdx.x;
    int kv = i >> 6, d = i & 63;
    float vv = qkv[(size_t)row*1536 + 1280 + i] + gs[kv]*ve[(size_t)row*256 + i];
    h16 h,l; split1(vv,h,l);
    size_t o = ((size_t)((row>>10)*4 + kv)*64 + d)*1024 + (row & 1023);
    vhi[o] = h; vlo[o] = l;
}

// ---------------- rope + per-head rmsnorm*1.2 -> hi/lo ----------------
__global__ void ropeRms_kernel(const float* __restrict__ src, int srcStride, int srcOff,
                               h16* __restrict__ dhi, h16* __restrict__ dlo,
                               const float* __restrict__ cosb, const float* __restrict__ sinb,
                               int nheads){
    int row  = blockIdx.x;
    int t    = row & (Tv-1);
    int head = blockIdx.y*4 + (threadIdx.x >> 5);
    if (head >= nheads) return;
    int lane = threadIdx.x & 31;
    const float* p = src + (size_t)row*srcStride + srcOff + head*HD;
    float x1 = p[lane], x2 = p[lane+32];
    float cc = cosb[t*32 + lane], sn = sinb[t*32 + lane];
    float o1 =  x1*cc + x2*sn;
    float o2 = -x1*sn + x2*cc;
    float ss = o1*o1 + o2*o2;
    for (int off=16; off>0; off>>=1) ss += __shfl_xor_sync(0xffffffffu, ss, off);
    float rr = rsqrtf(ss*(1.0f/HD) + 1e-6f)*1.2f;
    o1 *= rr; o2 *= rr;
    size_t base = ((size_t)row*nheads + head)*HD;
    h16 h,l;
    split1(o1,h,l); dhi[base+lane] = h;    dlo[base+lane] = l;
    split1(o2,h,l); dhi[base+lane+32] = h; dlo[base+lane+32] = l;
}

// =================== flash attention (fp16 3-term), double-buffered ===================
#define SM_Q    0
#define SM_KV0  16384
#define SM_KV1  49152
#define SM_PP0  81920
#define SM_PP1  99608
#define SM_S    117296
#define SM_PHI  136240
#define SM_PLO  144432
#define SM_CORR 152624
#define SM_LINV 152880
#define ATTN_SMEM 153136

__global__ void __launch_bounds__(256)
attn_kernel(const h16* __restrict__ qhi, const h16* __restrict__ qlo,
            const h16* __restrict__ khi, const h16* __restrict__ klo,
            const h16* __restrict__ vhi, const h16* __restrict__ vlo,
            const float* __restrict__ prev, const float* __restrict__ rw,
            const float* __restrict__ alphap,
            h16* __restrict__ yh){
    extern __shared__ char smc[];
    uint32_t sb = smem_u32(smc);
    float* S      = (float*)(smc + SM_S);
    float* corr_s = (float*)(smc + SM_CORR);
    float* linv   = (float*)(smc + SM_LINV);

    const int tid = threadIdx.x, lane = tid & 31, wid = tid >> 5;
    const int warpM = wid & 3, warpN = wid >> 2;
    const int row = tid >> 2, quad = tid & 3, c0 = quad << 4;
    const int qt = blockIdx.x, h = blockIdx.y, b = blockIdx.z;
    const int q0 = qt << 6;
    const int kvh = h >> 2;
    const int lr = lane & 15, lc = (lane < 16) ? 0 : 8;
    const int g = lane >> 2, t2 = (lane & 3) << 1;

    const float alpha = alphap[0];
    float w9[9];
    #pragma unroll
    for (int i=0;i<9;i++) w9[i] = alpha*rw[h*9 + i];

    const float* prevB = prev + ((size_t)(b*NH + h))*Tv*Tv;

    auto issueKV = [&](int kt, int s){
        int k0 = kt << 6;
        uint32_t kvb = sb + SM_KV0 + s*32768;
        #pragma unroll
        for (int i=0;i<8;i++){
            int idx = tid + (i << 8);
            int arr = idx >> 9, rr = (idx >> 3) & 63, kc = idx & 7;
            const h16* src;
            if (arr < 2) src = (arr ? klo : khi) + ((((size_t)(b*Tv + k0 + rr))*NKV + kvh) << 6) + (kc << 3);
            else         src = (arr == 2 ? vhi : vlo) + (((size_t)((b*NKV + kvh)*64 + rr)) << 10) + k0 + (kc << 3);
            cpa16(kvb + arr*8192 + sw128(rr, kc << 3), src);
        }
    };
    auto issuePP = [&](int kt, int s){
        int k0 = kt << 6;
        uint32_t ppb = sb + SM_PP0 + s*17688;
        for (int idx = tid; idx < 66*66; idx += 256){
            int i = idx/66, j = idx - i*66;
            int rr = q0 - 1 + i, cg = k0 - 1 + j;
            int ok = (rr >= 0 && rr < Tv && cg >= 0 && cg < Tv) ? 4 : 0;
            int rrc = rr < 0 ? 0 : (rr > 1023 ? 1023 : rr);
            int cgc = cg < 0 ? 0 : (cg > 1023 ? 1023 : cg);
            cpa4z(ppb + (uint32_t)(i*67 + j)*4, prevB + (size_t)rrc*Tv + cgc, ok);
        }
    };

    {
        #pragma unroll
        for (int i=0;i<4;i++){
            int idx = tid + (i << 8);
            int arr = idx >> 9, rr = (idx >> 3) & 63, kc = idx & 7;
            const h16* src = (arr ? qlo : qhi) + ((((size_t)(b*Tv + q0 + rr))*NH + h) << 6) + (kc << 3);
            cpa16(sb + SM_Q + arr*8192 + sw128(rr, kc << 3), src);
        }
        CPA_COMMIT();
        issueKV(0,0); issuePP(0,0);
        CPA_COMMIT();
    }

    float o[4][4];
    #pragma unroll
    for (int i=0;i<4;i++)
        #pragma unroll
        for (int j=0;j<4;j++) o[i][j]=0.f;
    float m = -1e30f, l = 0.f;

    for (int kt = 0; kt <= qt; kt++){
        int s = kt & 1;
        CPA_WAIT(0);
        __syncthreads();
        if (kt < qt){ issueKV(kt+1, s^1); issuePP(kt+1, s^1); CPA_COMMIT(); }
        uint32_t kvb = sb + SM_KV0 + s*32768;
        float* PP = (float*)(smc + SM_PP0 + s*17688);

        float c[4][4];
        #pragma unroll
        for (int i=0;i<4;i++)
            #pragma unroll
            for (int j=0;j<4;j++) c[i][j]=0.f;
        #pragma unroll
        for (int k16 = 0; k16 < 4; k16++){
            uint32_t qh_[4], ql_[4];
            uint32_t offq = sw128(warpM*16 + lr, k16*16 + lc);
            ldsm4(qh_, sb + SM_Q + offq);
            ldsm4(ql_, sb + SM_Q + 8192 + offq);
            #pragma unroll
            for (int nb=0; nb<2; nb++){
                uint32_t offk = sw128(warpN*32 + nb*16 + lr, k16*16 + lc);
                uint32_t kh_[4], kl_[4];
                ldsm4(kh_, kvb + offk);
                ldsm4(kl_, kvb + 8192 + offk);
                mma16816(c[nb*2+0], qh_, kh_[0], kh_[2]);
                mma16816(c[nb*2+0], qh_, kl_[0], kl_[2]);
                mma16816(c[nb*2+0], ql_, kh_[0], kh_[2]);
                mma16816(c[nb*2+1], qh_, kh_[1], kh_[3]);
                mma16816(c[nb*2+1], qh_, kl_[1], kl_[3]);
                mma16816(c[nb*2+1], ql_, kh_[1], kh_[3]);
            }
        }
        #pragma unroll
        for (int ni=0; ni<4; ni++){
            int col = warpN*32 + ni*8 + t2;
            int r0 = warpM*16 + g;
            *(float2*)(S + r0*74 + col)     = make_float2(c[ni][0], c[ni][1]);
            *(float2*)(S + (r0+8)*74 + col) = make_float2(c[ni][2], c[ni][3]);
        }
        __syncthreads();

        float sr[16];
        #pragma unroll
        for (int j=0;j<16;j++){
            int col = c0 + j;
            const float* p0 = PP + (row+0)*67 + col;
            const float* p1 = PP + (row+1)*67 + col;
            const float* p2 = PP + (row+2)*67 + col;
            float cv = w9[0]*p0[0] + w9[1]*p0[1] + w9[2]*p0[2]
                     + w9[3]*p1[0] + w9[4]*p1[1] + w9[5]*p1[2]
                     + w9[6]*p2[0] + w9[7]*p2[1] + w9[8]*p2[2];
            sr[j] = S[row*74 + col]*0.125f + cv;
            if (kt == qt && col > row) sr[j] = -1e30f;
        }
        float mt = sr[0];
        #pragma unroll
        for (int j=1;j<16;j++) mt = fmaxf(mt, sr[j]);
        for (int off=1; off<4; off<<=1) mt = fmaxf(mt, __shfl_xor_sync(0xffffffffu, mt, off));
        float mnew = fmaxf(m, mt);
        float corrv = __expf(m - mnew);
        float ls = 0.f;
        #pragma unroll
        for (int j=0;j<16;j++){ sr[j] = __expf(sr[j] - mnew); ls += sr[j]; }
        for (int off=1; off<4; off<<=1) ls += __shfl_xor_sync(0xffffffffu, ls, off);
        l = l*corrv + ls;
        m = mnew;
        if (quad == 0) corr_s[row] = corrv;
        #pragma unroll
        for (int j=0;j<16;j++){
            int col = c0 + j;
            h16 ph, pl; split1(sr[j], ph, pl);
            uint32_t off = sw128(row, col);
            *(h16*)(smc + SM_PHI + off) = ph;
            *(h16*)(smc + SM_PLO + off) = pl;
        }
        __syncthreads();

        float cr0 = corr_s[warpM*16 + g], cr1 = corr_s[warpM*16 + g + 8];
        #pragma unroll
        for (int ni=0; ni<4; ni++){
            o[ni][0] *= cr0; o[ni][1] *= cr0;
            o[ni][2] *= cr1; o[ni][3] *= cr1;
        }
        #pragma unroll
        for (int k16 = 0; k16 < 4; k16++){
            uint32_t ph_[4], pl_[4];
            uint32_t offp = sw128(warpM*16 + lr, k16*16 + lc);
            ldsm4(ph_, sb + SM_PHI + offp);
            ldsm4(pl_, sb + SM_PLO + offp);
            #pragma unroll
            for (int nb=0; nb<2; nb++){
                uint32_t offv = sw128(warpN*32 + nb*16 + lr, k16*16 + lc);
                uint32_t vh_[4], vl_[4];
                ldsm4(vh_, kvb + 16384 + offv);
                ldsm4(vl_, kvb + 24576 + offv);
                mma16816(o[nb*2+0], ph_, vh_[0], vh_[2]);
                mma16816(o[nb*2+0], ph_, vl_[0], vl_[2]);
                mma16816(o[nb*2+0], pl_, vh_[0], vh_[2]);
                mma16816(o[nb*2+1], ph_, vh_[1], vh_[3]);
                mma16816(o[nb*2+1], ph_, vl_[1], vl_[3]);
                mma16816(o[nb*2+1], pl_, vh_[1], vh_[3]);
            }
        }
    }

    if (quad == 0) linv[row] = 1.f/l;
    __syncthreads();
    float i0 = linv[warpM*16 + g], i1 = linv[warpM*16 + g + 8];
    #pragma unroll
    for (int ni=0; ni<4; ni++){
        int col = warpN*32 + ni*8 + t2;
        size_t base0 = ((((size_t)(b*Tv + q0 + warpM*16 + g))*NH + h) << 6) + col;
        size_t base1 = ((((size_t)(b*Tv + q0 + warpM*16 + g + 8))*NH + h) << 6) + col;
        *(uint32_t*)(yh + base0) = pack2(__float2half_rn(o[ni][0]*i0), __float2half_rn(o[ni][1]*i0));
        *(uint32_t*)(yh + base1) = pack2(__float2half_rn(o[ni][2]*i1), __float2half_rn(o[ni][3]*i1));
    }
}

// ---------------- CA conv + gelu ----------------
__global__ void caconv_kernel(const float* __restrict__ hin, const float* __restrict__ cw,
                              float* __restrict__ hout){
    int ch = blockIdx.x, b = blockIdx.y;
    __shared__ float s[Tv+2];
    for (int t = threadIdx.x; t < Tv; t += 256) s[1+t] = hin[((size_t)b*Tv + t)*32 + ch];
    if (threadIdx.x == 0){ s[0] = 0.f; s[Tv+1] = 0.f; }
    __syncthreads();
    float w0 = cw[ch*3], w1 = cw[ch*3+1], w2 = cw[ch*3+2];
    for (int t = threadIdx.x; t < Tv; t += 256){
        float vv = s[1+t] + 0.1f*(w0*s[t] + w1*s[1+t] + w2*s[2+t]);
        hout[((size_t)b*Tv + t)*32 + ch] = 0.5f*vv*(1.f + erff(vv*0.70710678118f));
    }
}

// ---------------- FFN conv x4: fp16 (B,F,T) in -> fp16 (B,T,F) out ----------------
#define FFNC_SMEM (2*16*1026*4)
__global__ void __launch_bounds__(256)
ffnconvT_kernel(const h16* __restrict__ hf, const float* __restrict__ cw,
                h16* __restrict__ hs){
    extern __shared__ float fs[];
    float (*buf0)[1026] = (float(*)[1026])fs;
    float (*buf1)[1026] = (float(*)[1026])(fs + 16*1026);
    int f0 = blockIdx.x << 4, b = blockIdx.y;
    for (int idx4 = threadIdx.x; idx4 < 16*256; idx4 += 256){
        int cch = idx4 >> 8, t4 = (idx4 & 255) << 2;
        size_t o = ((size_t)(b*FFH + f0 + cch))*Tv + t4;
        uint2 u = *(const uint2*)(hf + o);
        const h16* ph = (const h16*)&u;
        #pragma unroll
        for (int e=0;e<4;e++) buf0[cch][1+t4+e] = __half2float(ph[e]);
    }
    if (threadIdx.x < 16){
        buf0[threadIdx.x][0] = 0.f; buf0[threadIdx.x][1025] = 0.f;
        buf1[threadIdx.x][0] = 0.f; buf1[threadIdx.x][1025] = 0.f;
    }
    int cch = threadIdx.x >> 4, j = threadIdx.x & 15;
    float w0 = cw[(f0+cch)*3], w1 = cw[(f0+cch)*3+1], w2 = cw[(f0+cch)*3+2];
    float (*cur)[1026] = buf0; float (*nxt)[1026] = buf1;
    #pragma unroll
    for (int it=0; it<4; it++){
        __syncthreads();
        #pragma unroll 4
        for (int t = j*64; t < j*64 + 64; t++)
            nxt[cch][1+t] = cur[cch][1+t] + 0.1f*(w0*cur[cch][t] + w1*cur[cch][1+t] + w2*cur[cch][2+t]);
        float (*tmp)[1026] = cur; cur = nxt; nxt = tmp;
    }
    __syncthreads();
    for (int t = threadIdx.x; t < Tv; t += 256){
        uint32_t wv[8];
        #pragma unroll
        for (int cc = 0; cc < 16; cc += 2)
            wv[cc>>1] = pack2(__float2half_rn(cur[cc][1+t]), __float2half_rn(cur[cc+1][1+t]));
        size_t o = ((size_t)(b*Tv + t))*FFH + f0;
        *(uint4*)(hs + o)     = make_uint4(wv[0],wv[1],wv[2],wv[3]);
        *(uint4*)(hs + o + 8) = make_uint4(wv[4],wv[5],wv[6],wv[7]);
    }
}

// ---------------- elementwise ----------------
__global__ void vit2_kernel(const float* __restrict__ h32, const float* __restrict__ w2,
                            float* __restrict__ out){
    int row  = blockIdx.x*8 + (threadIdx.x >> 5);
    int lane = threadIdx.x & 31;
    float vv = h32[(size_t)row*32 + lane]*w2[lane];
    for (int off=16; off>0; off>>=1) vv += __shfl_xor_sync(0xffffffffu, vv, off);
    if (lane == 0) out[row] = 1.f/(1.f + expf(-vv));
}
__global__ void vitsmooth_kernel(const float* __restrict__ vin, float* __restrict__ vout){
    int b = blockIdx.x;
    __shared__ float s[Tv+4];
    for (int t = threadIdx.x; t < Tv; t += 256) s[2+t] = vin[b*Tv + t];
    if (threadIdx.x < 2){ s[threadIdx.x] = 0.f; s[Tv+2+threadIdx.x] = 0.f; }
    __syncthreads();
    for (int t = threadIdx.x; t < Tv; t += 256){
        float vs = (s[t] + s[t+1] + s[t+2] + s[t+3] + s[t+4])*0.2f;
        float vv = 0.7f*s[2+t] + 0.3f*vs;
        vout[b*Tv + t] = (vv > 0.3f) ? vv : 0.1f*vv;
    }
}
__global__ void final_kernel(const float* __restrict__ x1, const float* __restrict__ mlp,
                             const float* __restrict__ gate, const float* __restrict__ ca,
                             const float* __restrict__ vitf, float* __restrict__ out, int n){
    for (int i = blockIdx.x*blockDim.x + threadIdx.x; i < n; i += gridDim.x*blockDim.x){
        int row = i >> 10;
        float gg = 1.f/(1.f + expf(-gate[i]));
        out[i] = x1[i] + mlp[i]*gg*(1.f + 0.1f*tanhf(ca[i]))*vitf[row];
    }
}

// ---------------- launch ----------------
extern "C" void kernel_launch(void* const* d_in, const int* in_sizes, int n_in,
                              void* d_out, int out_size){
    const float* x     = (const float*)d_in[0];
    const float* ve    = (const float*)d_in[1];
    const float* cosp  = (const float*)d_in[2];
    const float* sinp  = (const float*)d_in[3];
    const float* prev  = (const float*)d_in[4];
    const float* w_q   = (const float*)d_in[5];
    const float* w_k   = (const float*)d_in[6];
    const float* w_v   = (const float*)d_in[7];
    const float* w_o   = (const float*)d_in[8];
    const float* w_veg = (const float*)d_in[9];
    const float* rfw   = (const float*)d_in[10];
    const float* ralpha= (const float*)d_in[11];
    const float* ca_pi = (const float*)d_in[12];
    const float* ca_cw = (const float*)d_in[13];
    const float* ca_po = (const float*)d_in[14];
    const float* ffn_in= (const float*)d_in[15];
    const float* ffn_cw= (const float*)d_in[16];
    const float* ffn_outw=(const float*)d_in[17];
    const float* ffn_gt= (const float*)d_in[18];
    const float* vit_w1= (const float*)d_in[19];
    const float* vit_w2= (const float*)d_in[20];
    float* out = (float*)d_out;

    float *xn,*qkv,*attn,*ca,*cah,*cah2,*x1,*mlp,*gate,*vit32,*vitv,*vitf;
    h16 *xnh,*xmh,*yh,*qh,*ql,*kh,*kl,*vh,*vl,*hf,*hs;
    h16 *wqkvh,*wqkvl,*woh,*wol,*finh,*finl,*fouth,*foutl,*fgth,*fgtl;
    cudaGetSymbolAddress((void**)&xn, g_xn);     cudaGetSymbolAddress((void**)&qkv, g_qkv);
    cudaGetSymbolAddress((void**)&attn, g_attn); cudaGetSymbolAddress((void**)&ca, g_ca);
    cudaGetSymbolAddress((void**)&cah, g_cah);   cudaGetSymbolAddress((void**)&cah2, g_cah2);
    cudaGetSymbolAddress((void**)&x1, g_x1);
    cudaGetSymbolAddress((void**)&mlp, g_mlp);   cudaGetSymbolAddress((void**)&gate, g_gate);
    cudaGetSymbolAddress((void**)&vit32, g_vit32); cudaGetSymbolAddress((void**)&vitv, g_vitv);
    cudaGetSymbolAddress((void**)&vitf, g_vitf);
    cudaGetSymbolAddress((void**)&xnh, g_xn_h);
    cudaGetSymbolAddress((void**)&xmh, g_xm_h);
    cudaGetSymbolAddress((void**)&yh, g_y_h);
    cudaGetSymbolAddress((void**)&qh, g_q_h);    cudaGetSymbolAddress((void**)&ql, g_q_l);
    cudaGetSymbolAddress((void**)&kh, g_k_h);    cudaGetSymbolAddress((void**)&kl, g_k_l);
    cudaGetSymbolAddress((void**)&vh, g_v_h);    cudaGetSymbolAddress((void**)&vl, g_v_l);
    cudaGetSymbolAddress((void**)&hf, g_hf);     cudaGetSymbolAddress((void**)&hs, g_hs);
    cudaGetSymbolAddress((void**)&wqkvh, g_wqkv_h); cudaGetSymbolAddress((void**)&wqkvl, g_wqkv_l);
    cudaGetSymbolAddress((void**)&woh, g_wo_h);  cudaGetSymbolAddress((void**)&wol, g_wo_l);
    cudaGetSymbolAddress((void**)&finh, g_fin_h); cudaGetSymbolAddress((void**)&finl, g_fin_l);
    cudaGetSymbolAddress((void**)&fouth, g_fout_h); cudaGetSymbolAddress((void**)&foutl, g_fout_l);
    cudaGetSymbolAddress((void**)&fgth, g_fgt_h); cudaGetSymbolAddress((void**)&fgtl, g_fgt_l);

    cudaFuncSetAttribute(attn_kernel, cudaFuncAttributeMaxDynamicSharedMemorySize, ATTN_SMEM);
    cudaFuncSetAttribute(gemm_f16<0>, cudaFuncAttributeMaxDynamicSharedMemorySize, GEMM_SMEM);
    cudaFuncSetAttribute(gemm_f16<1>, cudaFuncAttributeMaxDynamicSharedMemorySize, GEMM_SMEM);
    cudaFuncSetAttribute(ffnconvT_kernel, cudaFuncAttributeMaxDynamicSharedMemorySize, FFNC_SMEM);

    // launches 1-5: splits + rms (so launch #6 = QKV GEMM for ncu -s 5 -c 1)
    split_kernel<<<256,256>>>(w_q, wqkvh, wqkvl, 262144);
    split_kernel<<<64,256>>>(w_k, wqkvh + 1024*1024, wqkvl + 1024*1024, 65536);
    split_kernel<<<64,256>>>(w_v, wqkvh + 1280*1024, wqkvl + 1280*1024, 65536);
    rms_kernel<1><<<MT,256>>>(x, xn, xnh);
    split_kernel<<<256,256>>>(w_o, woh, wol, 262144);
    gemm_f16<0><<<dim3(6,32),512,GEMM_SMEM>>>(xnh, wqkvh, wqkvl, qkv, 0, 1536, 1024);

    vgate_kernel<<<MT,256>>>(xn, ve, w_veg, qkv, vh, vl);
    ropeRms_kernel<<<dim3(MT,4),128>>>(qkv, 1536, 0,    qh, ql, cosp, sinp, NH);
    ropeRms_kernel<<<dim3(MT,1),128>>>(qkv, 1536, 1024, kh, kl, cosp, sinp, NKV);

    attn_kernel<<<dim3(16,NH,Bv),256,ATTN_SMEM>>>(qh, ql, kh, kl, vh, vl, prev, rfw, ralpha, yh);
    gemm_f16<0><<<dim3(4,32),512,GEMM_SMEM>>>(yh, woh, wol, attn, 0, 1024, 1024);

    split_kernel<<<1024,256>>>(ffn_in, finh, finl, 1048576);
    split_kernel<<<1024,256>>>(ffn_outw, fouth, foutl, 1048576);
    split_kernel<<<256,256>>>(ffn_gt, fgth, fgtl, 262144);

    // ca1 on x; fused x1 + rms
    gemm32_kernel<0><<<512,256>>>(x, ca_pi, cah);
    caconv_kernel<<<dim3(32,Bv),256>>>(cah, ca_cw, cah2);
    gemm_k32<<<dim3(8,32),256>>>(cah2, ca_po, ca, 1024);
    x1rms_kernel<<<MT,256>>>(x, attn, ca, x1, xmh);

    // FFN
    gemm_f16<1><<<dim3(16,32),512,GEMM_SMEM>>>(xmh, finh, finl, 0, hf, FFH, 1024);
    ffnconvT_kernel<<<dim3(256,Bv),256,FFNC_SMEM>>>(hf, ffn_cw, hs);
    gemm_f16<0><<<dim3(4,32),512,GEMM_SMEM>>>(hs, fouth, foutl, mlp, 0, 1024, 4096);
    gemm_f16<0><<<dim3(4,32),512,GEMM_SMEM>>>(xmh, fgth, fgtl, gate, 0, 1024, 1024);

    // ca2 on x1
    gemm32_kernel<0><<<512,256>>>(x1, ca_pi, cah);
    caconv_kernel<<<dim3(32,Bv),256>>>(cah, ca_cw, cah2);
    gemm_k32<<<dim3(8,32),256>>>(cah2, ca_po, ca, 1024);

    // vit gate
    gemm32_kernel<2><<<512,256>>>(x1, vit_w1, vit32);
    vit2_kernel<<<512,256>>>(vit32, vit_w2, vitv);
    vitsmooth_kernel<<<Bv,256>>>(vitv, vitf);

    final_kernel<<<4096,256>>>(x1, mlp, gate, ca, vitf, out, MT*Cv);
}

// round 7
// speedup vs baseline: 2.6243x; 1.0260x over previous
#include <cuda_runtime.h>
#include <cuda_fp16.h>
#include <math.h>
#include <stdint.h>

#define Bv  4
#define Tv  1024
#define Cv  1024
#define NH  16
#define NKV 4
#define HD  64
#define FFH 4096
#define MT  (Bv*Tv)

typedef __half h16;

// ---------------- fp32 scratch ----------------
__device__ float g_xn  [MT*Cv];
__device__ float g_qkv [MT*1536];
__device__ float g_attn[MT*Cv];
__device__ float g_ca  [MT*Cv];
__device__ float g_cah [MT*32];
__device__ float g_cah2[MT*32];
__device__ float g_x1  [MT*Cv];
__device__ float g_mlp [MT*Cv];
__device__ float g_gate[MT*Cv];
__device__ float g_vit32[MT*32];
__device__ float g_vitv[MT];
__device__ float g_vitf[MT];

// ---------------- fp16 scratch ----------------
__device__ h16 g_xn_h[MT*Cv];
__device__ h16 g_xm_h[MT*Cv];
__device__ h16 g_y_h [MT*Cv];
__device__ h16 g_q_h [MT*1024];                  // (b,t,h,d) single
__device__ h16 g_k_h [MT*256],  g_k_l [MT*256];  // (b,t,kv,d) hi/lo
__device__ h16 g_v_h [MT*256],  g_v_l [MT*256];  // (b,kv,d,t) hi/lo
__device__ h16 g_hf  [(size_t)MT*FFH];           // (b,f,t)
__device__ h16 g_hs  [(size_t)MT*FFH];           // (b,t,f)
__device__ h16 g_wqkv_h[1536*1024], g_wqkv_l[1536*1024];
__device__ h16 g_wo_h[1024*1024],  g_wo_l[1024*1024];
__device__ h16 g_fin_h[FFH*1024],  g_fin_l[FFH*1024];
__device__ h16 g_fout_h[1024*FFH], g_fout_l[1024*FFH];
__device__ h16 g_fgt_h[1024*1024], g_fgt_l[1024*1024];

// =================== helpers ===================
__device__ __forceinline__ uint32_t smem_u32(const void* p){
    uint32_t a;
    asm("{ .reg .u64 t; cvta.to.shared.u64 t, %1; cvt.u32.u64 %0, t; }" : "=r"(a) : "l"(p));
    return a;
}
__device__ __forceinline__ void mma16816(float* c, const uint32_t* a, uint32_t b0, uint32_t b1){
    asm volatile("mma.sync.aligned.m16n8k16.row.col.f32.f16.f16.f32 "
        "{%0,%1,%2,%3}, {%4,%5,%6,%7}, {%8,%9}, {%0,%1,%2,%3};"
        : "+f"(c[0]), "+f"(c[1]), "+f"(c[2]), "+f"(c[3])
        : "r"(a[0]), "r"(a[1]), "r"(a[2]), "r"(a[3]), "r"(b0), "r"(b1));
}
__device__ __forceinline__ void ldsm4(uint32_t* r, uint32_t addr){
    asm volatile("ldmatrix.sync.aligned.m8n8.x4.shared.b16 {%0,%1,%2,%3}, [%4];"
        : "=r"(r[0]), "=r"(r[1]), "=r"(r[2]), "=r"(r[3]) : "r"(addr));
}
__device__ __forceinline__ void cpa16(uint32_t saddr, const void* g){
    asm volatile("cp.async.cg.shared.global [%0], [%1], 16;" :: "r"(saddr), "l"(g));
}
__device__ __forceinline__ void cpa4z(uint32_t saddr, const void* g, int srcsz){
    asm volatile("cp.async.ca.shared.global [%0], [%1], 4, %2;" :: "r"(saddr), "l"(g), "r"(srcsz));
}
#define CPA_COMMIT() asm volatile("cp.async.commit_group;" ::: "memory")
#define CPA_WAIT(n)  asm volatile("cp.async.wait_group %0;" :: "n"(n) : "memory")

__device__ __forceinline__ uint32_t sw_off(int row, int k){
    int chunk = (k >> 3) ^ ((row >> 1) & 3);
    return (uint32_t)(row*64 + chunk*16 + (k & 7)*2);
}
__device__ __forceinline__ uint32_t sw128(int row, int k){
    return (uint32_t)(row*128 + ((((k>>3) ^ (row & 7)) << 4) | ((k & 7) << 1)));
}
__device__ __forceinline__ void split1(float v, h16& h, h16& l){
    h = __float2half_rn(v);
    l = __float2half_rn(v - __half2float(h));
}
__device__ __forceinline__ uint32_t pack2(h16 a, h16 b){
    return ((uint32_t)__half_as_ushort(b) << 16) | __half_as_ushort(a);
}

// ---------------- weight split ----------------
__global__ void split_kernel(const float* __restrict__ src, h16* __restrict__ hi,
                             h16* __restrict__ lo, int n4){
    int i0 = blockIdx.x*1024 + threadIdx.x;
    #pragma unroll
    for (int j = 0; j < 4; j++){
        int i = i0 + (j << 8);
        if (i < n4){
            float4 v = ((const float4*)src)[i];
            h16 h0,h1,h2,h3,l0,l1,l2,l3;
            split1(v.x,h0,l0); split1(v.y,h1,l1); split1(v.z,h2,l2); split1(v.w,h3,l3);
            ((uint2*)hi)[i] = make_uint2(pack2(h0,h1), pack2(h2,h3));
            ((uint2*)lo)[i] = make_uint2(pack2(l0,l1), pack2(l2,l3));
        }
    }
}

// ---------------- rmsnorm (fp32 + single fp16) ----------------
template<int WF32>
__global__ void rms_kernel(const float* __restrict__ x, float* __restrict__ o32,
                           h16* __restrict__ ohi){
    int row = blockIdx.x;
    const float* xr = x + (size_t)row*Cv;
    float ss = 0.f;
    float v[4];
    #pragma unroll
    for (int j=0;j<4;j++){ v[j] = xr[threadIdx.x + (j<<8)]; ss += v[j]*v[j]; }
    __shared__ float red[8];
    for (int off=16; off>0; off>>=1) ss += __shfl_xor_sync(0xffffffffu, ss, off);
    if ((threadIdx.x & 31) == 0) red[threadIdx.x>>5] = ss;
    __syncthreads();
    if (threadIdx.x < 8){
        float t = red[threadIdx.x];
        for (int off=4; off>0; off>>=1) t += __shfl_xor_sync(0x000000ffu, t, off);
        if (threadIdx.x == 0) red[0] = t;
    }
    __syncthreads();
    float r = rsqrtf(red[0]*(1.0f/Cv) + 1e-6f);
    #pragma unroll
    for (int j=0;j<4;j++){
        int i = threadIdx.x + (j<<8);
        float vv = v[j]*r;
        if (WF32) o32[(size_t)row*Cv + i] = vv;
        ohi[(size_t)row*Cv + i] = __float2half_rn(vv);
    }
}

// ---------------- fused x1 + rmsnorm ----------------
__global__ void x1rms_kernel(const float* __restrict__ x, const float* __restrict__ attn,
                             const float* __restrict__ ca, float* __restrict__ x1,
                             h16* __restrict__ ohi){
    int row = blockIdx.x;
    size_t base = (size_t)row*Cv;
    float v[4]; float ss = 0.f;
    #pragma unroll
    for (int j=0;j<4;j++){
        int i = threadIdx.x + (j<<8);
        float vv = x[base+i] + attn[base+i]*(1.f + 0.1f*tanhf(ca[base+i]));
        v[j] = vv; ss += vv*vv;
    }
    __shared__ float red[8];
    for (int off=16; off>0; off>>=1) ss += __shfl_xor_sync(0xffffffffu, ss, off);
    if ((threadIdx.x & 31) == 0) red[threadIdx.x>>5] = ss;
    __syncthreads();
    if (threadIdx.x < 8){
        float t = red[threadIdx.x];
        for (int off=4; off>0; off>>=1) t += __shfl_xor_sync(0x000000ffu, t, off);
        if (threadIdx.x == 0) red[0] = t;
    }
    __syncthreads();
    float r = rsqrtf(red[0]*(1.0f/Cv) + 1e-6f);
    #pragma unroll
    for (int j=0;j<4;j++){
        int i = threadIdx.x + (j<<8);
        x1[base+i] = v[j];
        ohi[base+i] = __float2half_rn(v[j]*r);
    }
}

// =================== fp16 2-term GEMM: C = Ah*(Bh+Bl); tile 128x256 ===================
#define GSTG 40960
#define GEMM_SMEM (3*GSTG)
template<int EPI>
__global__ void __launch_bounds__(512,1)
gemm_f16(const h16* __restrict__ Ah, const h16* __restrict__ Bh, const h16* __restrict__ Bl,
         float* __restrict__ Cg, h16* __restrict__ Chf, int N, int K){
    extern __shared__ char smem[];
    const int tid = threadIdx.x, lane = tid & 31, wid = tid >> 5;
    const int warpM = wid & 3, warpN = wid >> 2;
    const int m0 = blockIdx.y << 7, n0 = blockIdx.x << 8;
    const int b = m0 >> 10, tb = m0 & 1023;
    uint32_t sb = smem_u32(smem);

    const int r = tid >> 2, kc = tid & 3;
    const h16* aP  = Ah + (size_t)(m0+r)*K + (kc<<3);
    const h16* bH0 = Bh + (size_t)(n0+r)*K + (kc<<3);
    const h16* bH1 = Bh + (size_t)(n0+r+128)*K + (kc<<3);
    const h16* bL0 = Bl + (size_t)(n0+r)*K + (kc<<3);
    const h16* bL1 = Bl + (size_t)(n0+r+128)*K + (kc<<3);
    const uint32_t dA  = sw_off(r, kc<<3);
    const uint32_t dB1 = sw_off(r+128, kc<<3);

    auto ISSUE = [&](int c, int s){
        int k0 = c << 5;
        uint32_t st = sb + s*GSTG;
        cpa16(st + dA,          aP + k0);
        cpa16(st + 8192 + dA,   bH0 + k0);
        cpa16(st + 8192 + dB1,  bH1 + k0);
        cpa16(st + 24576 + dA,  bL0 + k0);
        cpa16(st + 24576 + dB1, bL1 + k0);
        CPA_COMMIT();
    };

    float acc[2][8][4];
    #pragma unroll
    for (int i=0;i<2;i++)
        #pragma unroll
        for (int j=0;j<8;j++)
            #pragma unroll
            for (int q=0;q<4;q++) acc[i][j][q]=0.f;

    const int NC = K >> 5;
    ISSUE(0,0);
    ISSUE(1,1);
    const int lr = lane & 15, lc = (lane < 16) ? 0 : 8;
    for (int c = 0; c < NC; c++){
        if (c == NC-1) { CPA_WAIT(0); } else { CPA_WAIT(1); }
        __syncthreads();
        if (c + 2 < NC) ISSUE(c+2, (c+2)%3);
        uint32_t sA = sb + (c%3)*GSTG;
        #pragma unroll
        for (int kk = 0; kk < 32; kk += 16){
            uint32_t ah[2][4];
            #pragma unroll
            for (int mt=0; mt<2; mt++)
                ldsm4(ah[mt], sA + sw_off(warpM*32 + mt*16 + lr, kk + lc));
            #pragma unroll
            for (int nb=0; nb<4; nb++){
                uint32_t off = sw_off(warpN*64 + nb*16 + lr, kk + lc);
                uint32_t bh[4], bl[4];
                ldsm4(bh, sA + 8192 + off);
                ldsm4(bl, sA + 24576 + off);
                #pragma unroll
                for (int mt=0; mt<2; mt++){
                    mma16816(acc[mt][nb*2+0], ah[mt], bh[0], bh[2]);
                    mma16816(acc[mt][nb*2+0], ah[mt], bl[0], bl[2]);
                    mma16816(acc[mt][nb*2+1], ah[mt], bh[1], bh[3]);
                    mma16816(acc[mt][nb*2+1], ah[mt], bl[1], bl[3]);
                }
            }
        }
    }

    const int g = lane >> 2, t2 = (lane & 3) << 1;
    if (EPI == 0){
        #pragma unroll
        for (int mt=0; mt<2; mt++){
            int m = m0 + warpM*32 + mt*16 + g;
            #pragma unroll
            for (int ni=0; ni<8; ni++){
                int n = n0 + warpN*64 + ni*8 + t2;
                *(float2*)(Cg + (size_t)m*N + n) = make_float2(acc[mt][ni][0], acc[mt][ni][1]);
                *(float2*)(Cg + (size_t)(m+8)*N + n) = make_float2(acc[mt][ni][2], acc[mt][ni][3]);
            }
        }
    } else {
        float* ep = (float*)smem;
        #pragma unroll
        for (int slab=0; slab<4; slab++){
            __syncthreads();
            if (warpN == slab){
                #pragma unroll
                for (int mt=0; mt<2; mt++){
                    int mloc = warpM*32 + mt*16 + g;
                    #pragma unroll
                    for (int ni=0; ni<8; ni++){
                        int nL = ni*8 + t2;
                        ep[nL*136 + mloc]         = acc[mt][ni][0];
                        ep[(nL+1)*136 + mloc]     = acc[mt][ni][1];
                        ep[nL*136 + mloc + 8]     = acc[mt][ni][2];
                        ep[(nL+1)*136 + mloc + 8] = acc[mt][ni][3];
                    }
                }
            }
            __syncthreads();
            #pragma unroll
            for (int i=0;i<4;i++){
                int idx = tid + (i << 9);
                int nr = idx >> 5, t4 = (idx & 31) << 2;
                float a0 = fmaxf(ep[nr*136 + t4 + 0], 0.f);
                float a1 = fmaxf(ep[nr*136 + t4 + 1], 0.f);
                float a2 = fmaxf(ep[nr*136 + t4 + 2], 0.f);
                float a3 = fmaxf(ep[nr*136 + t4 + 3], 0.f);
                int n = n0 + slab*64 + nr;
                size_t o = ((size_t)b*N + n)*1024 + tb + t4;
                *(uint2*)(Chf + o) = make_uint2(
                    pack2(__float2half_rn(a0*a0), __float2half_rn(a1*a1)),
                    pack2(__float2half_rn(a2*a2), __float2half_rn(a3*a3)));
            }
        }
    }
}

// ---------------- small-N (=32) GEMM ----------------
template<int EPI>
__global__ void __launch_bounds__(256)
gemm32_kernel(const float* __restrict__ A, const float* __restrict__ W, float* __restrict__ Cg){
    __shared__ float xs[8*1024];
    int row0 = blockIdx.x << 3;
    #pragma unroll
    for (int i = 0; i < 8; i++){
        int f4 = threadIdx.x + (i << 8);
        ((float4*)xs)[f4] = ((const float4*)(A + ((size_t)row0 << 10)))[f4];
    }
    __syncthreads();
    int w = threadIdx.x >> 5, n = threadIdx.x & 31;
    const float4* Wr = (const float4*)(W + (size_t)n*1024);
    const float4* xr = (const float4*)(xs + (w << 10));
    float acc = 0.f;
    #pragma unroll 4
    for (int k = 0; k < 256; k++){
        float4 a = xr[k], b = Wr[k];
        acc += a.x*b.x + a.y*b.y + a.z*b.z + a.w*b.w;
    }
    if (EPI == 2) acc = 0.5f*acc*(1.f + erff(acc*0.70710678118f));
    Cg[((size_t)(row0 + w) << 5) + n] = acc;
}

// ---------------- FFMA GEMM (ca_po, K=32) ----------------
__global__ void __launch_bounds__(256,2)
gemm_k32(const float* __restrict__ A, const float* __restrict__ W,
         float* __restrict__ Cg, int N){
    __shared__ float As[32*132];
    __shared__ float Ws[32*132];
    const int tx = threadIdx.x & 15, ty = threadIdx.x >> 4;
    const int m0 = blockIdx.y << 7, n0 = blockIdx.x << 7;
    float acc[8][8];
    #pragma unroll
    for (int i=0;i<8;i++)
        #pragma unroll
        for (int j=0;j<8;j++) acc[i][j]=0.f;
    const int r = threadIdx.x >> 1;
    const int c4 = (threadIdx.x & 1) << 4;
    #pragma unroll
    for (int q=0;q<4;q++){
        float4 a0 = *(const float4*)(A + (size_t)(m0+r)*32 + c4 + q*4);
        As[(c4+q*4+0)*132 + r] = a0.x; As[(c4+q*4+1)*132 + r] = a0.y;
        As[(c4+q*4+2)*132 + r] = a0.z; As[(c4+q*4+3)*132 + r] = a0.w;
        float4 w0 = *(const float4*)(W + (size_t)(n0+r)*32 + c4 + q*4);
        Ws[(c4+q*4+0)*132 + r] = w0.x; Ws[(c4+q*4+1)*132 + r] = w0.y;
        Ws[(c4+q*4+2)*132 + r] = w0.z; Ws[(c4+q*4+3)*132 + r] = w0.w;
    }
    __syncthreads();
    #pragma unroll
    for (int kk=0; kk<32; kk++){
        float av[8], bv[8];
        *(float4*)&av[0] = *(const float4*)(As + kk*132 + (ty<<3));
        *(float4*)&av[4] = *(const float4*)(As + kk*132 + (ty<<3) + 4);
        *(float4*)&bv[0] = *(const float4*)(Ws + kk*132 + (tx<<3));
        *(float4*)&bv[4] = *(const float4*)(Ws + kk*132 + (tx<<3) + 4);
        #pragma unroll
        for (int i=0;i<8;i++)
            #pragma unroll
            for (int j=0;j<8;j++) acc[i][j] += av[i]*bv[j];
    }
    #pragma unroll
    for (int i=0;i<8;i++){
        int mg = m0 + (ty<<3) + i;
        #pragma unroll
        for (int j=0;j<8;j++)
            Cg[(size_t)mg*N + n0 + (tx<<3) + j] = acc[i][j];
    }
}

// ---------------- VE gate + V -> transposed hi/lo ----------------
__global__ void vgate_kernel(const float* __restrict__ xn, const float* __restrict__ ve,
                             const float* __restrict__ wg, const float* __restrict__ qkv,
                             h16* __restrict__ vhi, h16* __restrict__ vlo){
    int row = blockIdx.x;
    __shared__ float gs[4];
    if (threadIdx.x < 4){
        float s = 0.f;
        #pragma unroll
        for (int c=0;c<12;c++) s += xn[(size_t)row*Cv + c]*wg[threadIdx.x*12 + c];
        gs[threadIdx.x] = 3.f/(1.f + expf(-s));
    }
    __syncthreads();
    int i = threadIdx.x;
    int kv = i >> 6, d = i & 63;
    float vv = qkv[(size_t)row*1536 + 1280 + i] + gs[kv]*ve[(size_t)row*256 + i];
    h16 h,l; split1(vv,h,l);
    size_t o = ((size_t)((row>>10)*4 + kv)*64 + d)*1024 + (row & 1023);
    vhi[o] = h; vlo[o] = l;
}

// ---------------- rope + per-head rmsnorm*1.2 ----------------
__global__ void ropeRms_kernel(const float* __restrict__ src, int srcStride, int srcOff,
                               h16* __restrict__ dhi, h16* __restrict__ dlo,
                               const float* __restrict__ cosb, const float* __restrict__ sinb,
                               int nheads){
    int row  = blockIdx.x;
    int t    = row & (Tv-1);
    int head = blockIdx.y*4 + (threadIdx.x >> 5);
    if (head >= nheads) return;
    int lane = threadIdx.x & 31;
    const float* p = src + (size_t)row*srcStride + srcOff + head*HD;
    float x1 = p[lane], x2 = p[lane+32];
    float cc = cosb[t*32 + lane], sn = sinb[t*32 + lane];
    float o1 =  x1*cc + x2*sn;
    float o2 = -x1*sn + x2*cc;
    float ss = o1*o1 + o2*o2;
    for (int off=16; off>0; off>>=1) ss += __shfl_xor_sync(0xffffffffu, ss, off);
    float rr = rsqrtf(ss*(1.0f/HD) + 1e-6f)*1.2f;
    o1 *= rr; o2 *= rr;
    size_t base = ((size_t)row*nheads + head)*HD;
    if (dlo){
        h16 h,l;
        split1(o1,h,l); dhi[base+lane] = h;    dlo[base+lane] = l;
        split1(o2,h,l); dhi[base+lane+32] = h; dlo[base+lane+32] = l;
    } else {
        dhi[base+lane]    = __float2half_rn(o1);
        dhi[base+lane+32] = __float2half_rn(o2);
    }
}

// =================== flash attention: 2-term QK / 2-term PV ===================
// Q single 8KB; KV stages 2x32KB (Khi,Klo,Vhi,Vlo); PP 2x; S; P single
#define SM_Q    0
#define SM_KV0  8192
#define SM_KV1  40960
#define SM_PP0  73728
#define SM_PP1  91520
#define SM_S    109312
#define SM_PHI  128256
#define SM_CORR 136448
#define SM_LINV 136704
#define ATTN_SMEM 136960

__global__ void __launch_bounds__(256)
attn_kernel(const h16* __restrict__ qhi,
            const h16* __restrict__ khi, const h16* __restrict__ klo,
            const h16* __restrict__ vhi, const h16* __restrict__ vlo,
            const float* __restrict__ prev, const float* __restrict__ rw,
            const float* __restrict__ alphap,
            h16* __restrict__ yh){
    extern __shared__ char smc[];
    uint32_t sb = smem_u32(smc);
    float* S      = (float*)(smc + SM_S);
    float* corr_s = (float*)(smc + SM_CORR);
    float* linv   = (float*)(smc + SM_LINV);

    const int tid = threadIdx.x, lane = tid & 31, wid = tid >> 5;
    const int warpM = wid & 3, warpN = wid >> 2;
    const int row = tid >> 2, quad = tid & 3, c0 = quad << 4;
    const int qt = blockIdx.x, h = blockIdx.y, b = blockIdx.z;
    const int q0 = qt << 6;
    const int kvh = h >> 2;
    const int lr = lane & 15, lc = (lane < 16) ? 0 : 8;
    const int g = lane >> 2, t2 = (lane & 3) << 1;

    const float alpha = alphap[0];
    float w9[9];
    #pragma unroll
    for (int i=0;i<9;i++) w9[i] = alpha*rw[h*9 + i];

    const float* prevB = prev + ((size_t)(b*NH + h))*Tv*Tv;

    auto issueKV = [&](int kt, int s){
        int k0 = kt << 6;
        uint32_t kvb = sb + SM_KV0 + s*32768;
        #pragma unroll
        for (int i=0;i<8;i++){
            int idx = tid + (i << 8);
            int arr = idx >> 9, rr = (idx >> 3) & 63, kc = idx & 7;
            const h16* src;
            if (arr < 2) src = (arr ? klo : khi) + ((((size_t)(b*Tv + k0 + rr))*NKV + kvh) << 6) + (kc << 3);
            else         src = (arr == 2 ? vhi : vlo) + (((size_t)((b*NKV + kvh)*64 + rr)) << 10) + k0 + (kc << 3);
            cpa16(kvb + arr*8192 + sw128(rr, kc << 3), src);
        }
    };
    auto issuePP = [&](int kt, int s){
        int k0 = kt << 6;
        uint32_t ppb = sb + SM_PP0 + s*17792;
        for (int idx = tid; idx < 66*66; idx += 256){
            int i = idx/66, j = idx - i*66;
            int rr = q0 - 1 + i, cg = k0 - 1 + j;
            int ok = (rr >= 0 && rr < Tv && cg >= 0 && cg < Tv) ? 4 : 0;
            int rrc = rr < 0 ? 0 : (rr > 1023 ? 1023 : rr);
            int cgc = cg < 0 ? 0 : (cg > 1023 ? 1023 : cg);
            cpa4z(ppb + (uint32_t)(i*67 + j)*4, prevB + (size_t)rrc*Tv + cgc, ok);
        }
    };

    {
        #pragma unroll
        for (int i=0;i<2;i++){
            int idx = tid + (i << 8);
            int rr = idx >> 3, kc = idx & 7;
            const h16* src = qhi + ((((size_t)(b*Tv + q0 + rr))*NH + h) << 6) + (kc << 3);
            cpa16(sb + SM_Q + sw128(rr, kc << 3), src);
        }
        CPA_COMMIT();
        issueKV(0,0); issuePP(0,0);
        CPA_COMMIT();
    }

    float o[4][4];
    #pragma unroll
    for (int i=0;i<4;i++)
        #pragma unroll
        for (int j=0;j<4;j++) o[i][j]=0.f;
    float m = -1e30f, l = 0.f;

    for (int kt = 0; kt <= qt; kt++){
        int s = kt & 1;
        CPA_WAIT(0);
        __syncthreads();
        if (kt < qt){ issueKV(kt+1, s^1); issuePP(kt+1, s^1); CPA_COMMIT(); }
        uint32_t kvb = sb + SM_KV0 + s*32768;
        float* PP = (float*)(smc + SM_PP0 + s*17792);

        // ---- QK^T: qh * (kh + kl) ----
        float c[4][4];
        #pragma unroll
        for (int i=0;i<4;i++)
            #pragma unroll
            for (int j=0;j<4;j++) c[i][j]=0.f;
        #pragma unroll
        for (int k16 = 0; k16 < 4; k16++){
            uint32_t qh_[4];
            ldsm4(qh_, sb + SM_Q + sw128(warpM*16 + lr, k16*16 + lc));
            #pragma unroll
            for (int nb=0; nb<2; nb++){
                uint32_t offk = sw128(warpN*32 + nb*16 + lr, k16*16 + lc);
                uint32_t kh_[4], kl_[4];
                ldsm4(kh_, kvb + offk);
                ldsm4(kl_, kvb + 8192 + offk);
                mma16816(c[nb*2+0], qh_, kh_[0], kh_[2]);
                mma16816(c[nb*2+0], qh_, kl_[0], kl_[2]);
                mma16816(c[nb*2+1], qh_, kh_[1], kh_[3]);
                mma16816(c[nb*2+1], qh_, kl_[1], kl_[3]);
            }
        }
        #pragma unroll
        for (int ni=0; ni<4; ni++){
            int col = warpN*32 + ni*8 + t2;
            int r0 = warpM*16 + g;
            *(float2*)(S + r0*74 + col)     = make_float2(c[ni][0], c[ni][1]);
            *(float2*)(S + (r0+8)*74 + col) = make_float2(c[ni][2], c[ni][3]);
        }
        __syncthreads();

        // ---- scalar conv (register-cached halo) + mask + online softmax ----
        float p[3][18];
        #pragma unroll
        for (int i=0;i<3;i++)
            #pragma unroll
            for (int e=0;e<18;e++) p[i][e] = PP[(row+i)*67 + c0 + e];
        float sr[16];
        #pragma unroll
        for (int j=0;j<16;j++){
            float cv = w9[0]*p[0][j] + w9[1]*p[0][j+1] + w9[2]*p[0][j+2]
                     + w9[3]*p[1][j] + w9[4]*p[1][j+1] + w9[5]*p[1][j+2]
                     + w9[6]*p[2][j] + w9[7]*p[2][j+1] + w9[8]*p[2][j+2];
            int col = c0 + j;
            sr[j] = S[row*74 + col]*0.125f + cv;
            if (kt == qt && col > row) sr[j] = -1e30f;
        }
        float mt = sr[0];
        #pragma unroll
        for (int j=1;j<16;j++) mt = fmaxf(mt, sr[j]);
        for (int off=1; off<4; off<<=1) mt = fmaxf(mt, __shfl_xor_sync(0xffffffffu, mt, off));
        float mnew = fmaxf(m, mt);
        float corrv = __expf(m - mnew);
        float ls = 0.f;
        #pragma unroll
        for (int j=0;j<16;j++){ sr[j] = __expf(sr[j] - mnew); ls += sr[j]; }
        for (int off=1; off<4; off<<=1) ls += __shfl_xor_sync(0xffffffffu, ls, off);
        l = l*corrv + ls;
        m = mnew;
        if (quad == 0) corr_s[row] = corrv;
        #pragma unroll
        for (int j=0;j<16;j+=2){
            int col = c0 + j;
            *(uint32_t*)(smc + SM_PHI + sw128(row, col)) =
                pack2(__float2half_rn(sr[j]), __float2half_rn(sr[j+1]));
        }
        __syncthreads();

        // ---- PV: ph * (vh + vl) ----
        float cr0 = corr_s[warpM*16 + g], cr1 = corr_s[warpM*16 + g + 8];
        #pragma unroll
        for (int ni=0; ni<4; ni++){
            o[ni][0] *= cr0; o[ni][1] *= cr0;
            o[ni][2] *= cr1; o[ni][3] *= cr1;
        }
        #pragma unroll
        for (int k16 = 0; k16 < 4; k16++){
            uint32_t ph_[4];
            ldsm4(ph_, sb + SM_PHI + sw128(warpM*16 + lr, k16*16 + lc));
            #pragma unroll
            for (int nb=0; nb<2; nb++){
                uint32_t offv = sw128(warpN*32 + nb*16 + lr, k16*16 + lc);
                uint32_t vh_[4], vl_[4];
                ldsm4(vh_, kvb + 16384 + offv);
                ldsm4(vl_, kvb + 24576 + offv);
                mma16816(o[nb*2+0], ph_, vh_[0], vh_[2]);
                mma16816(o[nb*2+0], ph_, vl_[0], vl_[2]);
                mma16816(o[nb*2+1], ph_, vh_[1], vh_[3]);
                mma16816(o[nb*2+1], ph_, vl_[1], vl_[3]);
            }
        }
    }

    if (quad == 0) linv[row] = 1.f/l;
    __syncthreads();
    float i0 = linv[warpM*16 + g], i1 = linv[warpM*16 + g + 8];
    #pragma unroll
    for (int ni=0; ni<4; ni++){
        int col = warpN*32 + ni*8 + t2;
        size_t base0 = ((((size_t)(b*Tv + q0 + warpM*16 + g))*NH + h) << 6) + col;
        size_t base1 = ((((size_t)(b*Tv + q0 + warpM*16 + g + 8))*NH + h) << 6) + col;
        *(uint32_t*)(yh + base0) = pack2(__float2half_rn(o[ni][0]*i0), __float2half_rn(o[ni][1]*i0));
        *(uint32_t*)(yh + base1) = pack2(__float2half_rn(o[ni][2]*i1), __float2half_rn(o[ni][3]*i1));
    }
}

// ---------------- CA conv + gelu ----------------
__global__ void caconv_kernel(const float* __restrict__ hin, const float* __restrict__ cw,
                              float* __restrict__ hout){
    int ch = blockIdx.x, b = blockIdx.y;
    __shared__ float s[Tv+2];
    for (int t = threadIdx.x; t < Tv; t += 256) s[1+t] = hin[((size_t)b*Tv + t)*32 + ch];
    if (threadIdx.x == 0){ s[0] = 0.f; s[Tv+1] = 0.f; }
    __syncthreads();
    float w0 = cw[ch*3], w1 = cw[ch*3+1], w2 = cw[ch*3+2];
    for (int t = threadIdx.x; t < Tv; t += 256){
        float vv = s[1+t] + 0.1f*(w0*s[t] + w1*s[1+t] + w2*s[2+t]);
        hout[((size_t)b*Tv + t)*32 + ch] = 0.5f*vv*(1.f + erff(vv*0.70710678118f));
    }
}

// ---------------- FFN conv x4 ----------------
#define FFNC_SMEM (2*16*1026*4)
__global__ void __launch_bounds__(256)
ffnconvT_kernel(const h16* __restrict__ hf, const float* __restrict__ cw,
                h16* __restrict__ hs){
    extern __shared__ float fs[];
    float (*buf0)[1026] = (float(*)[1026])fs;
    float (*buf1)[1026] = (float(*)[1026])(fs + 16*1026);
    int f0 = blockIdx.x << 4, b = blockIdx.y;
    for (int idx4 = threadIdx.x; idx4 < 16*256; idx4 += 256){
        int cch = idx4 >> 8, t4 = (idx4 & 255) << 2;
        size_t o = ((size_t)(b*FFH + f0 + cch))*Tv + t4;
        uint2 u = *(const uint2*)(hf + o);
        const h16* ph = (const h16*)&u;
        #pragma unroll
        for (int e=0;e<4;e++) buf0[cch][1+t4+e] = __half2float(ph[e]);
    }
    if (threadIdx.x < 16){
        buf0[threadIdx.x][0] = 0.f; buf0[threadIdx.x][1025] = 0.f;
        buf1[threadIdx.x][0] = 0.f; buf1[threadIdx.x][1025] = 0.f;
    }
    int cch = threadIdx.x >> 4, j = threadIdx.x & 15;
    float w0 = cw[(f0+cch)*3], w1 = cw[(f0+cch)*3+1], w2 = cw[(f0+cch)*3+2];
    float (*cur)[1026] = buf0; float (*nxt)[1026] = buf1;
    #pragma unroll
    for (int it=0; it<4; it++){
        __syncthreads();
        #pragma unroll 4
        for (int t = j*64; t < j*64 + 64; t++)
            nxt[cch][1+t] = cur[cch][1+t] + 0.1f*(w0*cur[cch][t] + w1*cur[cch][1+t] + w2*cur[cch][2+t]);
        float (*tmp)[1026] = cur; cur = nxt; nxt = tmp;
    }
    __syncthreads();
    for (int t = threadIdx.x; t < Tv; t += 256){
        uint32_t wv[8];
        #pragma unroll
        for (int cc = 0; cc < 16; cc += 2)
            wv[cc>>1] = pack2(__float2half_rn(cur[cc][1+t]), __float2half_rn(cur[cc+1][1+t]));
        size_t o = ((size_t)(b*Tv + t))*FFH + f0;
        *(uint4*)(hs + o)     = make_uint4(wv[0],wv[1],wv[2],wv[3]);
        *(uint4*)(hs + o + 8) = make_uint4(wv[4],wv[5],wv[6],wv[7]);
    }
}

// ---------------- elementwise ----------------
__global__ void vit2_kernel(const float* __restrict__ h32, const float* __restrict__ w2,
                            float* __restrict__ out){
    int row  = blockIdx.x*8 + (threadIdx.x >> 5);
    int lane = threadIdx.x & 31;
    float vv = h32[(size_t)row*32 + lane]*w2[lane];
    for (int off=16; off>0; off>>=1) vv += __shfl_xor_sync(0xffffffffu, vv, off);
    if (lane == 0) out[row] = 1.f/(1.f + expf(-vv));
}
__global__ void vitsmooth_kernel(const float* __restrict__ vin, float* __restrict__ vout){
    int b = blockIdx.x;
    __shared__ float s[Tv+4];
    for (int t = threadIdx.x; t < Tv; t += 256) s[2+t] = vin[b*Tv + t];
    if (threadIdx.x < 2){ s[threadIdx.x] = 0.f; s[Tv+2+threadIdx.x] = 0.f; }
    __syncthreads();
    for (int t = threadIdx.x; t < Tv; t += 256){
        float vs = (s[t] + s[t+1] + s[t+2] + s[t+3] + s[t+4])*0.2f;
        float vv = 0.7f*s[2+t] + 0.3f*vs;
        vout[b*Tv + t] = (vv > 0.3f) ? vv : 0.1f*vv;
    }
}
__global__ void final_kernel(const float* __restrict__ x1, const float* __restrict__ mlp,
                             const float* __restrict__ gate, const float* __restrict__ ca,
                             const float* __restrict__ vitf, float* __restrict__ out, int n){
    for (int i = blockIdx.x*blockDim.x + threadIdx.x; i < n; i += gridDim.x*blockDim.x){
        int row = i >> 10;
        float gg = 1.f/(1.f + expf(-gate[i]));
        out[i] = x1[i] + mlp[i]*gg*(1.f + 0.1f*tanhf(ca[i]))*vitf[row];
    }
}

// ---------------- launch ----------------
extern "C" void kernel_launch(void* const* d_in, const int* in_sizes, int n_in,
                              void* d_out, int out_size){
    const float* x     = (const float*)d_in[0];
    const float* ve    = (const float*)d_in[1];
    const float* cosp  = (const float*)d_in[2];
    const float* sinp  = (const float*)d_in[3];
    const float* prev  = (const float*)d_in[4];
    const float* w_q   = (const float*)d_in[5];
    const float* w_k   = (const float*)d_in[6];
    const float* w_v   = (const float*)d_in[7];
    const float* w_o   = (const float*)d_in[8];
    const float* w_veg = (const float*)d_in[9];
    const float* rfw   = (const float*)d_in[10];
    const float* ralpha= (const float*)d_in[11];
    const float* ca_pi = (const float*)d_in[12];
    const float* ca_cw = (const float*)d_in[13];
    const float* ca_po = (const float*)d_in[14];
    const float* ffn_in= (const float*)d_in[15];
    const float* ffn_cw= (const float*)d_in[16];
    const float* ffn_outw=(const float*)d_in[17];
    const float* ffn_gt= (const float*)d_in[18];
    const float* vit_w1= (const float*)d_in[19];
    const float* vit_w2= (const float*)d_in[20];
    float* out = (float*)d_out;

    float *xn,*qkv,*attn,*ca,*cah,*cah2,*x1,*mlp,*gate,*vit32,*vitv,*vitf;
    h16 *xnh,*xmh,*yh,*qh,*kh,*kl,*vh,*vl,*hf,*hs;
    h16 *wqkvh,*wqkvl,*woh,*wol,*finh,*finl,*fouth,*foutl,*fgth,*fgtl;
    cudaGetSymbolAddress((void**)&xn, g_xn);     cudaGetSymbolAddress((void**)&qkv, g_qkv);
    cudaGetSymbolAddress((void**)&attn, g_attn); cudaGetSymbolAddress((void**)&ca, g_ca);
    cudaGetSymbolAddress((void**)&cah, g_cah);   cudaGetSymbolAddress((void**)&cah2, g_cah2);
    cudaGetSymbolAddress((void**)&x1, g_x1);
    cudaGetSymbolAddress((void**)&mlp, g_mlp);   cudaGetSymbolAddress((void**)&gate, g_gate);
    cudaGetSymbolAddress((void**)&vit32, g_vit32); cudaGetSymbolAddress((void**)&vitv, g_vitv);
    cudaGetSymbolAddress((void**)&vitf, g_vitf);
    cudaGetSymbolAddress((void**)&xnh, g_xn_h);
    cudaGetSymbolAddress((void**)&xmh, g_xm_h);
    cudaGetSymbolAddress((void**)&yh, g_y_h);
    cudaGetSymbolAddress((void**)&qh, g_q_h);
    cudaGetSymbolAddress((void**)&kh, g_k_h);    cudaGetSymbolAddress((void**)&kl, g_k_l);
    cudaGetSymbolAddress((void**)&vh, g_v_h);    cudaGetSymbolAddress((void**)&vl, g_v_l);
    cudaGetSymbolAddress((void**)&hf, g_hf);     cudaGetSymbolAddress((void**)&hs, g_hs);
    cudaGetSymbolAddress((void**)&wqkvh, g_wqkv_h); cudaGetSymbolAddress((void**)&wqkvl, g_wqkv_l);
    cudaGetSymbolAddress((void**)&woh, g_wo_h);  cudaGetSymbolAddress((void**)&wol, g_wo_l);
    cudaGetSymbolAddress((void**)&finh, g_fin_h); cudaGetSymbolAddress((void**)&finl, g_fin_l);
    cudaGetSymbolAddress((void**)&fouth, g_fout_h); cudaGetSymbolAddress((void**)&foutl, g_fout_l);
    cudaGetSymbolAddress((void**)&fgth, g_fgt_h); cudaGetSymbolAddress((void**)&fgtl, g_fgt_l);

    cudaFuncSetAttribute(attn_kernel, cudaFuncAttributeMaxDynamicSharedMemorySize, ATTN_SMEM);
    cudaFuncSetAttribute(gemm_f16<0>, cudaFuncAttributeMaxDynamicSharedMemorySize, GEMM_SMEM);
    cudaFuncSetAttribute(gemm_f16<1>, cudaFuncAttributeMaxDynamicSharedMemorySize, GEMM_SMEM);
    cudaFuncSetAttribute(ffnconvT_kernel, cudaFuncAttributeMaxDynamicSharedMemorySize, FFNC_SMEM);

    split_kernel<<<256,256>>>(w_q, wqkvh, wqkvl, 262144);
    split_kernel<<<64,256>>>(w_k, wqkvh + 1024*1024, wqkvl + 1024*1024, 65536);
    split_kernel<<<64,256>>>(w_v, wqkvh + 1280*1024, wqkvl + 1280*1024, 65536);
    rms_kernel<1><<<MT,256>>>(x, xn, xnh);
    split_kernel<<<256,256>>>(w_o, woh, wol, 262144);
    gemm_f16<0><<<dim3(6,32),512,GEMM_SMEM>>>(xnh, wqkvh, wqkvl, qkv, 0, 1536, 1024);

    vgate_kernel<<<MT,256>>>(xn, ve, w_veg, qkv, vh, vl);
    ropeRms_kernel<<<dim3(MT,4),128>>>(qkv, 1536, 0,    qh, (h16*)0, cosp, sinp, NH);
    ropeRms_kernel<<<dim3(MT,1),128>>>(qkv, 1536, 1024, kh, kl, cosp, sinp, NKV);

    attn_kernel<<<dim3(16,NH,Bv),256,ATTN_SMEM>>>(qh, kh, kl, vh, vl, prev, rfw, ralpha, yh);
    gemm_f16<0><<<dim3(4,32),512,GEMM_SMEM>>>(yh, woh, wol, attn, 0, 1024, 1024);

    split_kernel<<<1024,256>>>(ffn_in, finh, finl, 1048576);
    split_kernel<<<1024,256>>>(ffn_outw, fouth, foutl, 1048576);
    split_kernel<<<256,256>>>(ffn_gt, fgth, fgtl, 262144);

    gemm32_kernel<0><<<512,256>>>(x, ca_pi, cah);
    caconv_kernel<<<dim3(32,Bv),256>>>(cah, ca_cw, cah2);
    gemm_k32<<<dim3(8,32),256>>>(cah2, ca_po, ca, 1024);
    x1rms_kernel<<<MT,256>>>(x, attn, ca, x1, xmh);

    gemm_f16<1><<<dim3(16,32),512,GEMM_SMEM>>>(xmh, finh, finl, 0, hf, FFH, 1024);
    ffnconvT_kernel<<<dim3(256,Bv),256,FFNC_SMEM>>>(hf, ffn_cw, hs);
    gemm_f16<0><<<dim3(4,32),512,GEMM_SMEM>>>(hs, fouth, foutl, mlp, 0, 1024, 4096);
    gemm_f16<0><<<dim3(4,32),512,GEMM_SMEM>>>(xmh, fgth, fgtl, gate, 0, 1024, 1024);

    gemm32_kernel<0><<<512,256>>>(x1, ca_pi, cah);
    caconv_kernel<<<dim3(32,Bv),256>>>(cah, ca_cw, cah2);
    gemm_k32<<<dim3(8,32),256>>>(cah2, ca_po, ca, 1024);

    gemm32_kernel<2><<<512,256>>>(x1, vit_w1, vit32);
    vit2_kernel<<<512,256>>>(vit32, vit_w2, vitv);
    vitsmooth_kernel<<<Bv,256>>>(vitv, vitf);

    final_kernel<<<4096,256>>>(x1, mlp, gate, ca, vitf, out, MT*Cv);
}